// round 1
// baseline (speedup 1.0000x reference)
#include <cuda_runtime.h>
#include <math.h>
#include <stdint.h>

#define SEQ   2048
#define BATCH 2
#define DIM   768
#define NH    12
#define HD    64
#define WIN   512
#define ROWS  (BATCH*SEQ)     // 4096
#define LRATE 0.1f

// ----------------- device scratch (no cudaMalloc allowed) -----------------
__device__ float g_qkv[ROWS*3*DIM];
__device__ float g_att[ROWS*DIM];
__device__ float g_proj[ROWS*DIM];
__device__ float g_xlocal[ROWS*DIM];
__device__ float g_xglobal[ROWS*DIM];
__device__ float g_tq[ROWS*DIM];
__device__ float g_tk[ROWS*DIM];
__device__ float g_tv[ROWS*DIM];
__device__ float g_to[ROWS*DIM];
__device__ float g_xcat[ROWS*2*DIM];
__device__ float g_xc[ROWS*DIM];
__device__ float g_h[ROWS*4*DIM];
__device__ float g_acc[ROWS*DIM];

// ----------------- generic NT GEMM: C[M,N] = A[M,K] @ W[N,K]^T ------------
// epi: 0 = store (+bias), 1 = gelu(store+bias), 2 = C += (result+bias)
#define GBM 128
#define GBN 128
#define GBK 8

__global__ __launch_bounds__(256) void gemm_nt(const float* __restrict__ A,
    const float* __restrict__ W, const float* __restrict__ bias,
    float* __restrict__ C, int M, int N, int K, int epi)
{
    __shared__ __align__(16) float As[GBK][GBM + 4];
    __shared__ __align__(16) float Bs[GBK][GBN + 4];
    const int t    = threadIdx.x;
    const int bm   = blockIdx.y * GBM;
    const int bn   = blockIdx.x * GBN;
    const int lrow = t >> 1;          // 0..127
    const int lcol = (t & 1) << 2;    // 0 or 4
    const int tx   = t & 15;          // n-dir, 8 cols each
    const int ty   = t >> 4;          // m-dir, 8 rows each

    const float* Ap = A + (size_t)(bm + lrow) * K + lcol;
    const float* Wp = W + (size_t)(bn + lrow) * K + lcol;

    float acc[8][8];
#pragma unroll
    for (int i = 0; i < 8; ++i)
#pragma unroll
        for (int j = 0; j < 8; ++j) acc[i][j] = 0.f;

    for (int k0 = 0; k0 < K; k0 += GBK) {
        float4 av = *(const float4*)(Ap + k0);
        float4 wv = *(const float4*)(Wp + k0);
        As[lcol + 0][lrow] = av.x; As[lcol + 1][lrow] = av.y;
        As[lcol + 2][lrow] = av.z; As[lcol + 3][lrow] = av.w;
        Bs[lcol + 0][lrow] = wv.x; Bs[lcol + 1][lrow] = wv.y;
        Bs[lcol + 2][lrow] = wv.z; Bs[lcol + 3][lrow] = wv.w;
        __syncthreads();
#pragma unroll
        for (int kk = 0; kk < GBK; ++kk) {
            float a[8], b[8];
            const float4* ar = (const float4*)&As[kk][ty * 8];
            const float4* br = (const float4*)&Bs[kk][tx * 8];
            float4 a0 = ar[0], a1 = ar[1];
            float4 b0 = br[0], b1 = br[1];
            a[0]=a0.x; a[1]=a0.y; a[2]=a0.z; a[3]=a0.w;
            a[4]=a1.x; a[5]=a1.y; a[6]=a1.z; a[7]=a1.w;
            b[0]=b0.x; b[1]=b0.y; b[2]=b0.z; b[3]=b0.w;
            b[4]=b1.x; b[5]=b1.y; b[6]=b1.z; b[7]=b1.w;
#pragma unroll
            for (int i = 0; i < 8; ++i)
#pragma unroll
                for (int j = 0; j < 8; ++j) acc[i][j] += a[i] * b[j];
        }
        __syncthreads();
    }

    float bv[8];
#pragma unroll
    for (int j = 0; j < 8; ++j) bv[j] = bias ? bias[bn + tx * 8 + j] : 0.f;

#pragma unroll
    for (int i = 0; i < 8; ++i) {
        int row = bm + ty * 8 + i;
        float* Crow = C + (size_t)row * N + bn + tx * 8;
#pragma unroll
        for (int j = 0; j < 8; ++j) {
            float v = acc[i][j] + bv[j];
            if (epi == 1) {
                float x3 = v * v * v;
                v = 0.5f * v * (1.f + tanhf(0.7978845608028654f * (v + 0.044715f * x3)));
            } else if (epi == 2) {
                v += Crow[j];
            }
            Crow[j] = v;
        }
    }
}

// ----------------- sliding-window causal attention ------------------------
// grid (SEQ/64, BATCH, NH), 64 threads; each thread owns one query row.
__global__ __launch_bounds__(64) void attn_kernel(const float* __restrict__ qkv,
                                                  float* __restrict__ out)
{
    const int qt = blockIdx.x;
    const int b  = blockIdx.y;
    const int h  = blockIdx.z;
    const int t  = threadIdx.x;
    const int qi = qt * 64 + t;

    __shared__ __align__(16) float ks[64][64];
    __shared__ __align__(16) float vs[64][64];

    float q[64], o[64];
    {
        const float4* qb = (const float4*)(qkv + ((size_t)(b * SEQ + qi)) * (3 * DIM) + h * HD);
#pragma unroll
        for (int d4 = 0; d4 < 16; ++d4) {
            float4 v = qb[d4];
            q[4*d4+0] = v.x * 0.125f; q[4*d4+1] = v.y * 0.125f;
            q[4*d4+2] = v.z * 0.125f; q[4*d4+3] = v.w * 0.125f;
        }
    }
#pragma unroll
    for (int d = 0; d < 64; ++d) o[d] = 0.f;
    float m = -1e30f, l = 0.f;

    const int kt0 = (qt >= 8) ? (qt - 8) : 0;
    for (int kt = kt0; kt <= qt; ++kt) {
        const float* kbase = qkv + ((size_t)(b * SEQ + kt * 64)) * (3 * DIM) + DIM + h * HD + t;
        const float* vbase = kbase + DIM;
        for (int r = 0; r < 64; ++r) {
            ks[r][t] = kbase[(size_t)r * (3 * DIM)];
            vs[r][t] = vbase[(size_t)r * (3 * DIM)];
        }
        __syncthreads();

        int jlo = qi - WIN + 1 - kt * 64; if (jlo < 0)  jlo = 0;
        int jhi = qi - kt * 64;           if (jhi > 63) jhi = 63;
        for (int j = jlo; j <= jhi; ++j) {
            float s = 0.f;
            const float4* kr = (const float4*)ks[j];
#pragma unroll
            for (int d4 = 0; d4 < 16; ++d4) {
                float4 kv = kr[d4];
                s += q[4*d4+0]*kv.x + q[4*d4+1]*kv.y + q[4*d4+2]*kv.z + q[4*d4+3]*kv.w;
            }
            const float4* vr = (const float4*)vs[j];
            if (s <= m) {
                float p = __expf(s - m);
                l += p;
#pragma unroll
                for (int d4 = 0; d4 < 16; ++d4) {
                    float4 vv = vr[d4];
                    o[4*d4+0] += p*vv.x; o[4*d4+1] += p*vv.y;
                    o[4*d4+2] += p*vv.z; o[4*d4+3] += p*vv.w;
                }
            } else {
                float al = __expf(m - s);
                m = s; l = l * al + 1.f;
#pragma unroll
                for (int d4 = 0; d4 < 16; ++d4) {
                    float4 vv = vr[d4];
                    o[4*d4+0] = o[4*d4+0]*al + vv.x; o[4*d4+1] = o[4*d4+1]*al + vv.y;
                    o[4*d4+2] = o[4*d4+2]*al + vv.z; o[4*d4+3] = o[4*d4+3]*al + vv.w;
                }
            }
        }
        __syncthreads();
    }

    const float inv = 1.f / l;
    float4* ob = (float4*)(out + ((size_t)(b * SEQ + qi)) * DIM + h * HD);
#pragma unroll
    for (int d4 = 0; d4 < 16; ++d4)
        ob[d4] = make_float4(o[4*d4+0]*inv, o[4*d4+1]*inv, o[4*d4+2]*inv, o[4*d4+3]*inv);
}

// ----------------- fused residual-add + LayerNorm -------------------------
// y = LN(x + rscale*r) * g + b ; one block per row (768), 256 threads.
__global__ __launch_bounds__(256) void add_ln_kernel(const float* __restrict__ x,
    const float* __restrict__ r, float rscale, const float* __restrict__ gg,
    const float* __restrict__ bb, float* __restrict__ y)
{
    const int row = blockIdx.x;
    const int t = threadIdx.x;
    __shared__ float red[8];
    __shared__ float bc0, bc1;

    const float* xr = x + (size_t)row * DIM;
    const float* rr = r + (size_t)row * DIM;
    float v[3]; float s = 0.f;
#pragma unroll
    for (int i = 0; i < 3; ++i) { int c = t + i * 256; v[i] = xr[c] + rscale * rr[c]; s += v[i]; }
#pragma unroll
    for (int off = 16; off; off >>= 1) s += __shfl_xor_sync(0xffffffffu, s, off);
    if ((t & 31) == 0) red[t >> 5] = s;
    __syncthreads();
    if (t == 0) { float tot = 0.f;
#pragma unroll
        for (int w = 0; w < 8; ++w) tot += red[w];
        bc0 = tot * (1.f / DIM);
    }
    __syncthreads();
    const float mean = bc0;
    float sq = 0.f;
#pragma unroll
    for (int i = 0; i < 3; ++i) { float d = v[i] - mean; sq += d * d; }
#pragma unroll
    for (int off = 16; off; off >>= 1) sq += __shfl_xor_sync(0xffffffffu, sq, off);
    if ((t & 31) == 0) red[t >> 5] = sq;
    __syncthreads();
    if (t == 0) { float tot = 0.f;
#pragma unroll
        for (int w = 0; w < 8; ++w) tot += red[w];
        bc1 = rsqrtf(tot * (1.f / DIM) + 1e-5f);
    }
    __syncthreads();
    const float rstd = bc1;
#pragma unroll
    for (int i = 0; i < 3; ++i) {
        int c = t + i * 256;
        y[(size_t)row * DIM + c] = (v[i] - mean) * rstd * gg[c] + bb[c];
    }
}

// ----------------- delta-rule scan (SelfModifyingTitans) ------------------
// grid = B*NH blocks, 256 threads: thread (e = t&63, g = t>>6) owns
// M[d][e] for d in [16g, 16g+16).
__global__ __launch_bounds__(256) void delta_scan_kernel(const float* __restrict__ tq,
    const float* __restrict__ tk, const float* __restrict__ tv,
    float* __restrict__ t_o, float* __restrict__ Mout)
{
    const int bh = blockIdx.x;
    const int b = bh / NH, h = bh % NH;
    const int t = threadIdx.x;
    const int e = t & 63;
    const int g = t >> 6;

    __shared__ float ks[64], vs[64], qs[64];
    __shared__ float part[4][64];
    __shared__ float opart[4][64];

    float Mreg[16];
#pragma unroll
    for (int i = 0; i < 16; ++i) Mreg[i] = 0.f;

    const size_t base = ((size_t)b * SEQ) * DIM + h * HD + e;
    float nxt = 0.f;
    if (g == 0) nxt = tk[base];
    else if (g == 1) nxt = tv[base];
    else if (g == 2) nxt = tq[base];

    for (int s = 0; s < SEQ; ++s) {
        if (g == 0) ks[e] = nxt;
        else if (g == 1) vs[e] = nxt;
        else if (g == 2) qs[e] = nxt;
        __syncthreads();
        if (s + 1 < SEQ) {
            size_t nb = base + (size_t)(s + 1) * DIM;
            if (g == 0) nxt = tk[nb];
            else if (g == 1) nxt = tv[nb];
            else if (g == 2) nxt = tq[nb];
        }
        float kreg[16];
        float p0 = 0.f, p1 = 0.f, p2 = 0.f, p3 = 0.f;
#pragma unroll
        for (int i = 0; i < 16; i += 4) {
            kreg[i+0] = ks[g*16 + i+0]; kreg[i+1] = ks[g*16 + i+1];
            kreg[i+2] = ks[g*16 + i+2]; kreg[i+3] = ks[g*16 + i+3];
            p0 += Mreg[i+0]*kreg[i+0]; p1 += Mreg[i+1]*kreg[i+1];
            p2 += Mreg[i+2]*kreg[i+2]; p3 += Mreg[i+3]*kreg[i+3];
        }
        part[g][e] = (p0 + p1) + (p2 + p3);
        __syncthreads();
        const float pred  = (part[0][e] + part[1][e]) + (part[2][e] + part[3][e]);
        const float delta = LRATE * (vs[e] - pred);
        float q0 = 0.f, q1 = 0.f, q2 = 0.f, q3 = 0.f;
#pragma unroll
        for (int i = 0; i < 16; i += 4) {
            Mreg[i+0] += kreg[i+0]*delta; q0 += Mreg[i+0]*qs[g*16 + i+0];
            Mreg[i+1] += kreg[i+1]*delta; q1 += Mreg[i+1]*qs[g*16 + i+1];
            Mreg[i+2] += kreg[i+2]*delta; q2 += Mreg[i+2]*qs[g*16 + i+2];
            Mreg[i+3] += kreg[i+3]*delta; q3 += Mreg[i+3]*qs[g*16 + i+3];
        }
        opart[g][e] = (q0 + q1) + (q2 + q3);
        __syncthreads();
        if (g == 0)
            t_o[base + (size_t)s * DIM] =
                (opart[0][e] + opart[1][e]) + (opart[2][e] + opart[3][e]);
    }
    if (Mout) {
#pragma unroll
        for (int i = 0; i < 16; ++i)
            Mout[(((size_t)b * NH + h) * HD + (g * 16 + i)) * HD + e] = Mreg[i];
    }
}

// ----------------- small elementwise kernels -------------------------------
__global__ void concat_kernel(const float* __restrict__ a, const float* __restrict__ b,
                              float* __restrict__ c)
{
    int i = blockIdx.x * blockDim.x + threadIdx.x;
    if (i >= ROWS * 2 * DIM) return;
    int row = i / (2 * DIM), col = i % (2 * DIM);
    c[i] = (col < DIM) ? a[(size_t)row * DIM + col] : b[(size_t)row * DIM + col - DIM];
}

__global__ void combine_kernel(const float* __restrict__ gpre, const float* __restrict__ xl,
                               const float* __restrict__ xg, float* __restrict__ xc)
{
    int i = blockIdx.x * blockDim.x + threadIdx.x;
    if (i >= ROWS * DIM) return;
    float sgm = 1.f / (1.f + __expf(-gpre[i]));
    xc[i] = sgm * xl[i] + (1.f - sgm) * xg[i];
}

// ----------------- launch ---------------------------------------------------
static float* sym(const void* s) {
    void* p = nullptr;
    cudaGetSymbolAddress(&p, s);
    return (float*)p;
}

extern "C" void kernel_launch(void* const* d_in, const int* in_sizes, int n_in,
                              void* d_out, int out_size)
{
    const float* x          = (const float*)d_in[0];
    const float* in_proj_w  = (const float*)d_in[1];
    const float* in_proj_b  = (const float*)d_in[2];
    const float* out_proj_w = (const float*)d_in[3];
    const float* out_proj_b = (const float*)d_in[4];
    const float* ln_local_g = (const float*)d_in[5];
    const float* ln_local_b = (const float*)d_in[6];
    const float* t_wq       = (const float*)d_in[7];
    const float* t_wk       = (const float*)d_in[8];
    const float* t_wv       = (const float*)d_in[9];
    const float* t_wo       = (const float*)d_in[10];
    const float* ln_tit_g   = (const float*)d_in[11];
    const float* ln_tit_b   = (const float*)d_in[12];
    const float* gate_w     = (const float*)d_in[13];
    const float* gate_b     = (const float*)d_in[14];
    const float* cms_w1     = (const float*)d_in[15];
    const float* cms_b1     = (const float*)d_in[16];
    const float* cms_w2     = (const float*)d_in[17];
    const float* cms_b2     = (const float*)d_in[18];
    const float* ln_cms_g   = (const float*)d_in[19];
    const float* ln_cms_b   = (const float*)d_in[20];

    float* qkv    = sym(g_qkv);
    float* att    = sym(g_att);
    float* proj   = sym(g_proj);
    float* xlocal = sym(g_xlocal);
    float* xglob  = sym(g_xglobal);
    float* tq     = sym(g_tq);
    float* tk     = sym(g_tk);
    float* tv     = sym(g_tv);
    float* to_    = sym(g_to);
    float* xcat   = sym(g_xcat);
    float* xc     = sym(g_xc);
    float* hbuf   = sym(g_h);
    float* accb   = sym(g_acc);

    float* out = (float*)d_out;
    float* mout = (out_size >= ROWS * DIM + BATCH * NH * HD * HD)
                      ? out + (size_t)ROWS * DIM : nullptr;

    // 1) packed QKV projection
    gemm_nt<<<dim3(3 * DIM / GBN, ROWS / GBM), 256>>>(x, in_proj_w, in_proj_b, qkv,
                                                      ROWS, 3 * DIM, DIM, 0);
    // 2) sliding-window attention
    attn_kernel<<<dim3(SEQ / 64, BATCH, NH), 64>>>(qkv, att);
    // 3) out_proj + residual LN -> x_local
    gemm_nt<<<dim3(DIM / GBN, ROWS / GBM), 256>>>(att, out_proj_w, out_proj_b, proj,
                                                  ROWS, DIM, DIM, 0);
    add_ln_kernel<<<ROWS, 256>>>(x, proj, 1.f, ln_local_g, ln_local_b, xlocal);

    // 4) Titans projections
    gemm_nt<<<dim3(DIM / GBN, ROWS / GBM), 256>>>(x, t_wq, nullptr, tq, ROWS, DIM, DIM, 0);
    gemm_nt<<<dim3(DIM / GBN, ROWS / GBM), 256>>>(x, t_wk, nullptr, tk, ROWS, DIM, DIM, 0);
    gemm_nt<<<dim3(DIM / GBN, ROWS / GBM), 256>>>(x, t_wv, nullptr, tv, ROWS, DIM, DIM, 0);
    // 5) delta-rule scan (also writes memory_state to d_out tail)
    delta_scan_kernel<<<BATCH * NH, 256>>>(tq, tk, tv, to_, mout);
    // 6) titans out proj + residual LN -> x_global
    gemm_nt<<<dim3(DIM / GBN, ROWS / GBM), 256>>>(to_, t_wo, nullptr, proj, ROWS, DIM, DIM, 0);
    add_ln_kernel<<<ROWS, 256>>>(x, proj, 1.f, ln_tit_g, ln_tit_b, xglob);

    // 7) gate + combine
    concat_kernel<<<(ROWS * 2 * DIM + 255) / 256, 256>>>(xlocal, xglob, xcat);
    gemm_nt<<<dim3(DIM / GBN, ROWS / GBM), 256>>>(xcat, gate_w, gate_b, proj,
                                                  ROWS, DIM, 2 * DIM, 0);
    combine_kernel<<<(ROWS * DIM + 255) / 256, 256>>>(proj, xlocal, xglob, xc);

    // 8) CMS: 4 FFN levels accumulated
    for (int l = 0; l < 4; ++l) {
        gemm_nt<<<dim3(4 * DIM / GBN, ROWS / GBM), 256>>>(
            xc, cms_w1 + (size_t)l * 4 * DIM * DIM, cms_b1 + (size_t)l * 4 * DIM,
            hbuf, ROWS, 4 * DIM, DIM, 1);
        gemm_nt<<<dim3(DIM / GBN, ROWS / GBM), 256>>>(
            hbuf, cms_w2 + (size_t)l * DIM * 4 * DIM, cms_b2 + (size_t)l * DIM,
            accb, ROWS, DIM, 4 * DIM, (l == 0) ? 0 : 2);
    }
    // 9) final LN: out = LN(xc + mean(cms)) ; mean = acc * 0.25
    add_ln_kernel<<<ROWS, 256>>>(xc, accb, 0.25f, ln_cms_g, ln_cms_b, out);
}

// round 3
// speedup vs baseline: 1.4604x; 1.4604x over previous
#include <cuda_runtime.h>
#include <math.h>
#include <stdint.h>

#define SEQ   2048
#define BATCH 2
#define DIM   768
#define NH    12
#define HD    64
#define WIN   512
#define ROWS  (BATCH*SEQ)     // 4096
#define LRATE 0.1f

// ----------------- device scratch (no cudaMalloc allowed) -----------------
__device__ float g_qkv[ROWS*3*DIM];
__device__ float g_att[ROWS*DIM];
__device__ float g_proj[ROWS*DIM];
__device__ float g_xlocal[ROWS*DIM];
__device__ float g_xglobal[ROWS*DIM];
__device__ float g_tq[ROWS*DIM];
__device__ float g_tk[ROWS*DIM];
__device__ float g_tv[ROWS*DIM];
__device__ float g_to[ROWS*DIM];
__device__ float g_xc[ROWS*DIM];
__device__ float g_h[ROWS*4*DIM];
__device__ float g_acc[ROWS*DIM];

// ===================== mma.sync tf32x3 GEMM ================================
// C[M,N] = A[M,K](row-stride lda) @ W[N,K](row-stride ldw)^T (+bias)(+epi)
// epi: 0 = store, 1 = gelu, 2 = accumulate into C
#define TBM 128
#define TBN 128
#define TBK 32
#define GEMM_SMEM (2 * 2 * TBM * TBK * 4)   // 2 stages * (A+B) = 65536 B

#define CP_ASYNC16(dst, src) \
    asm volatile("cp.async.cg.shared.global [%0], [%1], 16;" :: "r"(dst), "l"(src))
#define CP_COMMIT() asm volatile("cp.async.commit_group;")
#define CP_WAIT1()  asm volatile("cp.async.wait_group 1;" ::: "memory")
#define CP_WAIT0()  asm volatile("cp.async.wait_group 0;" ::: "memory")

__device__ __forceinline__ uint32_t smem_u32(const void* p) {
    uint32_t a;
    asm("{ .reg .u64 t; cvta.to.shared.u64 t, %1; cvt.u32.u64 %0, t; }" : "=r"(a) : "l"(p));
    return a;
}
__device__ __forceinline__ void mma_tf32(float* c, uint32_t a0, uint32_t a1,
                                         uint32_t a2, uint32_t a3,
                                         uint32_t b0, uint32_t b1) {
    asm volatile("mma.sync.aligned.m16n8k8.row.col.f32.tf32.tf32.f32 "
                 "{%0,%1,%2,%3}, {%4,%5,%6,%7}, {%8,%9}, {%0,%1,%2,%3};"
                 : "+f"(c[0]), "+f"(c[1]), "+f"(c[2]), "+f"(c[3])
                 : "r"(a0), "r"(a1), "r"(a2), "r"(a3), "r"(b0), "r"(b1));
}
__device__ __forceinline__ int swz(int row, int col) {
    return row * 32 + (((col >> 2) ^ (row & 7)) << 2) + (col & 3);
}
__device__ __forceinline__ uint32_t hi_bits(float a) {
    return __float_as_uint(a) & 0xFFFFE000u;
}

__global__ __launch_bounds__(256) void gemm_tc(
    const float* __restrict__ A, int lda,
    const float* __restrict__ W, int ldw,
    const float* __restrict__ bias,
    float* __restrict__ C, int M, int N, int K, int epi)
{
    extern __shared__ float sm[];
    const int t   = threadIdx.x;
    const int lid = t & 31;
    const int wid = t >> 5;
    const int wm  = wid & 1;     // 2 warp-rows of 64
    const int wn  = wid >> 1;    // 4 warp-cols of 32
    const int grp = lid >> 2;
    const int tg  = lid & 3;
    const int bm  = blockIdx.y * TBM;
    const int bn  = blockIdx.x * TBN;

    float acc[4][4][4];
#pragma unroll
    for (int mi = 0; mi < 4; ++mi)
#pragma unroll
        for (int ni = 0; ni < 4; ++ni)
#pragma unroll
            for (int r = 0; r < 4; ++r) acc[mi][ni][r] = 0.f;

    const int row_l = t >> 1;          // 0..127 (load row)
    const int c4b   = (t & 1) << 2;    // 0 or 4 (float4 idx base; 2 per thread x4 iters)

    // stage loader: 1024 float4 per tile (A and B), 256 threads -> 4 iters
    auto ld_stage = [&](int buf, int k0) {
        float* sa = sm + buf * 8192;
        float* sb = sa + 4096;
#pragma unroll
        for (int i = 0; i < 4; ++i) {
            int f   = i * 256 + t;       // 0..1023
            int row = f >> 3, c4 = f & 7;
            int sw  = c4 ^ (row & 7);
            CP_ASYNC16(smem_u32(sa + row * 32 + sw * 4),
                       A + (size_t)(bm + row) * lda + k0 + c4 * 4);
            CP_ASYNC16(smem_u32(sb + row * 32 + sw * 4),
                       W + (size_t)(bn + row) * ldw + k0 + c4 * 4);
        }
    };
    (void)row_l; (void)c4b;

    const int nstage = K / TBK;
    ld_stage(0, 0); CP_COMMIT();
    ld_stage(1, TBK); CP_COMMIT();

    for (int s = 0; s < nstage; ++s) {
        if (s == nstage - 1) CP_WAIT0(); else CP_WAIT1();
        __syncthreads();
        const float* sa = sm + (s & 1) * 8192;
        const float* sb = sa + 4096;
#pragma unroll
        for (int kk = 0; kk < 4; ++kk) {
            const int c0 = kk * 8 + tg;
            uint32_t ah[4][4], al[4][4];
#pragma unroll
            for (int mi = 0; mi < 4; ++mi) {
                const int r0 = wm * 64 + mi * 16 + grp;
                const int r1 = r0 + 8;
                float a0 = sa[swz(r0, c0)];
                float a1 = sa[swz(r1, c0)];
                float a2 = sa[swz(r0, c0 + 4)];
                float a3 = sa[swz(r1, c0 + 4)];
                ah[mi][0] = hi_bits(a0); al[mi][0] = __float_as_uint(a0 - __uint_as_float(ah[mi][0]));
                ah[mi][1] = hi_bits(a1); al[mi][1] = __float_as_uint(a1 - __uint_as_float(ah[mi][1]));
                ah[mi][2] = hi_bits(a2); al[mi][2] = __float_as_uint(a2 - __uint_as_float(ah[mi][2]));
                ah[mi][3] = hi_bits(a3); al[mi][3] = __float_as_uint(a3 - __uint_as_float(ah[mi][3]));
            }
            uint32_t bh[4][2], bl[4][2];
#pragma unroll
            for (int ni = 0; ni < 4; ++ni) {
                const int nr = wn * 32 + ni * 8 + grp;
                float b0 = sb[swz(nr, c0)];
                float b1 = sb[swz(nr, c0 + 4)];
                bh[ni][0] = hi_bits(b0); bl[ni][0] = __float_as_uint(b0 - __uint_as_float(bh[ni][0]));
                bh[ni][1] = hi_bits(b1); bl[ni][1] = __float_as_uint(b1 - __uint_as_float(bh[ni][1]));
            }
#pragma unroll
            for (int mi = 0; mi < 4; ++mi)
#pragma unroll
                for (int ni = 0; ni < 4; ++ni)
                    mma_tf32(acc[mi][ni], ah[mi][0], ah[mi][1], ah[mi][2], ah[mi][3],
                             bh[ni][0], bh[ni][1]);
#pragma unroll
            for (int mi = 0; mi < 4; ++mi)
#pragma unroll
                for (int ni = 0; ni < 4; ++ni)
                    mma_tf32(acc[mi][ni], al[mi][0], al[mi][1], al[mi][2], al[mi][3],
                             bh[ni][0], bh[ni][1]);
#pragma unroll
            for (int mi = 0; mi < 4; ++mi)
#pragma unroll
                for (int ni = 0; ni < 4; ++ni)
                    mma_tf32(acc[mi][ni], ah[mi][0], ah[mi][1], ah[mi][2], ah[mi][3],
                             bl[ni][0], bl[ni][1]);
        }
        __syncthreads();
        if (s + 2 < nstage) { ld_stage(s & 1, (s + 2) * TBK); CP_COMMIT(); }
    }

    // ---------------- epilogue ----------------
#pragma unroll
    for (int mi = 0; mi < 4; ++mi) {
#pragma unroll
        for (int ni = 0; ni < 4; ++ni) {
            const int col = bn + wn * 32 + ni * 8 + 2 * tg;
            float bx = 0.f, by = 0.f;
            if (bias) { bx = bias[col]; by = bias[col + 1]; }
#pragma unroll
            for (int half = 0; half < 2; ++half) {
                const int row = bm + wm * 64 + mi * 16 + grp + half * 8;
                float v0 = acc[mi][ni][half * 2 + 0] + bx;
                float v1 = acc[mi][ni][half * 2 + 1] + by;
                float* Cp = C + (size_t)row * N + col;
                if (epi == 1) {
                    float u3;
                    u3 = v0 * v0 * v0;
                    v0 = 0.5f * v0 * (1.f + tanhf(0.7978845608028654f * (v0 + 0.044715f * u3)));
                    u3 = v1 * v1 * v1;
                    v1 = 0.5f * v1 * (1.f + tanhf(0.7978845608028654f * (v1 + 0.044715f * u3)));
                } else if (epi == 2) {
                    float2 old = *(const float2*)Cp;
                    v0 += old.x; v1 += old.y;
                }
                *(float2*)Cp = make_float2(v0, v1);
            }
        }
    }
}

// ----------------- sliding-window causal attention ------------------------
__global__ __launch_bounds__(64) void attn_kernel(const float* __restrict__ qkv,
                                                  float* __restrict__ out)
{
    const int qt = blockIdx.x;
    const int b  = blockIdx.y;
    const int h  = blockIdx.z;
    const int t  = threadIdx.x;
    const int qi = qt * 64 + t;

    __shared__ __align__(16) float ks[64][64];
    __shared__ __align__(16) float vs[64][64];

    float q[64], o[64];
    {
        const float4* qb = (const float4*)(qkv + ((size_t)(b * SEQ + qi)) * (3 * DIM) + h * HD);
#pragma unroll
        for (int d4 = 0; d4 < 16; ++d4) {
            float4 v = qb[d4];
            q[4*d4+0] = v.x * 0.125f; q[4*d4+1] = v.y * 0.125f;
            q[4*d4+2] = v.z * 0.125f; q[4*d4+3] = v.w * 0.125f;
        }
    }
#pragma unroll
    for (int d = 0; d < 64; ++d) o[d] = 0.f;
    float m = -1e30f, l = 0.f;

    const int kt0 = (qt >= 8) ? (qt - 8) : 0;
    for (int kt = kt0; kt <= qt; ++kt) {
        const float* kbase = qkv + ((size_t)(b * SEQ + kt * 64)) * (3 * DIM) + DIM + h * HD + t;
        const float* vbase = kbase + DIM;
        for (int r = 0; r < 64; ++r) {
            ks[r][t] = kbase[(size_t)r * (3 * DIM)];
            vs[r][t] = vbase[(size_t)r * (3 * DIM)];
        }
        __syncthreads();

        int jlo = qi - WIN + 1 - kt * 64; if (jlo < 0)  jlo = 0;
        int jhi = qi - kt * 64;           if (jhi > 63) jhi = 63;
        for (int j = jlo; j <= jhi; ++j) {
            float s = 0.f;
            const float4* kr = (const float4*)ks[j];
#pragma unroll
            for (int d4 = 0; d4 < 16; ++d4) {
                float4 kv = kr[d4];
                s += q[4*d4+0]*kv.x + q[4*d4+1]*kv.y + q[4*d4+2]*kv.z + q[4*d4+3]*kv.w;
            }
            const float4* vr = (const float4*)vs[j];
            if (s <= m) {
                float p = __expf(s - m);
                l += p;
#pragma unroll
                for (int d4 = 0; d4 < 16; ++d4) {
                    float4 vv = vr[d4];
                    o[4*d4+0] += p*vv.x; o[4*d4+1] += p*vv.y;
                    o[4*d4+2] += p*vv.z; o[4*d4+3] += p*vv.w;
                }
            } else {
                float al = __expf(m - s);
                m = s; l = l * al + 1.f;
#pragma unroll
                for (int d4 = 0; d4 < 16; ++d4) {
                    float4 vv = vr[d4];
                    o[4*d4+0] = o[4*d4+0]*al + vv.x; o[4*d4+1] = o[4*d4+1]*al + vv.y;
                    o[4*d4+2] = o[4*d4+2]*al + vv.z; o[4*d4+3] = o[4*d4+3]*al + vv.w;
                }
            }
        }
        __syncthreads();
    }

    const float inv = 1.f / l;
    float4* ob = (float4*)(out + ((size_t)(b * SEQ + qi)) * DIM + h * HD);
#pragma unroll
    for (int d4 = 0; d4 < 16; ++d4)
        ob[d4] = make_float4(o[4*d4+0]*inv, o[4*d4+1]*inv, o[4*d4+2]*inv, o[4*d4+3]*inv);
}

// ----------------- fused residual-add + LayerNorm -------------------------
__global__ __launch_bounds__(256) void add_ln_kernel(const float* __restrict__ x,
    const float* __restrict__ r, float rscale, const float* __restrict__ gg,
    const float* __restrict__ bb, float* __restrict__ y)
{
    const int row = blockIdx.x;
    const int t = threadIdx.x;
    __shared__ float red[8];
    __shared__ float bc0, bc1;

    const float* xr = x + (size_t)row * DIM;
    const float* rr = r + (size_t)row * DIM;
    float v[3]; float s = 0.f;
#pragma unroll
    for (int i = 0; i < 3; ++i) { int c = t + i * 256; v[i] = xr[c] + rscale * rr[c]; s += v[i]; }
#pragma unroll
    for (int off = 16; off; off >>= 1) s += __shfl_xor_sync(0xffffffffu, s, off);
    if ((t & 31) == 0) red[t >> 5] = s;
    __syncthreads();
    if (t == 0) { float tot = 0.f;
#pragma unroll
        for (int w = 0; w < 8; ++w) tot += red[w];
        bc0 = tot * (1.f / DIM);
    }
    __syncthreads();
    const float mean = bc0;
    float sq = 0.f;
#pragma unroll
    for (int i = 0; i < 3; ++i) { float d = v[i] - mean; sq += d * d; }
#pragma unroll
    for (int off = 16; off; off >>= 1) sq += __shfl_xor_sync(0xffffffffu, sq, off);
    if ((t & 31) == 0) red[t >> 5] = sq;
    __syncthreads();
    if (t == 0) { float tot = 0.f;
#pragma unroll
        for (int w = 0; w < 8; ++w) tot += red[w];
        bc1 = rsqrtf(tot * (1.f / DIM) + 1e-5f);
    }
    __syncthreads();
    const float rstd = bc1;
#pragma unroll
    for (int i = 0; i < 3; ++i) {
        int c = t + i * 256;
        y[(size_t)row * DIM + c] = (v[i] - mean) * rstd * gg[c] + bb[c];
    }
}

// ----------------- delta-rule scan (SelfModifyingTitans) ------------------
__global__ __launch_bounds__(256) void delta_scan_kernel(const float* __restrict__ tq,
    const float* __restrict__ tk, const float* __restrict__ tv,
    float* __restrict__ t_o, float* __restrict__ Mout)
{
    const int bh = blockIdx.x;
    const int b = bh / NH, h = bh % NH;
    const int t = threadIdx.x;
    const int e = t & 63;
    const int g = t >> 6;

    __shared__ float ks[64], vs[64], qs[64];
    __shared__ float part[4][64];
    __shared__ float opart[4][64];

    float Mreg[16];
#pragma unroll
    for (int i = 0; i < 16; ++i) Mreg[i] = 0.f;

    const size_t base = ((size_t)b * SEQ) * DIM + h * HD + e;
    float nxt = 0.f;
    if (g == 0) nxt = tk[base];
    else if (g == 1) nxt = tv[base];
    else if (g == 2) nxt = tq[base];

    for (int s = 0; s < SEQ; ++s) {
        if (g == 0) ks[e] = nxt;
        else if (g == 1) vs[e] = nxt;
        else if (g == 2) qs[e] = nxt;
        __syncthreads();
        if (s + 1 < SEQ) {
            size_t nb = base + (size_t)(s + 1) * DIM;
            if (g == 0) nxt = tk[nb];
            else if (g == 1) nxt = tv[nb];
            else if (g == 2) nxt = tq[nb];
        }
        float kreg[16];
        float p0 = 0.f, p1 = 0.f, p2 = 0.f, p3 = 0.f;
#pragma unroll
        for (int i = 0; i < 16; i += 4) {
            kreg[i+0] = ks[g*16 + i+0]; kreg[i+1] = ks[g*16 + i+1];
            kreg[i+2] = ks[g*16 + i+2]; kreg[i+3] = ks[g*16 + i+3];
            p0 += Mreg[i+0]*kreg[i+0]; p1 += Mreg[i+1]*kreg[i+1];
            p2 += Mreg[i+2]*kreg[i+2]; p3 += Mreg[i+3]*kreg[i+3];
        }
        part[g][e] = (p0 + p1) + (p2 + p3);
        __syncthreads();
        const float pred  = (part[0][e] + part[1][e]) + (part[2][e] + part[3][e]);
        const float delta = LRATE * (vs[e] - pred);
        float q0 = 0.f, q1 = 0.f, q2 = 0.f, q3 = 0.f;
#pragma unroll
        for (int i = 0; i < 16; i += 4) {
            Mreg[i+0] += kreg[i+0]*delta; q0 += Mreg[i+0]*qs[g*16 + i+0];
            Mreg[i+1] += kreg[i+1]*delta; q1 += Mreg[i+1]*qs[g*16 + i+1];
            Mreg[i+2] += kreg[i+2]*delta; q2 += Mreg[i+2]*qs[g*16 + i+2];
            Mreg[i+3] += kreg[i+3]*delta; q3 += Mreg[i+3]*qs[g*16 + i+3];
        }
        opart[g][e] = (q0 + q1) + (q2 + q3);
        __syncthreads();
        if (g == 0)
            t_o[base + (size_t)s * DIM] =
                (opart[0][e] + opart[1][e]) + (opart[2][e] + opart[3][e]);
    }
    if (Mout) {
#pragma unroll
        for (int i = 0; i < 16; ++i)
            Mout[(((size_t)b * NH + h) * HD + (g * 16 + i)) * HD + e] = Mreg[i];
    }
}

// ----------------- gated combine -------------------------------------------
__global__ void combine_kernel(const float* __restrict__ gpre, const float* __restrict__ xl,
                               const float* __restrict__ xg, float* __restrict__ xc)
{
    int i = blockIdx.x * blockDim.x + threadIdx.x;
    if (i >= ROWS * DIM) return;
    float sgm = 1.f / (1.f + __expf(-gpre[i]));
    xc[i] = sgm * xl[i] + (1.f - sgm) * xg[i];
}

// ----------------- launch ---------------------------------------------------
static float* sym(const void* s) {
    void* p = nullptr;
    cudaGetSymbolAddress(&p, s);
    return (float*)p;
}

extern "C" void kernel_launch(void* const* d_in, const int* in_sizes, int n_in,
                              void* d_out, int out_size)
{
    const float* x          = (const float*)d_in[0];
    const float* in_proj_w  = (const float*)d_in[1];
    const float* in_proj_b  = (const float*)d_in[2];
    const float* out_proj_w = (const float*)d_in[3];
    const float* out_proj_b = (const float*)d_in[4];
    const float* ln_local_g = (const float*)d_in[5];
    const float* ln_local_b = (const float*)d_in[6];
    const float* t_wq       = (const float*)d_in[7];
    const float* t_wk       = (const float*)d_in[8];
    const float* t_wv       = (const float*)d_in[9];
    const float* t_wo       = (const float*)d_in[10];
    const float* ln_tit_g   = (const float*)d_in[11];
    const float* ln_tit_b   = (const float*)d_in[12];
    const float* gate_w     = (const float*)d_in[13];
    const float* gate_b     = (const float*)d_in[14];
    const float* cms_w1     = (const float*)d_in[15];
    const float* cms_b1     = (const float*)d_in[16];
    const float* cms_w2     = (const float*)d_in[17];
    const float* cms_b2     = (const float*)d_in[18];
    const float* ln_cms_g   = (const float*)d_in[19];
    const float* ln_cms_b   = (const float*)d_in[20];

    float* qkv    = sym(g_qkv);
    float* att    = sym(g_att);
    float* proj   = sym(g_proj);
    float* xlocal = sym(g_xlocal);
    float* xglob  = sym(g_xglobal);
    float* tq     = sym(g_tq);
    float* tk     = sym(g_tk);
    float* tv     = sym(g_tv);
    float* to_    = sym(g_to);
    float* xc     = sym(g_xc);
    float* hbuf   = sym(g_h);
    float* accb   = sym(g_acc);

    float* out = (float*)d_out;
    float* mout = (out_size >= ROWS * DIM + BATCH * NH * HD * HD)
                      ? out + (size_t)ROWS * DIM : nullptr;

    static int smem_set = 0;
    if (!smem_set) {
        cudaFuncSetAttribute(gemm_tc, cudaFuncAttributeMaxDynamicSharedMemorySize, GEMM_SMEM);
        smem_set = 1;
    }

    // 1) packed QKV projection
    gemm_tc<<<dim3(3 * DIM / TBN, ROWS / TBM), 256, GEMM_SMEM>>>(
        x, DIM, in_proj_w, DIM, in_proj_b, qkv, ROWS, 3 * DIM, DIM, 0);
    // 2) sliding-window attention
    attn_kernel<<<dim3(SEQ / 64, BATCH, NH), 64>>>(qkv, att);
    // 3) out_proj + residual LN -> x_local
    gemm_tc<<<dim3(DIM / TBN, ROWS / TBM), 256, GEMM_SMEM>>>(
        att, DIM, out_proj_w, DIM, out_proj_b, proj, ROWS, DIM, DIM, 0);
    add_ln_kernel<<<ROWS, 256>>>(x, proj, 1.f, ln_local_g, ln_local_b, xlocal);

    // 4) Titans projections
    gemm_tc<<<dim3(DIM / TBN, ROWS / TBM), 256, GEMM_SMEM>>>(
        x, DIM, t_wq, DIM, nullptr, tq, ROWS, DIM, DIM, 0);
    gemm_tc<<<dim3(DIM / TBN, ROWS / TBM), 256, GEMM_SMEM>>>(
        x, DIM, t_wk, DIM, nullptr, tk, ROWS, DIM, DIM, 0);
    gemm_tc<<<dim3(DIM / TBN, ROWS / TBM), 256, GEMM_SMEM>>>(
        x, DIM, t_wv, DIM, nullptr, tv, ROWS, DIM, DIM, 0);
    // 5) delta-rule scan (also writes memory_state to d_out tail)
    delta_scan_kernel<<<BATCH * NH, 256>>>(tq, tk, tv, to_, mout);
    // 6) titans out proj + residual LN -> x_global
    gemm_tc<<<dim3(DIM / TBN, ROWS / TBM), 256, GEMM_SMEM>>>(
        to_, DIM, t_wo, DIM, nullptr, proj, ROWS, DIM, DIM, 0);
    add_ln_kernel<<<ROWS, 256>>>(x, proj, 1.f, ln_tit_g, ln_tit_b, xglob);

    // 7) gate (split-K over the concat: W = [W1 | W2]) + combine
    gemm_tc<<<dim3(DIM / TBN, ROWS / TBM), 256, GEMM_SMEM>>>(
        xlocal, DIM, gate_w, 2 * DIM, gate_b, proj, ROWS, DIM, DIM, 0);
    gemm_tc<<<dim3(DIM / TBN, ROWS / TBM), 256, GEMM_SMEM>>>(
        xglob, DIM, gate_w + DIM, 2 * DIM, nullptr, proj, ROWS, DIM, DIM, 2);
    combine_kernel<<<(ROWS * DIM + 255) / 256, 256>>>(proj, xlocal, xglob, xc);

    // 8) CMS: 4 FFN levels accumulated
    for (int l = 0; l < 4; ++l) {
        gemm_tc<<<dim3(4 * DIM / TBN, ROWS / TBM), 256, GEMM_SMEM>>>(
            xc, DIM, cms_w1 + (size_t)l * 4 * DIM * DIM, DIM,
            cms_b1 + (size_t)l * 4 * DIM, hbuf, ROWS, 4 * DIM, DIM, 1);
        gemm_tc<<<dim3(DIM / TBN, ROWS / TBM), 256, GEMM_SMEM>>>(
            hbuf, 4 * DIM, cms_w2 + (size_t)l * DIM * 4 * DIM, 4 * DIM,
            cms_b2 + (size_t)l * DIM, accb, ROWS, DIM, 4 * DIM, (l == 0) ? 0 : 2);
    }
    // 9) final LN: out = LN(xc + mean(cms)) ; mean = acc * 0.25
    add_ln_kernel<<<ROWS, 256>>>(xc, accb, 0.25f, ln_cms_g, ln_cms_b, out);
}

// round 4
// speedup vs baseline: 1.7850x; 1.2223x over previous
#include <cuda_runtime.h>
#include <math.h>
#include <stdint.h>

#define SEQ   2048
#define BATCH 2
#define DIM   768
#define NH    12
#define HD    64
#define WIN   512
#define ROWS  (BATCH*SEQ)     // 4096
#define LRATE 0.1f

// ----------------- device scratch (no cudaMalloc allowed) -----------------
__device__ float g_qkv[ROWS*3*DIM];
__device__ float g_att[ROWS*DIM];
__device__ float g_proj[ROWS*DIM];
__device__ float g_xlocal[ROWS*DIM];
__device__ float g_xglobal[ROWS*DIM];
__device__ float g_tq[ROWS*DIM];
__device__ float g_tk[ROWS*DIM];
__device__ float g_tv[ROWS*DIM];
__device__ float g_to[ROWS*DIM];
__device__ float g_xc[ROWS*DIM];
__device__ float g_h[4*(size_t)ROWS*4*DIM];     // 4 CMS levels of hidden
__device__ float g_cms[4*(size_t)ROWS*DIM];     // 4 CMS level outputs

// ===================== mma.sync tf32x3 GEMM ================================
// C[M,N] = A[M,K] @ W[N,K]^T (+bias)(+epi), z-batched via blockIdx.z.
// epi: 0 = store, 1 = gelu, 2 = accumulate, 3 = sigmoid-gate combine
#define TBM 128
#define TBN 128
#define TBK 32
#define NSTG 4
#define STG_F (2 * TBM * TBK)               // floats per stage (A+B) = 8192
#define GEMM_SMEM (NSTG * STG_F * 4)        // 131072 B

#define CP_ASYNC16(dst, src) \
    asm volatile("cp.async.cg.shared.global [%0], [%1], 16;" :: "r"(dst), "l"(src))
#define CP_COMMIT() asm volatile("cp.async.commit_group;")
#define CP_WAIT2()  asm volatile("cp.async.wait_group 2;" ::: "memory")

struct B4 {
    const float* A[4];
    const float* W[4];
    const float* bias[4];
    float*       C[4];
    const float* A2;     // optional second pair (gate)
    const float* W2;
    const float* xl;     // epi==3 operands
    const float* xg;
};

__device__ __forceinline__ uint32_t smem_u32(const void* p) {
    uint32_t a;
    asm("{ .reg .u64 t; cvta.to.shared.u64 t, %1; cvt.u32.u64 %0, t; }" : "=r"(a) : "l"(p));
    return a;
}
__device__ __forceinline__ void mma_tf32(float* c, uint32_t a0, uint32_t a1,
                                         uint32_t a2, uint32_t a3,
                                         uint32_t b0, uint32_t b1) {
    asm volatile("mma.sync.aligned.m16n8k8.row.col.f32.tf32.tf32.f32 "
                 "{%0,%1,%2,%3}, {%4,%5,%6,%7}, {%8,%9}, {%0,%1,%2,%3};"
                 : "+f"(c[0]), "+f"(c[1]), "+f"(c[2]), "+f"(c[3])
                 : "r"(a0), "r"(a1), "r"(a2), "r"(a3), "r"(b0), "r"(b1));
}
__device__ __forceinline__ int swz(int row, int col) {
    return row * 32 + (((col >> 2) ^ (row & 7)) << 2) + (col & 3);
}
__device__ __forceinline__ uint32_t hi_bits(float a) {
    return __float_as_uint(a) & 0xFFFFE000u;
}

__global__ __launch_bounds__(256) void gemm_tc(
    B4 b, int lda, int ldw, int N, int K, int epi)
{
    extern __shared__ float sm[];
    const int t   = threadIdx.x;
    const int lid = t & 31;
    const int wid = t >> 5;
    const int wm  = wid & 1;
    const int wn  = wid >> 1;
    const int grp = lid >> 2;
    const int tg  = lid & 3;
    const int bm  = blockIdx.y * TBM;
    const int bn  = blockIdx.x * TBN;
    const int z   = blockIdx.z;

    const float* A    = b.A[z];
    const float* W    = b.W[z];
    const float* bias = b.bias[z];
    float*       C    = b.C[z];

    float acc[4][4][4];
#pragma unroll
    for (int mi = 0; mi < 4; ++mi)
#pragma unroll
        for (int ni = 0; ni < 4; ++ni)
#pragma unroll
            for (int r = 0; r < 4; ++r) acc[mi][ni][r] = 0.f;

    const int nstage = K / TBK;
    const int npass  = b.A2 ? 2 : 1;

    for (int pass = 0; pass < npass; ++pass) {
        const float* Ap = pass ? b.A2 : A;
        const float* Wp = pass ? b.W2 : W;
        __syncthreads();   // protect smem reuse across passes

        auto ld_stage = [&](int buf, int k0) {
            float* sa = sm + buf * STG_F;
            float* sb = sa + 4096;
#pragma unroll
            for (int i = 0; i < 4; ++i) {
                int f   = i * 256 + t;       // 0..1023
                int row = f >> 3, c4 = f & 7;
                int sw  = c4 ^ (row & 7);
                CP_ASYNC16(smem_u32(sa + row * 32 + sw * 4),
                           Ap + (size_t)(bm + row) * lda + k0 + c4 * 4);
                CP_ASYNC16(smem_u32(sb + row * 32 + sw * 4),
                           Wp + (size_t)(bn + row) * ldw + k0 + c4 * 4);
            }
        };

        ld_stage(0, 0);       CP_COMMIT();
        ld_stage(1, TBK);     CP_COMMIT();
        ld_stage(2, 2 * TBK); CP_COMMIT();

        for (int s = 0; s < nstage; ++s) {
            CP_WAIT2();
            __syncthreads();
            if (s + 3 < nstage) { ld_stage((s + 3) & 3, (s + 3) * TBK); CP_COMMIT(); }

            const float* sa = sm + (s & 3) * STG_F;
            const float* sb = sa + 4096;
#pragma unroll
            for (int kk = 0; kk < 4; ++kk) {
                const int c0 = kk * 8 + tg;
                uint32_t ah[4][4], al[4][4];
#pragma unroll
                for (int mi = 0; mi < 4; ++mi) {
                    const int r0 = wm * 64 + mi * 16 + grp;
                    const int r1 = r0 + 8;
                    float a0 = sa[swz(r0, c0)];
                    float a1 = sa[swz(r1, c0)];
                    float a2 = sa[swz(r0, c0 + 4)];
                    float a3 = sa[swz(r1, c0 + 4)];
                    ah[mi][0] = hi_bits(a0); al[mi][0] = __float_as_uint(a0 - __uint_as_float(ah[mi][0]));
                    ah[mi][1] = hi_bits(a1); al[mi][1] = __float_as_uint(a1 - __uint_as_float(ah[mi][1]));
                    ah[mi][2] = hi_bits(a2); al[mi][2] = __float_as_uint(a2 - __uint_as_float(ah[mi][2]));
                    ah[mi][3] = hi_bits(a3); al[mi][3] = __float_as_uint(a3 - __uint_as_float(ah[mi][3]));
                }
                uint32_t bh[4][2], bl[4][2];
#pragma unroll
                for (int ni = 0; ni < 4; ++ni) {
                    const int nr = wn * 32 + ni * 8 + grp;
                    float b0 = sb[swz(nr, c0)];
                    float b1 = sb[swz(nr, c0 + 4)];
                    bh[ni][0] = hi_bits(b0); bl[ni][0] = __float_as_uint(b0 - __uint_as_float(bh[ni][0]));
                    bh[ni][1] = hi_bits(b1); bl[ni][1] = __float_as_uint(b1 - __uint_as_float(bh[ni][1]));
                }
#pragma unroll
                for (int mi = 0; mi < 4; ++mi)
#pragma unroll
                    for (int ni = 0; ni < 4; ++ni)
                        mma_tf32(acc[mi][ni], ah[mi][0], ah[mi][1], ah[mi][2], ah[mi][3],
                                 bh[ni][0], bh[ni][1]);
#pragma unroll
                for (int mi = 0; mi < 4; ++mi)
#pragma unroll
                    for (int ni = 0; ni < 4; ++ni)
                        mma_tf32(acc[mi][ni], al[mi][0], al[mi][1], al[mi][2], al[mi][3],
                                 bh[ni][0], bh[ni][1]);
#pragma unroll
                for (int mi = 0; mi < 4; ++mi)
#pragma unroll
                    for (int ni = 0; ni < 4; ++ni)
                        mma_tf32(acc[mi][ni], ah[mi][0], ah[mi][1], ah[mi][2], ah[mi][3],
                                 bl[ni][0], bl[ni][1]);
            }
        }
    }

    // ---------------- epilogue ----------------
#pragma unroll
    for (int mi = 0; mi < 4; ++mi) {
#pragma unroll
        for (int ni = 0; ni < 4; ++ni) {
            const int col = bn + wn * 32 + ni * 8 + 2 * tg;
            float bx = 0.f, by = 0.f;
            if (bias) { bx = bias[col]; by = bias[col + 1]; }
#pragma unroll
            for (int half = 0; half < 2; ++half) {
                const int row = bm + wm * 64 + mi * 16 + grp + half * 8;
                float v0 = acc[mi][ni][half * 2 + 0] + bx;
                float v1 = acc[mi][ni][half * 2 + 1] + by;
                float* Cp = C + (size_t)row * N + col;
                if (epi == 1) {
                    float u3;
                    u3 = v0 * v0 * v0;
                    v0 = 0.5f * v0 * (1.f + tanhf(0.7978845608028654f * (v0 + 0.044715f * u3)));
                    u3 = v1 * v1 * v1;
                    v1 = 0.5f * v1 * (1.f + tanhf(0.7978845608028654f * (v1 + 0.044715f * u3)));
                } else if (epi == 2) {
                    float2 old = *(const float2*)Cp;
                    v0 += old.x; v1 += old.y;
                } else if (epi == 3) {
                    const size_t idx = (size_t)row * N + col;
                    float s0 = 1.f / (1.f + __expf(-v0));
                    float s1 = 1.f / (1.f + __expf(-v1));
                    float2 xl2 = *(const float2*)(b.xl + idx);
                    float2 xg2 = *(const float2*)(b.xg + idx);
                    v0 = s0 * xl2.x + (1.f - s0) * xg2.x;
                    v1 = s1 * xl2.y + (1.f - s1) * xg2.y;
                }
                *(float2*)Cp = make_float2(v0, v1);
            }
        }
    }
}

// ----------------- sliding-window causal attention ------------------------
__global__ __launch_bounds__(64) void attn_kernel(const float* __restrict__ qkv,
                                                  float* __restrict__ out)
{
    const int qt = blockIdx.x;
    const int b  = blockIdx.y;
    const int h  = blockIdx.z;
    const int t  = threadIdx.x;
    const int qi = qt * 64 + t;

    __shared__ __align__(16) float ks[64][64];
    __shared__ __align__(16) float vs[64][64];

    float q[64], o[64];
    {
        const float4* qb = (const float4*)(qkv + ((size_t)(b * SEQ + qi)) * (3 * DIM) + h * HD);
#pragma unroll
        for (int d4 = 0; d4 < 16; ++d4) {
            float4 v = qb[d4];
            q[4*d4+0] = v.x * 0.125f; q[4*d4+1] = v.y * 0.125f;
            q[4*d4+2] = v.z * 0.125f; q[4*d4+3] = v.w * 0.125f;
        }
    }
#pragma unroll
    for (int d = 0; d < 64; ++d) o[d] = 0.f;
    float m = -1e30f, l = 0.f;

    const int kt0 = (qt >= 8) ? (qt - 8) : 0;
    for (int kt = kt0; kt <= qt; ++kt) {
        const float* kbase = qkv + ((size_t)(b * SEQ + kt * 64)) * (3 * DIM) + DIM + h * HD + t;
        const float* vbase = kbase + DIM;
        for (int r = 0; r < 64; ++r) {
            ks[r][t] = kbase[(size_t)r * (3 * DIM)];
            vs[r][t] = vbase[(size_t)r * (3 * DIM)];
        }
        __syncthreads();

        int jlo = qi - WIN + 1 - kt * 64; if (jlo < 0)  jlo = 0;
        int jhi = qi - kt * 64;           if (jhi > 63) jhi = 63;
        for (int j = jlo; j <= jhi; ++j) {
            float s = 0.f;
            const float4* kr = (const float4*)ks[j];
#pragma unroll
            for (int d4 = 0; d4 < 16; ++d4) {
                float4 kv = kr[d4];
                s += q[4*d4+0]*kv.x + q[4*d4+1]*kv.y + q[4*d4+2]*kv.z + q[4*d4+3]*kv.w;
            }
            const float4* vr = (const float4*)vs[j];
            if (s <= m) {
                float p = __expf(s - m);
                l += p;
#pragma unroll
                for (int d4 = 0; d4 < 16; ++d4) {
                    float4 vv = vr[d4];
                    o[4*d4+0] += p*vv.x; o[4*d4+1] += p*vv.y;
                    o[4*d4+2] += p*vv.z; o[4*d4+3] += p*vv.w;
                }
            } else {
                float al = __expf(m - s);
                m = s; l = l * al + 1.f;
#pragma unroll
                for (int d4 = 0; d4 < 16; ++d4) {
                    float4 vv = vr[d4];
                    o[4*d4+0] = o[4*d4+0]*al + vv.x; o[4*d4+1] = o[4*d4+1]*al + vv.y;
                    o[4*d4+2] = o[4*d4+2]*al + vv.z; o[4*d4+3] = o[4*d4+3]*al + vv.w;
                }
            }
        }
        __syncthreads();
    }

    const float inv = 1.f / l;
    float4* ob = (float4*)(out + ((size_t)(b * SEQ + qi)) * DIM + h * HD);
#pragma unroll
    for (int d4 = 0; d4 < 16; ++d4)
        ob[d4] = make_float4(o[4*d4+0]*inv, o[4*d4+1]*inv, o[4*d4+2]*inv, o[4*d4+3]*inv);
}

// ----------------- fused residual-add + LayerNorm -------------------------
__global__ __launch_bounds__(256) void add_ln_kernel(const float* __restrict__ x,
    const float* __restrict__ r, float rscale, const float* __restrict__ gg,
    const float* __restrict__ bb, float* __restrict__ y)
{
    const int row = blockIdx.x;
    const int t = threadIdx.x;
    __shared__ float red[8];
    __shared__ float bc0, bc1;

    const float* xr = x + (size_t)row * DIM;
    const float* rr = r + (size_t)row * DIM;
    float v[3]; float s = 0.f;
#pragma unroll
    for (int i = 0; i < 3; ++i) { int c = t + i * 256; v[i] = xr[c] + rscale * rr[c]; s += v[i]; }
#pragma unroll
    for (int off = 16; off; off >>= 1) s += __shfl_xor_sync(0xffffffffu, s, off);
    if ((t & 31) == 0) red[t >> 5] = s;
    __syncthreads();
    if (t == 0) { float tot = 0.f;
#pragma unroll
        for (int w = 0; w < 8; ++w) tot += red[w];
        bc0 = tot * (1.f / DIM);
    }
    __syncthreads();
    const float mean = bc0;
    float sq = 0.f;
#pragma unroll
    for (int i = 0; i < 3; ++i) { float d = v[i] - mean; sq += d * d; }
#pragma unroll
    for (int off = 16; off; off >>= 1) sq += __shfl_xor_sync(0xffffffffu, sq, off);
    if ((t & 31) == 0) red[t >> 5] = sq;
    __syncthreads();
    if (t == 0) { float tot = 0.f;
#pragma unroll
        for (int w = 0; w < 8; ++w) tot += red[w];
        bc1 = rsqrtf(tot * (1.f / DIM) + 1e-5f);
    }
    __syncthreads();
    const float rstd = bc1;
#pragma unroll
    for (int i = 0; i < 3; ++i) {
        int c = t + i * 256;
        y[(size_t)row * DIM + c] = (v[i] - mean) * rstd * gg[c] + bb[c];
    }
}

// ----------------- final LN with 4-way CMS mean ----------------------------
__global__ __launch_bounds__(256) void ln_final_kernel(const float* __restrict__ xc,
    const float* __restrict__ c0, const float* __restrict__ c1,
    const float* __restrict__ c2, const float* __restrict__ c3,
    const float* __restrict__ gg, const float* __restrict__ bb,
    float* __restrict__ y)
{
    const int row = blockIdx.x;
    const int t = threadIdx.x;
    __shared__ float red[8];
    __shared__ float bc0, bc1;

    const size_t rb = (size_t)row * DIM;
    float v[3]; float s = 0.f;
#pragma unroll
    for (int i = 0; i < 3; ++i) {
        int c = t + i * 256;
        v[i] = xc[rb + c] + 0.25f * (c0[rb + c] + c1[rb + c] + c2[rb + c] + c3[rb + c]);
        s += v[i];
    }
#pragma unroll
    for (int off = 16; off; off >>= 1) s += __shfl_xor_sync(0xffffffffu, s, off);
    if ((t & 31) == 0) red[t >> 5] = s;
    __syncthreads();
    if (t == 0) { float tot = 0.f;
#pragma unroll
        for (int w = 0; w < 8; ++w) tot += red[w];
        bc0 = tot * (1.f / DIM);
    }
    __syncthreads();
    const float mean = bc0;
    float sq = 0.f;
#pragma unroll
    for (int i = 0; i < 3; ++i) { float d = v[i] - mean; sq += d * d; }
#pragma unroll
    for (int off = 16; off; off >>= 1) sq += __shfl_xor_sync(0xffffffffu, sq, off);
    if ((t & 31) == 0) red[t >> 5] = sq;
    __syncthreads();
    if (t == 0) { float tot = 0.f;
#pragma unroll
        for (int w = 0; w < 8; ++w) tot += red[w];
        bc1 = rsqrtf(tot * (1.f / DIM) + 1e-5f);
    }
    __syncthreads();
    const float rstd = bc1;
#pragma unroll
    for (int i = 0; i < 3; ++i) {
        int c = t + i * 256;
        y[rb + c] = (v[i] - mean) * rstd * gg[c] + bb[c];
    }
}

// ----------------- delta-rule scan (SelfModifyingTitans) ------------------
__global__ __launch_bounds__(256) void delta_scan_kernel(const float* __restrict__ tq,
    const float* __restrict__ tk, const float* __restrict__ tv,
    float* __restrict__ t_o, float* __restrict__ Mout)
{
    const int bh = blockIdx.x;
    const int b = bh / NH, h = bh % NH;
    const int t = threadIdx.x;
    const int e = t & 63;
    const int g = t >> 6;

    __shared__ float ks[64], vs[64], qs[64];
    __shared__ float part[4][64];
    __shared__ float opart[4][64];

    float Mreg[16];
#pragma unroll
    for (int i = 0; i < 16; ++i) Mreg[i] = 0.f;

    const size_t base = ((size_t)b * SEQ) * DIM + h * HD + e;
    float nxt = 0.f;
    if (g == 0) nxt = tk[base];
    else if (g == 1) nxt = tv[base];
    else if (g == 2) nxt = tq[base];

    for (int s = 0; s < SEQ; ++s) {
        if (g == 0) ks[e] = nxt;
        else if (g == 1) vs[e] = nxt;
        else if (g == 2) qs[e] = nxt;
        __syncthreads();
        if (s + 1 < SEQ) {
            size_t nb = base + (size_t)(s + 1) * DIM;
            if (g == 0) nxt = tk[nb];
            else if (g == 1) nxt = tv[nb];
            else if (g == 2) nxt = tq[nb];
        }
        float kreg[16];
        float p0 = 0.f, p1 = 0.f, p2 = 0.f, p3 = 0.f;
#pragma unroll
        for (int i = 0; i < 16; i += 4) {
            kreg[i+0] = ks[g*16 + i+0]; kreg[i+1] = ks[g*16 + i+1];
            kreg[i+2] = ks[g*16 + i+2]; kreg[i+3] = ks[g*16 + i+3];
            p0 += Mreg[i+0]*kreg[i+0]; p1 += Mreg[i+1]*kreg[i+1];
            p2 += Mreg[i+2]*kreg[i+2]; p3 += Mreg[i+3]*kreg[i+3];
        }
        part[g][e] = (p0 + p1) + (p2 + p3);
        __syncthreads();
        const float pred  = (part[0][e] + part[1][e]) + (part[2][e] + part[3][e]);
        const float delta = LRATE * (vs[e] - pred);
        float q0 = 0.f, q1 = 0.f, q2 = 0.f, q3 = 0.f;
#pragma unroll
        for (int i = 0; i < 16; i += 4) {
            Mreg[i+0] += kreg[i+0]*delta; q0 += Mreg[i+0]*qs[g*16 + i+0];
            Mreg[i+1] += kreg[i+1]*delta; q1 += Mreg[i+1]*qs[g*16 + i+1];
            Mreg[i+2] += kreg[i+2]*delta; q2 += Mreg[i+2]*qs[g*16 + i+2];
            Mreg[i+3] += kreg[i+3]*delta; q3 += Mreg[i+3]*qs[g*16 + i+3];
        }
        opart[g][e] = (q0 + q1) + (q2 + q3);
        __syncthreads();
        if (g == 0)
            t_o[base + (size_t)s * DIM] =
                (opart[0][e] + opart[1][e]) + (opart[2][e] + opart[3][e]);
    }
    if (Mout) {
#pragma unroll
        for (int i = 0; i < 16; ++i)
            Mout[(((size_t)b * NH + h) * HD + (g * 16 + i)) * HD + e] = Mreg[i];
    }
}

// ----------------- launch ---------------------------------------------------
static float* sym(const void* s) {
    void* p = nullptr;
    cudaGetSymbolAddress(&p, s);
    return (float*)p;
}

extern "C" void kernel_launch(void* const* d_in, const int* in_sizes, int n_in,
                              void* d_out, int out_size)
{
    const float* x          = (const float*)d_in[0];
    const float* in_proj_w  = (const float*)d_in[1];
    const float* in_proj_b  = (const float*)d_in[2];
    const float* out_proj_w = (const float*)d_in[3];
    const float* out_proj_b = (const float*)d_in[4];
    const float* ln_local_g = (const float*)d_in[5];
    const float* ln_local_b = (const float*)d_in[6];
    const float* t_wq       = (const float*)d_in[7];
    const float* t_wk       = (const float*)d_in[8];
    const float* t_wv       = (const float*)d_in[9];
    const float* t_wo       = (const float*)d_in[10];
    const float* ln_tit_g   = (const float*)d_in[11];
    const float* ln_tit_b   = (const float*)d_in[12];
    const float* gate_w     = (const float*)d_in[13];
    const float* gate_b     = (const float*)d_in[14];
    const float* cms_w1     = (const float*)d_in[15];
    const float* cms_b1     = (const float*)d_in[16];
    const float* cms_w2     = (const float*)d_in[17];
    const float* cms_b2     = (const float*)d_in[18];
    const float* ln_cms_g   = (const float*)d_in[19];
    const float* ln_cms_b   = (const float*)d_in[20];

    float* qkv    = sym(g_qkv);
    float* att    = sym(g_att);
    float* proj   = sym(g_proj);
    float* xlocal = sym(g_xlocal);
    float* xglob  = sym(g_xglobal);
    float* tq     = sym(g_tq);
    float* tk     = sym(g_tk);
    float* tv     = sym(g_tv);
    float* to_    = sym(g_to);
    float* xc     = sym(g_xc);
    float* hbuf   = sym(g_h);
    float* cmsb   = sym(g_cms);

    float* out = (float*)d_out;
    float* mout = (out_size >= ROWS * DIM + BATCH * NH * HD * HD)
                      ? out + (size_t)ROWS * DIM : nullptr;

    static int smem_set = 0;
    if (!smem_set) {
        cudaFuncSetAttribute(gemm_tc, cudaFuncAttributeMaxDynamicSharedMemorySize, GEMM_SMEM);
        smem_set = 1;
    }

    B4 b{};

    // 1) packed QKV projection
    b = B4{};
    b.A[0] = x; b.W[0] = in_proj_w; b.bias[0] = in_proj_b; b.C[0] = qkv;
    gemm_tc<<<dim3(3 * DIM / TBN, ROWS / TBM, 1), 256, GEMM_SMEM>>>(b, DIM, DIM, 3 * DIM, DIM, 0);

    // 2) sliding-window attention
    attn_kernel<<<dim3(SEQ / 64, BATCH, NH), 64>>>(qkv, att);

    // 3) out_proj + residual LN -> x_local
    b = B4{};
    b.A[0] = att; b.W[0] = out_proj_w; b.bias[0] = out_proj_b; b.C[0] = proj;
    gemm_tc<<<dim3(DIM / TBN, ROWS / TBM, 1), 256, GEMM_SMEM>>>(b, DIM, DIM, DIM, DIM, 0);
    add_ln_kernel<<<ROWS, 256>>>(x, proj, 1.f, ln_local_g, ln_local_b, xlocal);

    // 4) Titans projections (z-batched x3)
    b = B4{};
    b.A[0] = x;  b.W[0] = t_wq; b.C[0] = tq;
    b.A[1] = x;  b.W[1] = t_wk; b.C[1] = tk;
    b.A[2] = x;  b.W[2] = t_wv; b.C[2] = tv;
    gemm_tc<<<dim3(DIM / TBN, ROWS / TBM, 3), 256, GEMM_SMEM>>>(b, DIM, DIM, DIM, DIM, 0);

    // 5) delta-rule scan (also writes memory_state to d_out tail)
    delta_scan_kernel<<<BATCH * NH, 256>>>(tq, tk, tv, to_, mout);

    // 6) titans out proj + residual LN -> x_global
    b = B4{};
    b.A[0] = to_; b.W[0] = t_wo; b.C[0] = proj;
    gemm_tc<<<dim3(DIM / TBN, ROWS / TBM, 1), 256, GEMM_SMEM>>>(b, DIM, DIM, DIM, DIM, 0);
    add_ln_kernel<<<ROWS, 256>>>(x, proj, 1.f, ln_tit_g, ln_tit_b, xglob);

    // 7) gate: two K-passes over [xlocal|xglob] with fused sigmoid-combine
    b = B4{};
    b.A[0] = xlocal; b.W[0] = gate_w; b.bias[0] = gate_b; b.C[0] = xc;
    b.A2 = xglob; b.W2 = gate_w + DIM;
    b.xl = xlocal; b.xg = xglob;
    gemm_tc<<<dim3(DIM / TBN, ROWS / TBM, 1), 256, GEMM_SMEM>>>(b, DIM, 2 * DIM, DIM, DIM, 3);

    // 8) CMS: w1 x4 (gelu), z-batched
    b = B4{};
    for (int l = 0; l < 4; ++l) {
        b.A[l]    = xc;
        b.W[l]    = cms_w1 + (size_t)l * 4 * DIM * DIM;
        b.bias[l] = cms_b1 + (size_t)l * 4 * DIM;
        b.C[l]    = hbuf + (size_t)l * ROWS * 4 * DIM;
    }
    gemm_tc<<<dim3(4 * DIM / TBN, ROWS / TBM, 4), 256, GEMM_SMEM>>>(b, DIM, DIM, 4 * DIM, DIM, 1);

    //    CMS: w2 x4, z-batched, per-level outputs
    b = B4{};
    for (int l = 0; l < 4; ++l) {
        b.A[l]    = hbuf + (size_t)l * ROWS * 4 * DIM;
        b.W[l]    = cms_w2 + (size_t)l * DIM * 4 * DIM;
        b.bias[l] = cms_b2 + (size_t)l * DIM;
        b.C[l]    = cmsb + (size_t)l * ROWS * DIM;
    }
    gemm_tc<<<dim3(DIM / TBN, ROWS / TBM, 4), 256, GEMM_SMEM>>>(b, 4 * DIM, 4 * DIM, DIM, 4 * DIM, 0);

    // 9) final LN: out = LN(xc + mean over levels)
    ln_final_kernel<<<ROWS, 256>>>(xc, cmsb, cmsb + (size_t)ROWS * DIM,
                                   cmsb + 2 * (size_t)ROWS * DIM, cmsb + 3 * (size_t)ROWS * DIM,
                                   ln_cms_g, ln_cms_b, out);
}

// round 5
// speedup vs baseline: 1.9008x; 1.0649x over previous
#include <cuda_runtime.h>
#include <math.h>
#include <stdint.h>

#define SEQ   2048
#define BATCH 2
#define DIM   768
#define NH    12
#define HD    64
#define WIN   512
#define ROWS  (BATCH*SEQ)     // 4096
#define LRATE 0.1f

// ----------------- device scratch (no cudaMalloc allowed) -----------------
__device__ float g_qkv[ROWS*3*DIM];
__device__ float g_att[ROWS*DIM];
__device__ float g_proj[ROWS*DIM];
__device__ float g_proj2[ROWS*DIM];
__device__ float g_xlocal[ROWS*DIM];
__device__ float g_xglobal[ROWS*DIM];
__device__ float g_tq[ROWS*DIM];
__device__ float g_tk[ROWS*DIM];
__device__ float g_tv[ROWS*DIM];
__device__ float g_to[ROWS*DIM];
__device__ float g_xc[ROWS*DIM];
__device__ float g_h[4*(size_t)ROWS*4*DIM];     // 4 CMS levels of hidden
__device__ float g_cms[4*(size_t)ROWS*DIM];     // 4 CMS level outputs

// ===================== mma.sync tf32x3 GEMM ================================
// C[M,N] = A[M,K] @ W[N,K]^T (+bias)(+epi), z-batched via blockIdx.z.
// epi: 0 = store, 1 = gelu, 2 = accumulate, 3 = sigmoid-gate combine
#define TBM 128
#define TBN 128
#define TBK 32
#define NSTG 3
#define STG_F (2 * TBM * TBK)               // floats per stage (A+B) = 8192
#define GEMM_SMEM (NSTG * STG_F * 4)        // 98304 B -> 2 blocks/SM

#define CP_ASYNC16(dst, src) \
    asm volatile("cp.async.cg.shared.global [%0], [%1], 16;" :: "r"(dst), "l"(src))
#define CP_COMMIT() asm volatile("cp.async.commit_group;")
#define CP_WAIT1()  asm volatile("cp.async.wait_group 1;" ::: "memory")
#define CP_WAIT0()  asm volatile("cp.async.wait_group 0;" ::: "memory")

struct B4 {
    const float* A[4];
    const float* W[4];
    const float* bias[4];
    float*       C[4];
    const float* A2;     // optional second pair (gate)
    const float* W2;
    const float* xl;     // epi==3 operands
    const float* xg;
};

__device__ __forceinline__ uint32_t smem_u32(const void* p) {
    uint32_t a;
    asm("{ .reg .u64 t; cvta.to.shared.u64 t, %1; cvt.u32.u64 %0, t; }" : "=r"(a) : "l"(p));
    return a;
}
__device__ __forceinline__ void mma_tf32(float* c, uint32_t a0, uint32_t a1,
                                         uint32_t a2, uint32_t a3,
                                         uint32_t b0, uint32_t b1) {
    asm volatile("mma.sync.aligned.m16n8k8.row.col.f32.tf32.tf32.f32 "
                 "{%0,%1,%2,%3}, {%4,%5,%6,%7}, {%8,%9}, {%0,%1,%2,%3};"
                 : "+f"(c[0]), "+f"(c[1]), "+f"(c[2]), "+f"(c[3])
                 : "r"(a0), "r"(a1), "r"(a2), "r"(a3), "r"(b0), "r"(b1));
}
__device__ __forceinline__ int swz(int row, int col) {
    return row * 32 + (((col >> 2) ^ (row & 7)) << 2) + (col & 3);
}
__device__ __forceinline__ uint32_t hi_bits(float a) {
    return __float_as_uint(a) & 0xFFFFE000u;
}

__global__ __launch_bounds__(256, 2) void gemm_tc(
    B4 b, int lda, int ldw, int N, int K, int epi)
{
    extern __shared__ float sm[];
    const int t   = threadIdx.x;
    const int lid = t & 31;
    const int wid = t >> 5;
    const int wm  = wid & 1;
    const int wn  = wid >> 1;
    const int grp = lid >> 2;
    const int tg  = lid & 3;
    const int bm  = blockIdx.y * TBM;
    const int bn  = blockIdx.x * TBN;
    const int z   = blockIdx.z;

    const float* A    = b.A[z];
    const float* W    = b.W[z];
    const float* bias = b.bias[z];
    float*       C    = b.C[z];

    float acc[4][4][4];
#pragma unroll
    for (int mi = 0; mi < 4; ++mi)
#pragma unroll
        for (int ni = 0; ni < 4; ++ni)
#pragma unroll
            for (int r = 0; r < 4; ++r) acc[mi][ni][r] = 0.f;

    const int nstage = K / TBK;
    const int npass  = b.A2 ? 2 : 1;

    for (int pass = 0; pass < npass; ++pass) {
        const float* Ap = pass ? b.A2 : A;
        const float* Wp = pass ? b.W2 : W;
        __syncthreads();   // protect smem reuse across passes

        auto ld_stage = [&](int buf, int k0) {
            float* sa = sm + buf * STG_F;
            float* sb = sa + 4096;
#pragma unroll
            for (int i = 0; i < 4; ++i) {
                int f   = i * 256 + t;       // 0..1023
                int row = f >> 3, c4 = f & 7;
                int sw  = c4 ^ (row & 7);
                CP_ASYNC16(smem_u32(sa + row * 32 + sw * 4),
                           Ap + (size_t)(bm + row) * lda + k0 + c4 * 4);
                CP_ASYNC16(smem_u32(sb + row * 32 + sw * 4),
                           Wp + (size_t)(bn + row) * ldw + k0 + c4 * 4);
            }
        };

        ld_stage(0, 0);   CP_COMMIT();
        ld_stage(1, TBK); CP_COMMIT();

        for (int s = 0; s < nstage; ++s) {
            if (s == nstage - 1) CP_WAIT0(); else CP_WAIT1();
            __syncthreads();
            int sidx = s % 3;
            int nidx = (s + 2) % 3;
            if (s + 2 < nstage) { ld_stage(nidx, (s + 2) * TBK); CP_COMMIT(); }

            const float* sa = sm + sidx * STG_F;
            const float* sb = sa + 4096;
#pragma unroll
            for (int kk = 0; kk < 4; ++kk) {
                const int c0 = kk * 8 + tg;
                uint32_t bh[4][2], bl[4][2];
#pragma unroll
                for (int ni = 0; ni < 4; ++ni) {
                    const int nr = wn * 32 + ni * 8 + grp;
                    float b0 = sb[swz(nr, c0)];
                    float b1 = sb[swz(nr, c0 + 4)];
                    bh[ni][0] = hi_bits(b0); bl[ni][0] = __float_as_uint(b0 - __uint_as_float(bh[ni][0]));
                    bh[ni][1] = hi_bits(b1); bl[ni][1] = __float_as_uint(b1 - __uint_as_float(bh[ni][1]));
                }
#pragma unroll
                for (int mi = 0; mi < 4; ++mi) {
                    const int r0 = wm * 64 + mi * 16 + grp;
                    float a0 = sa[swz(r0, c0)];
                    float a1 = sa[swz(r0 + 8, c0)];
                    float a2 = sa[swz(r0, c0 + 4)];
                    float a3 = sa[swz(r0 + 8, c0 + 4)];
                    uint32_t ah0 = hi_bits(a0), al0 = __float_as_uint(a0 - __uint_as_float(ah0));
                    uint32_t ah1 = hi_bits(a1), al1 = __float_as_uint(a1 - __uint_as_float(ah1));
                    uint32_t ah2 = hi_bits(a2), al2 = __float_as_uint(a2 - __uint_as_float(ah2));
                    uint32_t ah3 = hi_bits(a3), al3 = __float_as_uint(a3 - __uint_as_float(ah3));
#pragma unroll
                    for (int ni = 0; ni < 4; ++ni)
                        mma_tf32(acc[mi][ni], ah0, ah1, ah2, ah3, bh[ni][0], bh[ni][1]);
#pragma unroll
                    for (int ni = 0; ni < 4; ++ni)
                        mma_tf32(acc[mi][ni], al0, al1, al2, al3, bh[ni][0], bh[ni][1]);
#pragma unroll
                    for (int ni = 0; ni < 4; ++ni)
                        mma_tf32(acc[mi][ni], ah0, ah1, ah2, ah3, bl[ni][0], bl[ni][1]);
                }
            }
        }
    }

    // ---------------- epilogue ----------------
#pragma unroll
    for (int mi = 0; mi < 4; ++mi) {
#pragma unroll
        for (int ni = 0; ni < 4; ++ni) {
            const int col = bn + wn * 32 + ni * 8 + 2 * tg;
            float bx = 0.f, by = 0.f;
            if (bias) { bx = bias[col]; by = bias[col + 1]; }
#pragma unroll
            for (int half = 0; half < 2; ++half) {
                const int row = bm + wm * 64 + mi * 16 + grp + half * 8;
                float v0 = acc[mi][ni][half * 2 + 0] + bx;
                float v1 = acc[mi][ni][half * 2 + 1] + by;
                float* Cp = C + (size_t)row * N + col;
                if (epi == 1) {
                    float u3;
                    u3 = v0 * v0 * v0;
                    v0 = 0.5f * v0 * (1.f + tanhf(0.7978845608028654f * (v0 + 0.044715f * u3)));
                    u3 = v1 * v1 * v1;
                    v1 = 0.5f * v1 * (1.f + tanhf(0.7978845608028654f * (v1 + 0.044715f * u3)));
                } else if (epi == 2) {
                    float2 old = *(const float2*)Cp;
                    v0 += old.x; v1 += old.y;
                } else if (epi == 3) {
                    const size_t idx = (size_t)row * N + col;
                    float s0 = 1.f / (1.f + __expf(-v0));
                    float s1 = 1.f / (1.f + __expf(-v1));
                    float2 xl2 = *(const float2*)(b.xl + idx);
                    float2 xg2 = *(const float2*)(b.xg + idx);
                    v0 = s0 * xl2.x + (1.f - s0) * xg2.x;
                    v1 = s1 * xl2.y + (1.f - s1) * xg2.y;
                }
                *(float2*)Cp = make_float2(v0, v1);
            }
        }
    }
}

// ----------------- sliding-window causal attention ------------------------
__global__ __launch_bounds__(64) void attn_kernel(const float* __restrict__ qkv,
                                                  float* __restrict__ out)
{
    const int qt = blockIdx.x;
    const int b  = blockIdx.y;
    const int h  = blockIdx.z;
    const int t  = threadIdx.x;
    const int qi = qt * 64 + t;

    __shared__ __align__(16) float ks[64][64];
    __shared__ __align__(16) float vs[64][64];

    float q[64], o[64];
    {
        const float4* qb = (const float4*)(qkv + ((size_t)(b * SEQ + qi)) * (3 * DIM) + h * HD);
#pragma unroll
        for (int d4 = 0; d4 < 16; ++d4) {
            float4 v = qb[d4];
            q[4*d4+0] = v.x * 0.125f; q[4*d4+1] = v.y * 0.125f;
            q[4*d4+2] = v.z * 0.125f; q[4*d4+3] = v.w * 0.125f;
        }
    }
#pragma unroll
    for (int d = 0; d < 64; ++d) o[d] = 0.f;
    float m = -1e30f, l = 0.f;

    const int kt0 = (qt >= 8) ? (qt - 8) : 0;
    for (int kt = kt0; kt <= qt; ++kt) {
        const float* kbase = qkv + ((size_t)(b * SEQ + kt * 64)) * (3 * DIM) + DIM + h * HD + t;
        const float* vbase = kbase + DIM;
        for (int r = 0; r < 64; ++r) {
            ks[r][t] = kbase[(size_t)r * (3 * DIM)];
            vs[r][t] = vbase[(size_t)r * (3 * DIM)];
        }
        __syncthreads();

        int jlo = qi - WIN + 1 - kt * 64; if (jlo < 0)  jlo = 0;
        int jhi = qi - kt * 64;           if (jhi > 63) jhi = 63;
        for (int j = jlo; j <= jhi; ++j) {
            float s = 0.f;
            const float4* kr = (const float4*)ks[j];
#pragma unroll
            for (int d4 = 0; d4 < 16; ++d4) {
                float4 kv = kr[d4];
                s += q[4*d4+0]*kv.x + q[4*d4+1]*kv.y + q[4*d4+2]*kv.z + q[4*d4+3]*kv.w;
            }
            const float4* vr = (const float4*)vs[j];
            if (s <= m) {
                float p = __expf(s - m);
                l += p;
#pragma unroll
                for (int d4 = 0; d4 < 16; ++d4) {
                    float4 vv = vr[d4];
                    o[4*d4+0] += p*vv.x; o[4*d4+1] += p*vv.y;
                    o[4*d4+2] += p*vv.z; o[4*d4+3] += p*vv.w;
                }
            } else {
                float al = __expf(m - s);
                m = s; l = l * al + 1.f;
#pragma unroll
                for (int d4 = 0; d4 < 16; ++d4) {
                    float4 vv = vr[d4];
                    o[4*d4+0] = o[4*d4+0]*al + vv.x; o[4*d4+1] = o[4*d4+1]*al + vv.y;
                    o[4*d4+2] = o[4*d4+2]*al + vv.z; o[4*d4+3] = o[4*d4+3]*al + vv.w;
                }
            }
        }
        __syncthreads();
    }

    const float inv = 1.f / l;
    float4* ob = (float4*)(out + ((size_t)(b * SEQ + qi)) * DIM + h * HD);
#pragma unroll
    for (int d4 = 0; d4 < 16; ++d4)
        ob[d4] = make_float4(o[4*d4+0]*inv, o[4*d4+1]*inv, o[4*d4+2]*inv, o[4*d4+3]*inv);
}

// ----------------- fused residual-add + LayerNorm -------------------------
__global__ __launch_bounds__(256) void add_ln_kernel(const float* __restrict__ x,
    const float* __restrict__ r, float rscale, const float* __restrict__ gg,
    const float* __restrict__ bb, float* __restrict__ y)
{
    const int row = blockIdx.x;
    const int t = threadIdx.x;
    __shared__ float red[8];
    __shared__ float bc0, bc1;

    const float* xr = x + (size_t)row * DIM;
    const float* rr = r + (size_t)row * DIM;
    float v[3]; float s = 0.f;
#pragma unroll
    for (int i = 0; i < 3; ++i) { int c = t + i * 256; v[i] = xr[c] + rscale * rr[c]; s += v[i]; }
#pragma unroll
    for (int off = 16; off; off >>= 1) s += __shfl_xor_sync(0xffffffffu, s, off);
    if ((t & 31) == 0) red[t >> 5] = s;
    __syncthreads();
    if (t == 0) { float tot = 0.f;
#pragma unroll
        for (int w = 0; w < 8; ++w) tot += red[w];
        bc0 = tot * (1.f / DIM);
    }
    __syncthreads();
    const float mean = bc0;
    float sq = 0.f;
#pragma unroll
    for (int i = 0; i < 3; ++i) { float d = v[i] - mean; sq += d * d; }
#pragma unroll
    for (int off = 16; off; off >>= 1) sq += __shfl_xor_sync(0xffffffffu, sq, off);
    if ((t & 31) == 0) red[t >> 5] = sq;
    __syncthreads();
    if (t == 0) { float tot = 0.f;
#pragma unroll
        for (int w = 0; w < 8; ++w) tot += red[w];
        bc1 = rsqrtf(tot * (1.f / DIM) + 1e-5f);
    }
    __syncthreads();
    const float rstd = bc1;
#pragma unroll
    for (int i = 0; i < 3; ++i) {
        int c = t + i * 256;
        y[(size_t)row * DIM + c] = (v[i] - mean) * rstd * gg[c] + bb[c];
    }
}

// ----------------- final LN with 4-way CMS mean ----------------------------
__global__ __launch_bounds__(256) void ln_final_kernel(const float* __restrict__ xc,
    const float* __restrict__ c0, const float* __restrict__ c1,
    const float* __restrict__ c2, const float* __restrict__ c3,
    const float* __restrict__ gg, const float* __restrict__ bb,
    float* __restrict__ y)
{
    const int row = blockIdx.x;
    const int t = threadIdx.x;
    __shared__ float red[8];
    __shared__ float bc0, bc1;

    const size_t rb = (size_t)row * DIM;
    float v[3]; float s = 0.f;
#pragma unroll
    for (int i = 0; i < 3; ++i) {
        int c = t + i * 256;
        v[i] = xc[rb + c] + 0.25f * (c0[rb + c] + c1[rb + c] + c2[rb + c] + c3[rb + c]);
        s += v[i];
    }
#pragma unroll
    for (int off = 16; off; off >>= 1) s += __shfl_xor_sync(0xffffffffu, s, off);
    if ((t & 31) == 0) red[t >> 5] = s;
    __syncthreads();
    if (t == 0) { float tot = 0.f;
#pragma unroll
        for (int w = 0; w < 8; ++w) tot += red[w];
        bc0 = tot * (1.f / DIM);
    }
    __syncthreads();
    const float mean = bc0;
    float sq = 0.f;
#pragma unroll
    for (int i = 0; i < 3; ++i) { float d = v[i] - mean; sq += d * d; }
#pragma unroll
    for (int off = 16; off; off >>= 1) sq += __shfl_xor_sync(0xffffffffu, sq, off);
    if ((t & 31) == 0) red[t >> 5] = sq;
    __syncthreads();
    if (t == 0) { float tot = 0.f;
#pragma unroll
        for (int w = 0; w < 8; ++w) tot += red[w];
        bc1 = rsqrtf(tot * (1.f / DIM) + 1e-5f);
    }
    __syncthreads();
    const float rstd = bc1;
#pragma unroll
    for (int i = 0; i < 3; ++i) {
        int c = t + i * 256;
        y[rb + c] = (v[i] - mean) * rstd * gg[c] + bb[c];
    }
}

// ----------------- delta-rule scan (SelfModifyingTitans) ------------------
__global__ __launch_bounds__(256) void delta_scan_kernel(const float* __restrict__ tq,
    const float* __restrict__ tk, const float* __restrict__ tv,
    float* __restrict__ t_o, float* __restrict__ Mout)
{
    const int bh = blockIdx.x;
    const int b = bh / NH, h = bh % NH;
    const int t = threadIdx.x;
    const int e = t & 63;
    const int g = t >> 6;

    __shared__ float ks[64], vs[64], qs[64];
    __shared__ float part[4][64];
    __shared__ float opart[4][64];

    float Mreg[16];
#pragma unroll
    for (int i = 0; i < 16; ++i) Mreg[i] = 0.f;

    const size_t base = ((size_t)b * SEQ) * DIM + h * HD + e;
    float nxt = 0.f;
    if (g == 0) nxt = tk[base];
    else if (g == 1) nxt = tv[base];
    else if (g == 2) nxt = tq[base];

    for (int s = 0; s < SEQ; ++s) {
        if (g == 0) ks[e] = nxt;
        else if (g == 1) vs[e] = nxt;
        else if (g == 2) qs[e] = nxt;
        __syncthreads();
        if (s + 1 < SEQ) {
            size_t nb = base + (size_t)(s + 1) * DIM;
            if (g == 0) nxt = tk[nb];
            else if (g == 1) nxt = tv[nb];
            else if (g == 2) nxt = tq[nb];
        }
        float kreg[16];
        float p0 = 0.f, p1 = 0.f, p2 = 0.f, p3 = 0.f;
#pragma unroll
        for (int i = 0; i < 16; i += 4) {
            kreg[i+0] = ks[g*16 + i+0]; kreg[i+1] = ks[g*16 + i+1];
            kreg[i+2] = ks[g*16 + i+2]; kreg[i+3] = ks[g*16 + i+3];
            p0 += Mreg[i+0]*kreg[i+0]; p1 += Mreg[i+1]*kreg[i+1];
            p2 += Mreg[i+2]*kreg[i+2]; p3 += Mreg[i+3]*kreg[i+3];
        }
        part[g][e] = (p0 + p1) + (p2 + p3);
        __syncthreads();
        const float pred  = (part[0][e] + part[1][e]) + (part[2][e] + part[3][e]);
        const float delta = LRATE * (vs[e] - pred);
        float q0 = 0.f, q1 = 0.f, q2 = 0.f, q3 = 0.f;
#pragma unroll
        for (int i = 0; i < 16; i += 4) {
            Mreg[i+0] += kreg[i+0]*delta; q0 += Mreg[i+0]*qs[g*16 + i+0];
            Mreg[i+1] += kreg[i+1]*delta; q1 += Mreg[i+1]*qs[g*16 + i+1];
            Mreg[i+2] += kreg[i+2]*delta; q2 += Mreg[i+2]*qs[g*16 + i+2];
            Mreg[i+3] += kreg[i+3]*delta; q3 += Mreg[i+3]*qs[g*16 + i+3];
        }
        opart[g][e] = (q0 + q1) + (q2 + q3);
        __syncthreads();
        if (g == 0)
            t_o[base + (size_t)s * DIM] =
                (opart[0][e] + opart[1][e]) + (opart[2][e] + opart[3][e]);
    }
    if (Mout) {
#pragma unroll
        for (int i = 0; i < 16; ++i)
            Mout[(((size_t)b * NH + h) * HD + (g * 16 + i)) * HD + e] = Mreg[i];
    }
}

// ----------------- launch ---------------------------------------------------
static float* sym(const void* s) {
    void* p = nullptr;
    cudaGetSymbolAddress(&p, s);
    return (float*)p;
}

extern "C" void kernel_launch(void* const* d_in, const int* in_sizes, int n_in,
                              void* d_out, int out_size)
{
    const float* x          = (const float*)d_in[0];
    const float* in_proj_w  = (const float*)d_in[1];
    const float* in_proj_b  = (const float*)d_in[2];
    const float* out_proj_w = (const float*)d_in[3];
    const float* out_proj_b = (const float*)d_in[4];
    const float* ln_local_g = (const float*)d_in[5];
    const float* ln_local_b = (const float*)d_in[6];
    const float* t_wq       = (const float*)d_in[7];
    const float* t_wk       = (const float*)d_in[8];
    const float* t_wv       = (const float*)d_in[9];
    const float* t_wo       = (const float*)d_in[10];
    const float* ln_tit_g   = (const float*)d_in[11];
    const float* ln_tit_b   = (const float*)d_in[12];
    const float* gate_w     = (const float*)d_in[13];
    const float* gate_b     = (const float*)d_in[14];
    const float* cms_w1     = (const float*)d_in[15];
    const float* cms_b1     = (const float*)d_in[16];
    const float* cms_w2     = (const float*)d_in[17];
    const float* cms_b2     = (const float*)d_in[18];
    const float* ln_cms_g   = (const float*)d_in[19];
    const float* ln_cms_b   = (const float*)d_in[20];

    float* qkv    = sym(g_qkv);
    float* att    = sym(g_att);
    float* proj   = sym(g_proj);
    float* proj2  = sym(g_proj2);
    float* xlocal = sym(g_xlocal);
    float* xglob  = sym(g_xglobal);
    float* tq     = sym(g_tq);
    float* tk     = sym(g_tk);
    float* tv     = sym(g_tv);
    float* to_    = sym(g_to);
    float* xc     = sym(g_xc);
    float* hbuf   = sym(g_h);
    float* cmsb   = sym(g_cms);

    float* out = (float*)d_out;
    float* mout = (out_size >= ROWS * DIM + BATCH * NH * HD * HD)
                      ? out + (size_t)ROWS * DIM : nullptr;

    static cudaStream_t s2 = nullptr;
    static cudaEvent_t ev_fork = nullptr, ev_join = nullptr;
    if (!s2) {
        cudaFuncSetAttribute(gemm_tc, cudaFuncAttributeMaxDynamicSharedMemorySize, GEMM_SMEM);
        cudaStreamCreateWithFlags(&s2, cudaStreamNonBlocking);
        cudaEventCreateWithFlags(&ev_fork, cudaEventDisableTiming);
        cudaEventCreateWithFlags(&ev_join, cudaEventDisableTiming);
    }

    B4 b{};

    // ---- fork: titans branch runs on s2 concurrently with local branch ----
    cudaEventRecord(ev_fork, 0);
    cudaStreamWaitEvent(s2, ev_fork, 0);

    // [s2] Titans projections (z-batched x3)
    b = B4{};
    b.A[0] = x;  b.W[0] = t_wq; b.C[0] = tq;
    b.A[1] = x;  b.W[1] = t_wk; b.C[1] = tk;
    b.A[2] = x;  b.W[2] = t_wv; b.C[2] = tv;
    gemm_tc<<<dim3(DIM / TBN, ROWS / TBM, 3), 256, GEMM_SMEM, s2>>>(b, DIM, DIM, DIM, DIM, 0);

    // [s2] delta-rule scan (also writes memory_state to d_out tail)
    delta_scan_kernel<<<BATCH * NH, 256, 0, s2>>>(tq, tk, tv, to_, mout);

    // [s2] titans out proj + residual LN -> x_global
    b = B4{};
    b.A[0] = to_; b.W[0] = t_wo; b.C[0] = proj2;
    gemm_tc<<<dim3(DIM / TBN, ROWS / TBM, 1), 256, GEMM_SMEM, s2>>>(b, DIM, DIM, DIM, DIM, 0);
    add_ln_kernel<<<ROWS, 256, 0, s2>>>(x, proj2, 1.f, ln_tit_g, ln_tit_b, xglob);
    cudaEventRecord(ev_join, s2);

    // [0] packed QKV projection
    b = B4{};
    b.A[0] = x; b.W[0] = in_proj_w; b.bias[0] = in_proj_b; b.C[0] = qkv;
    gemm_tc<<<dim3(3 * DIM / TBN, ROWS / TBM, 1), 256, GEMM_SMEM>>>(b, DIM, DIM, 3 * DIM, DIM, 0);

    // [0] sliding-window attention
    attn_kernel<<<dim3(SEQ / 64, BATCH, NH), 64>>>(qkv, att);

    // [0] out_proj + residual LN -> x_local
    b = B4{};
    b.A[0] = att; b.W[0] = out_proj_w; b.bias[0] = out_proj_b; b.C[0] = proj;
    gemm_tc<<<dim3(DIM / TBN, ROWS / TBM, 1), 256, GEMM_SMEM>>>(b, DIM, DIM, DIM, DIM, 0);
    add_ln_kernel<<<ROWS, 256>>>(x, proj, 1.f, ln_local_g, ln_local_b, xlocal);

    // ---- join ----
    cudaStreamWaitEvent(0, ev_join, 0);

    // [0] gate: two K-passes over [xlocal|xglob] with fused sigmoid-combine
    b = B4{};
    b.A[0] = xlocal; b.W[0] = gate_w; b.bias[0] = gate_b; b.C[0] = xc;
    b.A2 = xglob; b.W2 = gate_w + DIM;
    b.xl = xlocal; b.xg = xglob;
    gemm_tc<<<dim3(DIM / TBN, ROWS / TBM, 1), 256, GEMM_SMEM>>>(b, DIM, 2 * DIM, DIM, DIM, 3);

    // [0] CMS: w1 x4 (gelu), z-batched
    b = B4{};
    for (int l = 0; l < 4; ++l) {
        b.A[l]    = xc;
        b.W[l]    = cms_w1 + (size_t)l * 4 * DIM * DIM;
        b.bias[l] = cms_b1 + (size_t)l * 4 * DIM;
        b.C[l]    = hbuf + (size_t)l * ROWS * 4 * DIM;
    }
    gemm_tc<<<dim3(4 * DIM / TBN, ROWS / TBM, 4), 256, GEMM_SMEM>>>(b, DIM, DIM, 4 * DIM, DIM, 1);

    // [0] CMS: w2 x4, z-batched, per-level outputs
    b = B4{};
    for (int l = 0; l < 4; ++l) {
        b.A[l]    = hbuf + (size_t)l * ROWS * 4 * DIM;
        b.W[l]    = cms_w2 + (size_t)l * DIM * 4 * DIM;
        b.bias[l] = cms_b2 + (size_t)l * DIM;
        b.C[l]    = cmsb + (size_t)l * ROWS * DIM;
    }
    gemm_tc<<<dim3(DIM / TBN, ROWS / TBM, 4), 256, GEMM_SMEM>>>(b, 4 * DIM, 4 * DIM, DIM, 4 * DIM, 0);

    // [0] final LN: out = LN(xc + mean over levels)
    ln_final_kernel<<<ROWS, 256>>>(xc, cmsb, cmsb + (size_t)ROWS * DIM,
                                   cmsb + 2 * (size_t)ROWS * DIM, cmsb + 3 * (size_t)ROWS * DIM,
                                   ln_cms_g, ln_cms_b, out);
}

// round 6
// speedup vs baseline: 2.4631x; 1.2958x over previous
#include <cuda_runtime.h>
#include <cuda_fp16.h>
#include <math.h>
#include <stdint.h>

#define SEQ   2048
#define BATCH 2
#define DIM   768
#define NH    12
#define HD    64
#define WIN   512
#define ROWS  (BATCH*SEQ)     // 4096
#define LRATE 0.1f

// ----------------- device scratch (no cudaMalloc allowed) -----------------
__device__ float g_qkv[ROWS*3*DIM];
__device__ float g_att[ROWS*DIM];
__device__ float g_proj[ROWS*DIM];
__device__ float g_proj2[ROWS*DIM];
__device__ float g_xlocal[ROWS*DIM];
__device__ float g_xglobal[ROWS*DIM];
__device__ float g_tq[ROWS*DIM];
__device__ float g_tk[ROWS*DIM];
__device__ float g_tv[ROWS*DIM];
__device__ float g_to[ROWS*DIM];
__device__ float g_xc[ROWS*DIM];
__device__ float g_h[4*(size_t)ROWS*4*DIM];     // 4 CMS levels of hidden
__device__ float g_cms[4*(size_t)ROWS*DIM];     // 4 CMS level outputs

// ===================== mma.sync fp16x3 GEMM ================================
// C[M,N] = A[M,K] @ W[N,K]^T (+bias)(+epi), z-batched via blockIdx.z.
// fp32 emulated as 3 passes of f16 m16n8k16 (hi*hi + lo*hi + hi*lo), fp32 acc.
// epi: 0 = store, 1 = gelu, 2 = accumulate, 3 = sigmoid-gate combine
#define TBM 128
#define TBN 128
#define TBK 32
#define NSTG 3
#define STG_F (2 * TBM * TBK)               // floats per stage (A+B) = 8192
#define GEMM_SMEM (NSTG * STG_F * 4)        // 98304 B -> 2 blocks/SM

#define CP_ASYNC16(dst, src) \
    asm volatile("cp.async.cg.shared.global [%0], [%1], 16;" :: "r"(dst), "l"(src))
#define CP_COMMIT() asm volatile("cp.async.commit_group;")
#define CP_WAIT1()  asm volatile("cp.async.wait_group 1;" ::: "memory")
#define CP_WAIT0()  asm volatile("cp.async.wait_group 0;" ::: "memory")

struct B4 {
    const float* A[4];
    const float* W[4];
    const float* bias[4];
    float*       C[4];
    const float* A2;     // optional second pair (gate)
    const float* W2;
    const float* xl;     // epi==3 operands
    const float* xg;
};

__device__ __forceinline__ uint32_t smem_u32(const void* p) {
    uint32_t a;
    asm("{ .reg .u64 t; cvta.to.shared.u64 t, %1; cvt.u32.u64 %0, t; }" : "=r"(a) : "l"(p));
    return a;
}
__device__ __forceinline__ void mma_f16(float* c, uint32_t a0, uint32_t a1,
                                        uint32_t a2, uint32_t a3,
                                        uint32_t b0, uint32_t b1) {
    asm volatile("mma.sync.aligned.m16n8k16.row.col.f32.f16.f16.f32 "
                 "{%0,%1,%2,%3}, {%4,%5,%6,%7}, {%8,%9}, {%0,%1,%2,%3};"
                 : "+f"(c[0]), "+f"(c[1]), "+f"(c[2]), "+f"(c[3])
                 : "r"(a0), "r"(a1), "r"(a2), "r"(a3), "r"(b0), "r"(b1));
}
__device__ __forceinline__ int swz(int row, int col) {
    return row * 32 + (((col >> 2) ^ (row & 7)) << 2) + (col & 3);
}
// split a float2 into hi (f16x2) and lo (f16x2) with rn rounding
__device__ __forceinline__ void split2(float x, float y, uint32_t& hi, uint32_t& lo) {
    __half2 h = __floats2half2_rn(x, y);
    float2 f = __half22float2(h);
    __half2 l = __floats2half2_rn(x - f.x, y - f.y);
    hi = *reinterpret_cast<uint32_t*>(&h);
    lo = *reinterpret_cast<uint32_t*>(&l);
}

__global__ __launch_bounds__(256, 2) void gemm_tc(
    B4 b, int lda, int ldw, int N, int K, int epi)
{
    extern __shared__ float sm[];
    const int t   = threadIdx.x;
    const int lid = t & 31;
    const int wid = t >> 5;
    const int wm  = wid & 1;
    const int wn  = wid >> 1;
    const int grp = lid >> 2;
    const int tg  = lid & 3;
    const int bm  = blockIdx.y * TBM;
    const int bn  = blockIdx.x * TBN;
    const int z   = blockIdx.z;

    const float* A    = b.A[z];
    const float* W    = b.W[z];
    const float* bias = b.bias[z];
    float*       C    = b.C[z];

    float acc[4][4][4];
#pragma unroll
    for (int mi = 0; mi < 4; ++mi)
#pragma unroll
        for (int ni = 0; ni < 4; ++ni)
#pragma unroll
            for (int r = 0; r < 4; ++r) acc[mi][ni][r] = 0.f;

    const int nstage = K / TBK;
    const int npass  = b.A2 ? 2 : 1;

    for (int pass = 0; pass < npass; ++pass) {
        const float* Ap = pass ? b.A2 : A;
        const float* Wp = pass ? b.W2 : W;
        __syncthreads();   // protect smem reuse across passes

        auto ld_stage = [&](int buf, int k0) {
            float* sa = sm + buf * STG_F;
            float* sb = sa + 4096;
#pragma unroll
            for (int i = 0; i < 4; ++i) {
                int f   = i * 256 + t;       // 0..1023
                int row = f >> 3, c4 = f & 7;
                int sw  = c4 ^ (row & 7);
                CP_ASYNC16(smem_u32(sa + row * 32 + sw * 4),
                           Ap + (size_t)(bm + row) * lda + k0 + c4 * 4);
                CP_ASYNC16(smem_u32(sb + row * 32 + sw * 4),
                           Wp + (size_t)(bn + row) * ldw + k0 + c4 * 4);
            }
        };

        ld_stage(0, 0);   CP_COMMIT();
        ld_stage(1, TBK); CP_COMMIT();

        for (int s = 0; s < nstage; ++s) {
            if (s == nstage - 1) CP_WAIT0(); else CP_WAIT1();
            __syncthreads();
            int sidx = s % 3;
            int nidx = (s + 2) % 3;
            if (s + 2 < nstage) { ld_stage(nidx, (s + 2) * TBK); CP_COMMIT(); }

            const float* sa = sm + sidx * STG_F;
            const float* sb = sa + 4096;
#pragma unroll
            for (int kk = 0; kk < 2; ++kk) {     // two k=16 chunks per stage
                const int c = kk * 16 + tg * 2;
                uint32_t bh[4][2], bl[4][2];
#pragma unroll
                for (int ni = 0; ni < 4; ++ni) {
                    const int nr = wn * 32 + ni * 8 + grp;
                    float2 w0 = *(const float2*)&sb[swz(nr, c)];
                    float2 w1 = *(const float2*)&sb[swz(nr, c + 8)];
                    split2(w0.x, w0.y, bh[ni][0], bl[ni][0]);
                    split2(w1.x, w1.y, bh[ni][1], bl[ni][1]);
                }
#pragma unroll
                for (int mi = 0; mi < 4; ++mi) {
                    const int r0 = wm * 64 + mi * 16 + grp;
                    float2 x0 = *(const float2*)&sa[swz(r0,     c)];
                    float2 x1 = *(const float2*)&sa[swz(r0 + 8, c)];
                    float2 x2 = *(const float2*)&sa[swz(r0,     c + 8)];
                    float2 x3 = *(const float2*)&sa[swz(r0 + 8, c + 8)];
                    uint32_t ah0, al0, ah1, al1, ah2, al2, ah3, al3;
                    split2(x0.x, x0.y, ah0, al0);
                    split2(x1.x, x1.y, ah1, al1);
                    split2(x2.x, x2.y, ah2, al2);
                    split2(x3.x, x3.y, ah3, al3);
#pragma unroll
                    for (int ni = 0; ni < 4; ++ni)
                        mma_f16(acc[mi][ni], ah0, ah1, ah2, ah3, bh[ni][0], bh[ni][1]);
#pragma unroll
                    for (int ni = 0; ni < 4; ++ni)
                        mma_f16(acc[mi][ni], al0, al1, al2, al3, bh[ni][0], bh[ni][1]);
#pragma unroll
                    for (int ni = 0; ni < 4; ++ni)
                        mma_f16(acc[mi][ni], ah0, ah1, ah2, ah3, bl[ni][0], bl[ni][1]);
                }
            }
        }
    }

    // ---------------- epilogue ----------------
#pragma unroll
    for (int mi = 0; mi < 4; ++mi) {
#pragma unroll
        for (int ni = 0; ni < 4; ++ni) {
            const int col = bn + wn * 32 + ni * 8 + 2 * tg;
            float bx = 0.f, by = 0.f;
            if (bias) { bx = bias[col]; by = bias[col + 1]; }
#pragma unroll
            for (int half = 0; half < 2; ++half) {
                const int row = bm + wm * 64 + mi * 16 + grp + half * 8;
                float v0 = acc[mi][ni][half * 2 + 0] + bx;
                float v1 = acc[mi][ni][half * 2 + 1] + by;
                float* Cp = C + (size_t)row * N + col;
                if (epi == 1) {
                    float u3;
                    u3 = v0 * v0 * v0;
                    v0 = 0.5f * v0 * (1.f + tanhf(0.7978845608028654f * (v0 + 0.044715f * u3)));
                    u3 = v1 * v1 * v1;
                    v1 = 0.5f * v1 * (1.f + tanhf(0.7978845608028654f * (v1 + 0.044715f * u3)));
                } else if (epi == 2) {
                    float2 old = *(const float2*)Cp;
                    v0 += old.x; v1 += old.y;
                } else if (epi == 3) {
                    const size_t idx = (size_t)row * N + col;
                    float s0 = 1.f / (1.f + __expf(-v0));
                    float s1 = 1.f / (1.f + __expf(-v1));
                    float2 xl2 = *(const float2*)(b.xl + idx);
                    float2 xg2 = *(const float2*)(b.xg + idx);
                    v0 = s0 * xl2.x + (1.f - s0) * xg2.x;
                    v1 = s1 * xl2.y + (1.f - s1) * xg2.y;
                }
                *(float2*)Cp = make_float2(v0, v1);
            }
        }
    }
}

// ----------------- sliding-window causal attention ------------------------
__global__ __launch_bounds__(64) void attn_kernel(const float* __restrict__ qkv,
                                                  float* __restrict__ out)
{
    const int qt = blockIdx.x;
    const int b  = blockIdx.y;
    const int h  = blockIdx.z;
    const int t  = threadIdx.x;
    const int qi = qt * 64 + t;

    __shared__ __align__(16) float ks[64][64];
    __shared__ __align__(16) float vs[64][64];

    float q[64], o[64];
    {
        const float4* qb = (const float4*)(qkv + ((size_t)(b * SEQ + qi)) * (3 * DIM) + h * HD);
#pragma unroll
        for (int d4 = 0; d4 < 16; ++d4) {
            float4 v = qb[d4];
            q[4*d4+0] = v.x * 0.125f; q[4*d4+1] = v.y * 0.125f;
            q[4*d4+2] = v.z * 0.125f; q[4*d4+3] = v.w * 0.125f;
        }
    }
#pragma unroll
    for (int d = 0; d < 64; ++d) o[d] = 0.f;
    float m = -1e30f, l = 0.f;

    const int kt0 = (qt >= 8) ? (qt - 8) : 0;
    for (int kt = kt0; kt <= qt; ++kt) {
        const float* kbase = qkv + ((size_t)(b * SEQ + kt * 64)) * (3 * DIM) + DIM + h * HD + t;
        const float* vbase = kbase + DIM;
        for (int r = 0; r < 64; ++r) {
            ks[r][t] = kbase[(size_t)r * (3 * DIM)];
            vs[r][t] = vbase[(size_t)r * (3 * DIM)];
        }
        __syncthreads();

        int jlo = qi - WIN + 1 - kt * 64; if (jlo < 0)  jlo = 0;
        int jhi = qi - kt * 64;           if (jhi > 63) jhi = 63;
        for (int j = jlo; j <= jhi; ++j) {
            float s = 0.f;
            const float4* kr = (const float4*)ks[j];
#pragma unroll
            for (int d4 = 0; d4 < 16; ++d4) {
                float4 kv = kr[d4];
                s += q[4*d4+0]*kv.x + q[4*d4+1]*kv.y + q[4*d4+2]*kv.z + q[4*d4+3]*kv.w;
            }
            const float4* vr = (const float4*)vs[j];
            if (s <= m) {
                float p = __expf(s - m);
                l += p;
#pragma unroll
                for (int d4 = 0; d4 < 16; ++d4) {
                    float4 vv = vr[d4];
                    o[4*d4+0] += p*vv.x; o[4*d4+1] += p*vv.y;
                    o[4*d4+2] += p*vv.z; o[4*d4+3] += p*vv.w;
                }
            } else {
                float al = __expf(m - s);
                m = s; l = l * al + 1.f;
#pragma unroll
                for (int d4 = 0; d4 < 16; ++d4) {
                    float4 vv = vr[d4];
                    o[4*d4+0] = o[4*d4+0]*al + vv.x; o[4*d4+1] = o[4*d4+1]*al + vv.y;
                    o[4*d4+2] = o[4*d4+2]*al + vv.z; o[4*d4+3] = o[4*d4+3]*al + vv.w;
                }
            }
        }
        __syncthreads();
    }

    const float inv = 1.f / l;
    float4* ob = (float4*)(out + ((size_t)(b * SEQ + qi)) * DIM + h * HD);
#pragma unroll
    for (int d4 = 0; d4 < 16; ++d4)
        ob[d4] = make_float4(o[4*d4+0]*inv, o[4*d4+1]*inv, o[4*d4+2]*inv, o[4*d4+3]*inv);
}

// ----------------- fused residual-add + LayerNorm -------------------------
__global__ __launch_bounds__(256) void add_ln_kernel(const float* __restrict__ x,
    const float* __restrict__ r, float rscale, const float* __restrict__ gg,
    const float* __restrict__ bb, float* __restrict__ y)
{
    const int row = blockIdx.x;
    const int t = threadIdx.x;
    __shared__ float red[8];
    __shared__ float bc0, bc1;

    const float* xr = x + (size_t)row * DIM;
    const float* rr = r + (size_t)row * DIM;
    float v[3]; float s = 0.f;
#pragma unroll
    for (int i = 0; i < 3; ++i) { int c = t + i * 256; v[i] = xr[c] + rscale * rr[c]; s += v[i]; }
#pragma unroll
    for (int off = 16; off; off >>= 1) s += __shfl_xor_sync(0xffffffffu, s, off);
    if ((t & 31) == 0) red[t >> 5] = s;
    __syncthreads();
    if (t == 0) { float tot = 0.f;
#pragma unroll
        for (int w = 0; w < 8; ++w) tot += red[w];
        bc0 = tot * (1.f / DIM);
    }
    __syncthreads();
    const float mean = bc0;
    float sq = 0.f;
#pragma unroll
    for (int i = 0; i < 3; ++i) { float d = v[i] - mean; sq += d * d; }
#pragma unroll
    for (int off = 16; off; off >>= 1) sq += __shfl_xor_sync(0xffffffffu, sq, off);
    if ((t & 31) == 0) red[t >> 5] = sq;
    __syncthreads();
    if (t == 0) { float tot = 0.f;
#pragma unroll
        for (int w = 0; w < 8; ++w) tot += red[w];
        bc1 = rsqrtf(tot * (1.f / DIM) + 1e-5f);
    }
    __syncthreads();
    const float rstd = bc1;
#pragma unroll
    for (int i = 0; i < 3; ++i) {
        int c = t + i * 256;
        y[(size_t)row * DIM + c] = (v[i] - mean) * rstd * gg[c] + bb[c];
    }
}

// ----------------- final LN with 4-way CMS mean ----------------------------
__global__ __launch_bounds__(256) void ln_final_kernel(const float* __restrict__ xc,
    const float* __restrict__ c0, const float* __restrict__ c1,
    const float* __restrict__ c2, const float* __restrict__ c3,
    const float* __restrict__ gg, const float* __restrict__ bb,
    float* __restrict__ y)
{
    const int row = blockIdx.x;
    const int t = threadIdx.x;
    __shared__ float red[8];
    __shared__ float bc0, bc1;

    const size_t rb = (size_t)row * DIM;
    float v[3]; float s = 0.f;
#pragma unroll
    for (int i = 0; i < 3; ++i) {
        int c = t + i * 256;
        v[i] = xc[rb + c] + 0.25f * (c0[rb + c] + c1[rb + c] + c2[rb + c] + c3[rb + c]);
        s += v[i];
    }
#pragma unroll
    for (int off = 16; off; off >>= 1) s += __shfl_xor_sync(0xffffffffu, s, off);
    if ((t & 31) == 0) red[t >> 5] = s;
    __syncthreads();
    if (t == 0) { float tot = 0.f;
#pragma unroll
        for (int w = 0; w < 8; ++w) tot += red[w];
        bc0 = tot * (1.f / DIM);
    }
    __syncthreads();
    const float mean = bc0;
    float sq = 0.f;
#pragma unroll
    for (int i = 0; i < 3; ++i) { float d = v[i] - mean; sq += d * d; }
#pragma unroll
    for (int off = 16; off; off >>= 1) sq += __shfl_xor_sync(0xffffffffu, sq, off);
    if ((t & 31) == 0) red[t >> 5] = sq;
    __syncthreads();
    if (t == 0) { float tot = 0.f;
#pragma unroll
        for (int w = 0; w < 8; ++w) tot += red[w];
        bc1 = rsqrtf(tot * (1.f / DIM) + 1e-5f);
    }
    __syncthreads();
    const float rstd = bc1;
#pragma unroll
    for (int i = 0; i < 3; ++i) {
        int c = t + i * 256;
        y[rb + c] = (v[i] - mean) * rstd * gg[c] + bb[c];
    }
}

// ----------------- delta-rule scan (SelfModifyingTitans) ------------------
__global__ __launch_bounds__(256) void delta_scan_kernel(const float* __restrict__ tq,
    const float* __restrict__ tk, const float* __restrict__ tv,
    float* __restrict__ t_o, float* __restrict__ Mout)
{
    const int bh = blockIdx.x;
    const int b = bh / NH, h = bh % NH;
    const int t = threadIdx.x;
    const int e = t & 63;
    const int g = t >> 6;

    __shared__ float ks[64], vs[64], qs[64];
    __shared__ float part[4][64];
    __shared__ float opart[4][64];

    float Mreg[16];
#pragma unroll
    for (int i = 0; i < 16; ++i) Mreg[i] = 0.f;

    const size_t base = ((size_t)b * SEQ) * DIM + h * HD + e;
    float nxt = 0.f;
    if (g == 0) nxt = tk[base];
    else if (g == 1) nxt = tv[base];
    else if (g == 2) nxt = tq[base];

    for (int s = 0; s < SEQ; ++s) {
        if (g == 0) ks[e] = nxt;
        else if (g == 1) vs[e] = nxt;
        else if (g == 2) qs[e] = nxt;
        __syncthreads();
        if (s + 1 < SEQ) {
            size_t nb = base + (size_t)(s + 1) * DIM;
            if (g == 0) nxt = tk[nb];
            else if (g == 1) nxt = tv[nb];
            else if (g == 2) nxt = tq[nb];
        }
        float kreg[16];
        float p0 = 0.f, p1 = 0.f, p2 = 0.f, p3 = 0.f;
#pragma unroll
        for (int i = 0; i < 16; i += 4) {
            kreg[i+0] = ks[g*16 + i+0]; kreg[i+1] = ks[g*16 + i+1];
            kreg[i+2] = ks[g*16 + i+2]; kreg[i+3] = ks[g*16 + i+3];
            p0 += Mreg[i+0]*kreg[i+0]; p1 += Mreg[i+1]*kreg[i+1];
            p2 += Mreg[i+2]*kreg[i+2]; p3 += Mreg[i+3]*kreg[i+3];
        }
        part[g][e] = (p0 + p1) + (p2 + p3);
        __syncthreads();
        const float pred  = (part[0][e] + part[1][e]) + (part[2][e] + part[3][e]);
        const float delta = LRATE * (vs[e] - pred);
        float q0 = 0.f, q1 = 0.f, q2 = 0.f, q3 = 0.f;
#pragma unroll
        for (int i = 0; i < 16; i += 4) {
            Mreg[i+0] += kreg[i+0]*delta; q0 += Mreg[i+0]*qs[g*16 + i+0];
            Mreg[i+1] += kreg[i+1]*delta; q1 += Mreg[i+1]*qs[g*16 + i+1];
            Mreg[i+2] += kreg[i+2]*delta; q2 += Mreg[i+2]*qs[g*16 + i+2];
            Mreg[i+3] += kreg[i+3]*delta; q3 += Mreg[i+3]*qs[g*16 + i+3];
        }
        opart[g][e] = (q0 + q1) + (q2 + q3);
        __syncthreads();
        if (g == 0)
            t_o[base + (size_t)s * DIM] =
                (opart[0][e] + opart[1][e]) + (opart[2][e] + opart[3][e]);
    }
    if (Mout) {
#pragma unroll
        for (int i = 0; i < 16; ++i)
            Mout[(((size_t)b * NH + h) * HD + (g * 16 + i)) * HD + e] = Mreg[i];
    }
}

// ----------------- launch ---------------------------------------------------
static float* sym(const void* s) {
    void* p = nullptr;
    cudaGetSymbolAddress(&p, s);
    return (float*)p;
}

extern "C" void kernel_launch(void* const* d_in, const int* in_sizes, int n_in,
                              void* d_out, int out_size)
{
    const float* x          = (const float*)d_in[0];
    const float* in_proj_w  = (const float*)d_in[1];
    const float* in_proj_b  = (const float*)d_in[2];
    const float* out_proj_w = (const float*)d_in[3];
    const float* out_proj_b = (const float*)d_in[4];
    const float* ln_local_g = (const float*)d_in[5];
    const float* ln_local_b = (const float*)d_in[6];
    const float* t_wq       = (const float*)d_in[7];
    const float* t_wk       = (const float*)d_in[8];
    const float* t_wv       = (const float*)d_in[9];
    const float* t_wo       = (const float*)d_in[10];
    const float* ln_tit_g   = (const float*)d_in[11];
    const float* ln_tit_b   = (const float*)d_in[12];
    const float* gate_w     = (const float*)d_in[13];
    const float* gate_b     = (const float*)d_in[14];
    const float* cms_w1     = (const float*)d_in[15];
    const float* cms_b1     = (const float*)d_in[16];
    const float* cms_w2     = (const float*)d_in[17];
    const float* cms_b2     = (const float*)d_in[18];
    const float* ln_cms_g   = (const float*)d_in[19];
    const float* ln_cms_b   = (const float*)d_in[20];

    float* qkv    = sym(g_qkv);
    float* att    = sym(g_att);
    float* proj   = sym(g_proj);
    float* proj2  = sym(g_proj2);
    float* xlocal = sym(g_xlocal);
    float* xglob  = sym(g_xglobal);
    float* tq     = sym(g_tq);
    float* tk     = sym(g_tk);
    float* tv     = sym(g_tv);
    float* to_    = sym(g_to);
    float* xc     = sym(g_xc);
    float* hbuf   = sym(g_h);
    float* cmsb   = sym(g_cms);

    float* out = (float*)d_out;
    float* mout = (out_size >= ROWS * DIM + BATCH * NH * HD * HD)
                      ? out + (size_t)ROWS * DIM : nullptr;

    static cudaStream_t s2 = nullptr;
    static cudaEvent_t ev_fork = nullptr, ev_join = nullptr;
    if (!s2) {
        cudaFuncSetAttribute(gemm_tc, cudaFuncAttributeMaxDynamicSharedMemorySize, GEMM_SMEM);
        cudaStreamCreateWithFlags(&s2, cudaStreamNonBlocking);
        cudaEventCreateWithFlags(&ev_fork, cudaEventDisableTiming);
        cudaEventCreateWithFlags(&ev_join, cudaEventDisableTiming);
    }

    B4 b{};

    // ---- fork: titans branch runs on s2 concurrently with local branch ----
    cudaEventRecord(ev_fork, 0);
    cudaStreamWaitEvent(s2, ev_fork, 0);

    // [s2] Titans projections (z-batched x3)
    b = B4{};
    b.A[0] = x;  b.W[0] = t_wq; b.C[0] = tq;
    b.A[1] = x;  b.W[1] = t_wk; b.C[1] = tk;
    b.A[2] = x;  b.W[2] = t_wv; b.C[2] = tv;
    gemm_tc<<<dim3(DIM / TBN, ROWS / TBM, 3), 256, GEMM_SMEM, s2>>>(b, DIM, DIM, DIM, DIM, 0);

    // [s2] delta-rule scan (also writes memory_state to d_out tail)
    delta_scan_kernel<<<BATCH * NH, 256, 0, s2>>>(tq, tk, tv, to_, mout);

    // [s2] titans out proj + residual LN -> x_global
    b = B4{};
    b.A[0] = to_; b.W[0] = t_wo; b.C[0] = proj2;
    gemm_tc<<<dim3(DIM / TBN, ROWS / TBM, 1), 256, GEMM_SMEM, s2>>>(b, DIM, DIM, DIM, DIM, 0);
    add_ln_kernel<<<ROWS, 256, 0, s2>>>(x, proj2, 1.f, ln_tit_g, ln_tit_b, xglob);
    cudaEventRecord(ev_join, s2);

    // [0] packed QKV projection
    b = B4{};
    b.A[0] = x; b.W[0] = in_proj_w; b.bias[0] = in_proj_b; b.C[0] = qkv;
    gemm_tc<<<dim3(3 * DIM / TBN, ROWS / TBM, 1), 256, GEMM_SMEM>>>(b, DIM, DIM, 3 * DIM, DIM, 0);

    // [0] sliding-window attention
    attn_kernel<<<dim3(SEQ / 64, BATCH, NH), 64>>>(qkv, att);

    // [0] out_proj + residual LN -> x_local
    b = B4{};
    b.A[0] = att; b.W[0] = out_proj_w; b.bias[0] = out_proj_b; b.C[0] = proj;
    gemm_tc<<<dim3(DIM / TBN, ROWS / TBM, 1), 256, GEMM_SMEM>>>(b, DIM, DIM, DIM, DIM, 0);
    add_ln_kernel<<<ROWS, 256>>>(x, proj, 1.f, ln_local_g, ln_local_b, xlocal);

    // ---- join ----
    cudaStreamWaitEvent(0, ev_join, 0);

    // [0] gate: two K-passes over [xlocal|xglob] with fused sigmoid-combine
    b = B4{};
    b.A[0] = xlocal; b.W[0] = gate_w; b.bias[0] = gate_b; b.C[0] = xc;
    b.A2 = xglob; b.W2 = gate_w + DIM;
    b.xl = xlocal; b.xg = xglob;
    gemm_tc<<<dim3(DIM / TBN, ROWS / TBM, 1), 256, GEMM_SMEM>>>(b, DIM, 2 * DIM, DIM, DIM, 3);

    // [0] CMS: w1 x4 (gelu), z-batched
    b = B4{};
    for (int l = 0; l < 4; ++l) {
        b.A[l]    = xc;
        b.W[l]    = cms_w1 + (size_t)l * 4 * DIM * DIM;
        b.bias[l] = cms_b1 + (size_t)l * 4 * DIM;
        b.C[l]    = hbuf + (size_t)l * ROWS * 4 * DIM;
    }
    gemm_tc<<<dim3(4 * DIM / TBN, ROWS / TBM, 4), 256, GEMM_SMEM>>>(b, DIM, DIM, 4 * DIM, DIM, 1);

    // [0] CMS: w2 x4, z-batched, per-level outputs
    b = B4{};
    for (int l = 0; l < 4; ++l) {
        b.A[l]    = hbuf + (size_t)l * ROWS * 4 * DIM;
        b.W[l]    = cms_w2 + (size_t)l * DIM * 4 * DIM;
        b.bias[l] = cms_b2 + (size_t)l * DIM;
        b.C[l]    = cmsb + (size_t)l * ROWS * DIM;
    }
    gemm_tc<<<dim3(DIM / TBN, ROWS / TBM, 4), 256, GEMM_SMEM>>>(b, 4 * DIM, 4 * DIM, DIM, 4 * DIM, 0);

    // [0] final LN: out = LN(xc + mean over levels)
    ln_final_kernel<<<ROWS, 256>>>(xc, cmsb, cmsb + (size_t)ROWS * DIM,
                                   cmsb + 2 * (size_t)ROWS * DIM, cmsb + 3 * (size_t)ROWS * DIM,
                                   ln_cms_g, ln_cms_b, out);
}

// round 7
// speedup vs baseline: 2.8146x; 1.1427x over previous
#include <cuda_runtime.h>
#include <cuda_fp16.h>
#include <math.h>
#include <stdint.h>

#define SEQ   2048
#define BATCH 2
#define DIM   768
#define NH    12
#define HD    64
#define WIN   512
#define ROWS  (BATCH*SEQ)     // 4096
#define LRATE 0.1f

// ----------------- device scratch (no cudaMalloc allowed) -----------------
__device__ float g_qkv[ROWS*3*DIM];
__device__ float g_proj[ROWS*DIM];
__device__ float g_proj2[ROWS*DIM];
__device__ float g_xlocal[ROWS*DIM];
__device__ float g_xglobal[ROWS*DIM];
__device__ float g_tq[ROWS*DIM];
__device__ float g_tk[ROWS*DIM];
__device__ float g_tv[ROWS*DIM];
__device__ float g_xc[ROWS*DIM];
__device__ float g_cms[4*(size_t)ROWS*DIM];     // 4 CMS level outputs (f32)

// hi/lo f16 planes for GEMM operands
__device__ __half g_x_h[ROWS*DIM],     g_x_l[ROWS*DIM];
__device__ __half g_wi_h[3*DIM*DIM],   g_wi_l[3*DIM*DIM];
__device__ __half g_wo_h[DIM*DIM],     g_wo_l[DIM*DIM];
__device__ __half g_wtq_h[DIM*DIM],    g_wtq_l[DIM*DIM];
__device__ __half g_wtk_h[DIM*DIM],    g_wtk_l[DIM*DIM];
__device__ __half g_wtv_h[DIM*DIM],    g_wtv_l[DIM*DIM];
__device__ __half g_wto_h[DIM*DIM],    g_wto_l[DIM*DIM];
__device__ __half g_wg_h[2*DIM*DIM],   g_wg_l[2*DIM*DIM];
__device__ __half g_wc1_h[4*4*DIM*DIM], g_wc1_l[4*4*DIM*DIM];
__device__ __half g_wc2_h[4*4*DIM*DIM], g_wc2_l[4*4*DIM*DIM];
__device__ __half g_att_h[ROWS*DIM],   g_att_l[ROWS*DIM];
__device__ __half g_to_h[ROWS*DIM],    g_to_l[ROWS*DIM];
__device__ __half g_xl_h[ROWS*DIM],    g_xl_l[ROWS*DIM];
__device__ __half g_xg_h[ROWS*DIM],    g_xg_l[ROWS*DIM];
__device__ __half g_xc_h[ROWS*DIM],    g_xc_l[ROWS*DIM];
__device__ __half g_hb_h[4*(size_t)ROWS*4*DIM], g_hb_l[4*(size_t)ROWS*4*DIM];

// ===================== fp16x3 GEMM with pre-split operands =================
// C[M,N] = A[M,K] @ W[N,K]^T, A/W given as separate f16 hi/lo planes.
// 3 HMMA passes per fragment: hh + lh + hl. fp32 accumulators.
// epi: 0 = f32 store (+bias), 1 = gelu -> hi/lo store only, 3 = gate combine
#define TBM 128
#define TBN 128
#define TBK 32
#define STG_BYTES 32768                  // Ahi|Alo|Whi|Wlo tiles, 8KB each
#define GEMM_SMEM (3*STG_BYTES)          // 98304 -> 2 blocks/SM

#define CP_ASYNC16(dst, src) \
    asm volatile("cp.async.cg.shared.global [%0], [%1], 16;" :: "r"(dst), "l"(src))
#define CP_COMMIT() asm volatile("cp.async.commit_group;")
#define CP_WAIT1()  asm volatile("cp.async.wait_group 1;" ::: "memory")
#define CP_WAIT0()  asm volatile("cp.async.wait_group 0;" ::: "memory")
#define LDSM_X4(r0,r1,r2,r3,addr) \
    asm volatile("ldmatrix.sync.aligned.m8n8.x4.shared.b16 {%0,%1,%2,%3}, [%4];" \
        : "=r"(r0),"=r"(r1),"=r"(r2),"=r"(r3) : "r"(addr))
#define LDSM_X2(r0,r1,addr) \
    asm volatile("ldmatrix.sync.aligned.m8n8.x2.shared.b16 {%0,%1}, [%2];" \
        : "=r"(r0),"=r"(r1) : "r"(addr))

struct B4 {
    const __half *Ah[4], *Al[4], *Wh[4], *Wl[4];
    const float* bias[4];
    float* C[4];
    __half *Ch[4], *Cl[4];
    const __half *A2h, *A2l, *W2h, *W2l;   // gate second K-pass
    const float *xl, *xg;                  // epi==3 operands
    __half *xch, *xcl;                     // epi==3 split outputs
};

__device__ __forceinline__ uint32_t smem_u32(const void* p) {
    uint32_t a;
    asm("{ .reg .u64 t; cvta.to.shared.u64 t, %1; cvt.u32.u64 %0, t; }" : "=r"(a) : "l"(p));
    return a;
}
__device__ __forceinline__ void mma_f16(float* c, uint32_t a0, uint32_t a1,
                                        uint32_t a2, uint32_t a3,
                                        uint32_t b0, uint32_t b1) {
    asm volatile("mma.sync.aligned.m16n8k16.row.col.f32.f16.f16.f32 "
                 "{%0,%1,%2,%3}, {%4,%5,%6,%7}, {%8,%9}, {%0,%1,%2,%3};"
                 : "+f"(c[0]), "+f"(c[1]), "+f"(c[2]), "+f"(c[3])
                 : "r"(a0), "r"(a1), "r"(a2), "r"(a3), "r"(b0), "r"(b1));
}

__global__ __launch_bounds__(256, 2) void gemm_tc(
    B4 b, int lda, int ldw, int N, int K, int epi)
{
    extern __shared__ char smc[];
    const int t   = threadIdx.x;
    const int lid = t & 31;
    const int wid = t >> 5;
    const int wm  = wid & 1;
    const int wn  = wid >> 1;
    const int grp = lid >> 2;
    const int tg  = lid & 3;
    const int bm  = blockIdx.y * TBM;
    const int bn  = blockIdx.x * TBN;
    const int z   = blockIdx.z;

    float acc[4][4][4];
#pragma unroll
    for (int mi = 0; mi < 4; ++mi)
#pragma unroll
        for (int ni = 0; ni < 4; ++ni)
#pragma unroll
            for (int r = 0; r < 4; ++r) acc[mi][ni][r] = 0.f;

    const int nstage = K / TBK;
    const int npass  = b.A2h ? 2 : 1;
    const uint32_t sbase = smem_u32(smc);

    for (int pass = 0; pass < npass; ++pass) {
        const __half* pAh = pass ? b.A2h : b.Ah[z];
        const __half* pAl = pass ? b.A2l : b.Al[z];
        const __half* pWh = pass ? b.W2h : b.Wh[z];
        const __half* pWl = pass ? b.W2l : b.Wl[z];
        __syncthreads();

        auto ld_stage = [&](int buf, int k0) {
#pragma unroll
            for (int i = 0; i < 8; ++i) {
                const int tile = i >> 1;               // 0:Ahi 1:Alo 2:Whi 3:Wlo
                const int rem  = ((i & 1) << 8) + t;   // 0..511
                const int row  = rem >> 2;
                const int chn  = t & 3;
                const __half* src;
                if (tile == 0)      src = pAh + (size_t)(bm + row) * lda + k0 + chn * 8;
                else if (tile == 1) src = pAl + (size_t)(bm + row) * lda + k0 + chn * 8;
                else if (tile == 2) src = pWh + (size_t)(bn + row) * ldw + k0 + chn * 8;
                else                src = pWl + (size_t)(bn + row) * ldw + k0 + chn * 8;
                const uint32_t dst = sbase + buf * STG_BYTES + tile * 8192
                                   + row * 64 + ((chn ^ ((row >> 1) & 3)) << 4);
                CP_ASYNC16(dst, src);
            }
        };

        ld_stage(0, 0);   CP_COMMIT();
        ld_stage(1, TBK); CP_COMMIT();

        const int lr   = lid & 7;
        const int hsel = (lid >> 3) & 1;
        const int seg2 = (lid >> 4) & 1;

        for (int s = 0; s < nstage; ++s) {
            if (s == nstage - 1) CP_WAIT0(); else CP_WAIT1();
            __syncthreads();
            if (s + 2 < nstage) { ld_stage((s + 2) % 3, (s + 2) * TBK); CP_COMMIT(); }

            const uint32_t stg = sbase + (s % 3) * STG_BYTES;
            const uint32_t a_h = stg, a_l = stg + 8192;
            const uint32_t w_h = stg + 16384, w_l = stg + 24576;

#pragma unroll
            for (int kk = 0; kk < 2; ++kk) {
                uint32_t bh[4][2], bl[4][2];
#pragma unroll
                for (int ni = 0; ni < 4; ++ni) {
                    const int nr = wn * 32 + ni * 8 + lr;
                    const int ch = kk * 2 + hsel;
                    const uint32_t off = nr * 64 + ((ch ^ ((nr >> 1) & 3)) << 4);
                    LDSM_X2(bh[ni][0], bh[ni][1], w_h + off);
                    LDSM_X2(bl[ni][0], bl[ni][1], w_l + off);
                }
#pragma unroll
                for (int mi = 0; mi < 4; ++mi) {
                    const int ar = wm * 64 + mi * 16 + hsel * 8 + lr;
                    const int ch = kk * 2 + seg2;
                    const uint32_t off = ar * 64 + ((ch ^ ((ar >> 1) & 3)) << 4);
                    uint32_t ah[4], al[4];
                    LDSM_X4(ah[0], ah[1], ah[2], ah[3], a_h + off);
                    LDSM_X4(al[0], al[1], al[2], al[3], a_l + off);
#pragma unroll
                    for (int ni = 0; ni < 4; ++ni)
                        mma_f16(acc[mi][ni], ah[0], ah[1], ah[2], ah[3], bh[ni][0], bh[ni][1]);
#pragma unroll
                    for (int ni = 0; ni < 4; ++ni)
                        mma_f16(acc[mi][ni], al[0], al[1], al[2], al[3], bh[ni][0], bh[ni][1]);
#pragma unroll
                    for (int ni = 0; ni < 4; ++ni)
                        mma_f16(acc[mi][ni], ah[0], ah[1], ah[2], ah[3], bl[ni][0], bl[ni][1]);
                }
            }
        }
    }

    // ---------------- epilogue ----------------
#pragma unroll
    for (int mi = 0; mi < 4; ++mi) {
#pragma unroll
        for (int ni = 0; ni < 4; ++ni) {
            const int col = bn + wn * 32 + ni * 8 + 2 * tg;
            float bx = 0.f, by = 0.f;
            if (b.bias[z]) { bx = b.bias[z][col]; by = b.bias[z][col + 1]; }
#pragma unroll
            for (int hf = 0; hf < 2; ++hf) {
                const int row = bm + wm * 64 + mi * 16 + grp + hf * 8;
                float v0 = acc[mi][ni][hf * 2 + 0] + bx;
                float v1 = acc[mi][ni][hf * 2 + 1] + by;
                const size_t idx = (size_t)row * N + col;
                if (epi == 0) {
                    *(float2*)(b.C[z] + idx) = make_float2(v0, v1);
                } else if (epi == 1) {
                    float u3;
                    u3 = v0 * v0 * v0;
                    v0 = 0.5f * v0 * (1.f + tanhf(0.7978845608028654f * (v0 + 0.044715f * u3)));
                    u3 = v1 * v1 * v1;
                    v1 = 0.5f * v1 * (1.f + tanhf(0.7978845608028654f * (v1 + 0.044715f * u3)));
                    __half2 hh = __floats2half2_rn(v0, v1);
                    float2 hv = __half22float2(hh);
                    __half2 ll = __floats2half2_rn(v0 - hv.x, v1 - hv.y);
                    *(__half2*)(b.Ch[z] + idx) = hh;
                    *(__half2*)(b.Cl[z] + idx) = ll;
                } else { // epi == 3: sigmoid-gate combine + split store
                    float s0 = 1.f / (1.f + __expf(-v0));
                    float s1 = 1.f / (1.f + __expf(-v1));
                    float2 xl2 = *(const float2*)(b.xl + idx);
                    float2 xg2 = *(const float2*)(b.xg + idx);
                    v0 = s0 * xl2.x + (1.f - s0) * xg2.x;
                    v1 = s1 * xl2.y + (1.f - s1) * xg2.y;
                    *(float2*)(b.C[z] + idx) = make_float2(v0, v1);
                    __half2 hh = __floats2half2_rn(v0, v1);
                    float2 hv = __half22float2(hh);
                    __half2 ll = __floats2half2_rn(v0 - hv.x, v1 - hv.y);
                    *(__half2*)(b.xch + idx) = hh;
                    *(__half2*)(b.xcl + idx) = ll;
                }
            }
        }
    }
}

// ----------------- splitter: f32 -> f16 hi/lo planes -----------------------
__global__ void split_kernel(const float4* __restrict__ src, uint2* __restrict__ hi,
                             uint2* __restrict__ lo, int n4)
{
    int i = blockIdx.x * blockDim.x + threadIdx.x;
    if (i >= n4) return;
    float4 v = src[i];
    __half2 h0 = __floats2half2_rn(v.x, v.y);
    __half2 h1 = __floats2half2_rn(v.z, v.w);
    float2 f0 = __half22float2(h0), f1 = __half22float2(h1);
    __half2 l0 = __floats2half2_rn(v.x - f0.x, v.y - f0.y);
    __half2 l1 = __floats2half2_rn(v.z - f1.x, v.w - f1.y);
    hi[i] = make_uint2(*(uint32_t*)&h0, *(uint32_t*)&h1);
    lo[i] = make_uint2(*(uint32_t*)&l0, *(uint32_t*)&l1);
}

// ----------------- sliding-window causal attention (split f16 out) --------
__global__ __launch_bounds__(64) void attn_kernel(const float* __restrict__ qkv,
                                                  __half* __restrict__ oh,
                                                  __half* __restrict__ ol)
{
    const int qt = blockIdx.x;
    const int b  = blockIdx.y;
    const int h  = blockIdx.z;
    const int t  = threadIdx.x;
    const int qi = qt * 64 + t;

    __shared__ __align__(16) float ks[64][64];
    __shared__ __align__(16) float vs[64][64];

    float q[64], o[64];
    {
        const float4* qb = (const float4*)(qkv + ((size_t)(b * SEQ + qi)) * (3 * DIM) + h * HD);
#pragma unroll
        for (int d4 = 0; d4 < 16; ++d4) {
            float4 v = qb[d4];
            q[4*d4+0] = v.x * 0.125f; q[4*d4+1] = v.y * 0.125f;
            q[4*d4+2] = v.z * 0.125f; q[4*d4+3] = v.w * 0.125f;
        }
    }
#pragma unroll
    for (int d = 0; d < 64; ++d) o[d] = 0.f;
    float m = -1e30f, l = 0.f;

    const int kt0 = (qt >= 8) ? (qt - 8) : 0;
    for (int kt = kt0; kt <= qt; ++kt) {
        const float* kbase = qkv + ((size_t)(b * SEQ + kt * 64)) * (3 * DIM) + DIM + h * HD + t;
        const float* vbase = kbase + DIM;
        for (int r = 0; r < 64; ++r) {
            ks[r][t] = kbase[(size_t)r * (3 * DIM)];
            vs[r][t] = vbase[(size_t)r * (3 * DIM)];
        }
        __syncthreads();

        int jlo = qi - WIN + 1 - kt * 64; if (jlo < 0)  jlo = 0;
        int jhi = qi - kt * 64;           if (jhi > 63) jhi = 63;
        for (int j = jlo; j <= jhi; ++j) {
            float s = 0.f;
            const float4* kr = (const float4*)ks[j];
#pragma unroll
            for (int d4 = 0; d4 < 16; ++d4) {
                float4 kv = kr[d4];
                s += q[4*d4+0]*kv.x + q[4*d4+1]*kv.y + q[4*d4+2]*kv.z + q[4*d4+3]*kv.w;
            }
            const float4* vr = (const float4*)vs[j];
            if (s <= m) {
                float p = __expf(s - m);
                l += p;
#pragma unroll
                for (int d4 = 0; d4 < 16; ++d4) {
                    float4 vv = vr[d4];
                    o[4*d4+0] += p*vv.x; o[4*d4+1] += p*vv.y;
                    o[4*d4+2] += p*vv.z; o[4*d4+3] += p*vv.w;
                }
            } else {
                float al = __expf(m - s);
                m = s; l = l * al + 1.f;
#pragma unroll
                for (int d4 = 0; d4 < 16; ++d4) {
                    float4 vv = vr[d4];
                    o[4*d4+0] = o[4*d4+0]*al + vv.x; o[4*d4+1] = o[4*d4+1]*al + vv.y;
                    o[4*d4+2] = o[4*d4+2]*al + vv.z; o[4*d4+3] = o[4*d4+3]*al + vv.w;
                }
            }
        }
        __syncthreads();
    }

    const float inv = 1.f / l;
    const size_t ob = ((size_t)(b * SEQ + qi)) * DIM + h * HD;
#pragma unroll
    for (int d4 = 0; d4 < 16; ++d4) {
        float v0 = o[4*d4+0]*inv, v1 = o[4*d4+1]*inv;
        float v2 = o[4*d4+2]*inv, v3 = o[4*d4+3]*inv;
        __half2 h0 = __floats2half2_rn(v0, v1);
        __half2 h1 = __floats2half2_rn(v2, v3);
        float2 f0 = __half22float2(h0), f1 = __half22float2(h1);
        __half2 l0 = __floats2half2_rn(v0 - f0.x, v1 - f0.y);
        __half2 l1 = __floats2half2_rn(v2 - f1.x, v3 - f1.y);
        *(uint2*)(oh + ob + 4*d4) = make_uint2(*(uint32_t*)&h0, *(uint32_t*)&h1);
        *(uint2*)(ol + ob + 4*d4) = make_uint2(*(uint32_t*)&l0, *(uint32_t*)&l1);
    }
}

// ----------------- fused residual-add + LayerNorm (+split out) ------------
__global__ __launch_bounds__(256) void add_ln_kernel(const float* __restrict__ x,
    const float* __restrict__ r, const float* __restrict__ gg,
    const float* __restrict__ bb, float* __restrict__ y,
    __half* __restrict__ yh, __half* __restrict__ yl)
{
    const int row = blockIdx.x;
    const int t = threadIdx.x;
    __shared__ float red[8];
    __shared__ float bc0, bc1;

    const float* xr = x + (size_t)row * DIM;
    const float* rr = r + (size_t)row * DIM;
    float v[3]; float s = 0.f;
#pragma unroll
    for (int i = 0; i < 3; ++i) { int c = t + i * 256; v[i] = xr[c] + rr[c]; s += v[i]; }
#pragma unroll
    for (int off = 16; off; off >>= 1) s += __shfl_xor_sync(0xffffffffu, s, off);
    if ((t & 31) == 0) red[t >> 5] = s;
    __syncthreads();
    if (t == 0) { float tot = 0.f;
#pragma unroll
        for (int w = 0; w < 8; ++w) tot += red[w];
        bc0 = tot * (1.f / DIM);
    }
    __syncthreads();
    const float mean = bc0;
    float sq = 0.f;
#pragma unroll
    for (int i = 0; i < 3; ++i) { float d = v[i] - mean; sq += d * d; }
#pragma unroll
    for (int off = 16; off; off >>= 1) sq += __shfl_xor_sync(0xffffffffu, sq, off);
    if ((t & 31) == 0) red[t >> 5] = sq;
    __syncthreads();
    if (t == 0) { float tot = 0.f;
#pragma unroll
        for (int w = 0; w < 8; ++w) tot += red[w];
        bc1 = rsqrtf(tot * (1.f / DIM) + 1e-5f);
    }
    __syncthreads();
    const float rstd = bc1;
#pragma unroll
    for (int i = 0; i < 3; ++i) {
        int c = t + i * 256;
        float val = (v[i] - mean) * rstd * gg[c] + bb[c];
        y[(size_t)row * DIM + c] = val;
        __half hh = __float2half_rn(val);
        __half ll = __float2half_rn(val - __half2float(hh));
        yh[(size_t)row * DIM + c] = hh;
        yl[(size_t)row * DIM + c] = ll;
    }
}

// ----------------- final LN with 4-way CMS mean ----------------------------
__global__ __launch_bounds__(256) void ln_final_kernel(const float* __restrict__ xc,
    const float* __restrict__ c0, const float* __restrict__ c1,
    const float* __restrict__ c2, const float* __restrict__ c3,
    const float* __restrict__ gg, const float* __restrict__ bb,
    float* __restrict__ y)
{
    const int row = blockIdx.x;
    const int t = threadIdx.x;
    __shared__ float red[8];
    __shared__ float bc0, bc1;

    const size_t rb = (size_t)row * DIM;
    float v[3]; float s = 0.f;
#pragma unroll
    for (int i = 0; i < 3; ++i) {
        int c = t + i * 256;
        v[i] = xc[rb + c] + 0.25f * (c0[rb + c] + c1[rb + c] + c2[rb + c] + c3[rb + c]);
        s += v[i];
    }
#pragma unroll
    for (int off = 16; off; off >>= 1) s += __shfl_xor_sync(0xffffffffu, s, off);
    if ((t & 31) == 0) red[t >> 5] = s;
    __syncthreads();
    if (t == 0) { float tot = 0.f;
#pragma unroll
        for (int w = 0; w < 8; ++w) tot += red[w];
        bc0 = tot * (1.f / DIM);
    }
    __syncthreads();
    const float mean = bc0;
    float sq = 0.f;
#pragma unroll
    for (int i = 0; i < 3; ++i) { float d = v[i] - mean; sq += d * d; }
#pragma unroll
    for (int off = 16; off; off >>= 1) sq += __shfl_xor_sync(0xffffffffu, sq, off);
    if ((t & 31) == 0) red[t >> 5] = sq;
    __syncthreads();
    if (t == 0) { float tot = 0.f;
#pragma unroll
        for (int w = 0; w < 8; ++w) tot += red[w];
        bc1 = rsqrtf(tot * (1.f / DIM) + 1e-5f);
    }
    __syncthreads();
    const float rstd = bc1;
#pragma unroll
    for (int i = 0; i < 3; ++i) {
        int c = t + i * 256;
        y[rb + c] = (v[i] - mean) * rstd * gg[c] + bb[c];
    }
}

// ----------------- delta-rule scan (split f16 out) -------------------------
__global__ __launch_bounds__(256) void delta_scan_kernel(const float* __restrict__ tq,
    const float* __restrict__ tk, const float* __restrict__ tv,
    __half* __restrict__ toh, __half* __restrict__ tol, float* __restrict__ Mout)
{
    const int bh = blockIdx.x;
    const int b = bh / NH, h = bh % NH;
    const int t = threadIdx.x;
    const int e = t & 63;
    const int g = t >> 6;

    __shared__ float ks[64], vs[64], qs[64];
    __shared__ float part[4][64];
    __shared__ float opart[4][64];

    float Mreg[16];
#pragma unroll
    for (int i = 0; i < 16; ++i) Mreg[i] = 0.f;

    const size_t base = ((size_t)b * SEQ) * DIM + h * HD + e;
    float nxt = 0.f;
    if (g == 0) nxt = tk[base];
    else if (g == 1) nxt = tv[base];
    else if (g == 2) nxt = tq[base];

    for (int s = 0; s < SEQ; ++s) {
        if (g == 0) ks[e] = nxt;
        else if (g == 1) vs[e] = nxt;
        else if (g == 2) qs[e] = nxt;
        __syncthreads();
        if (s + 1 < SEQ) {
            size_t nb = base + (size_t)(s + 1) * DIM;
            if (g == 0) nxt = tk[nb];
            else if (g == 1) nxt = tv[nb];
            else if (g == 2) nxt = tq[nb];
        }
        float kreg[16];
        float p0 = 0.f, p1 = 0.f, p2 = 0.f, p3 = 0.f;
#pragma unroll
        for (int i = 0; i < 16; i += 4) {
            kreg[i+0] = ks[g*16 + i+0]; kreg[i+1] = ks[g*16 + i+1];
            kreg[i+2] = ks[g*16 + i+2]; kreg[i+3] = ks[g*16 + i+3];
            p0 += Mreg[i+0]*kreg[i+0]; p1 += Mreg[i+1]*kreg[i+1];
            p2 += Mreg[i+2]*kreg[i+2]; p3 += Mreg[i+3]*kreg[i+3];
        }
        part[g][e] = (p0 + p1) + (p2 + p3);
        __syncthreads();
        const float pred  = (part[0][e] + part[1][e]) + (part[2][e] + part[3][e]);
        const float delta = LRATE * (vs[e] - pred);
        float q0 = 0.f, q1 = 0.f, q2 = 0.f, q3 = 0.f;
#pragma unroll
        for (int i = 0; i < 16; i += 4) {
            Mreg[i+0] += kreg[i+0]*delta; q0 += Mreg[i+0]*qs[g*16 + i+0];
            Mreg[i+1] += kreg[i+1]*delta; q1 += Mreg[i+1]*qs[g*16 + i+1];
            Mreg[i+2] += kreg[i+2]*delta; q2 += Mreg[i+2]*qs[g*16 + i+2];
            Mreg[i+3] += kreg[i+3]*delta; q3 += Mreg[i+3]*qs[g*16 + i+3];
        }
        opart[g][e] = (q0 + q1) + (q2 + q3);
        __syncthreads();
        if (g == 0) {
            float ov = (opart[0][e] + opart[1][e]) + (opart[2][e] + opart[3][e]);
            __half hh = __float2half_rn(ov);
            __half ll = __float2half_rn(ov - __half2float(hh));
            toh[base + (size_t)s * DIM] = hh;
            tol[base + (size_t)s * DIM] = ll;
        }
    }
    if (Mout) {
#pragma unroll
        for (int i = 0; i < 16; ++i)
            Mout[(((size_t)b * NH + h) * HD + (g * 16 + i)) * HD + e] = Mreg[i];
    }
}

// ----------------- launch ---------------------------------------------------
static void* symp(const void* s) {
    void* p = nullptr;
    cudaGetSymbolAddress(&p, s);
    return p;
}
static void split_arr(const float* s, __half* h, __half* l, size_t n, cudaStream_t st) {
    int n4 = (int)(n / 4);
    split_kernel<<<(n4 + 255) / 256, 256, 0, st>>>((const float4*)s, (uint2*)h, (uint2*)l, n4);
}

extern "C" void kernel_launch(void* const* d_in, const int* in_sizes, int n_in,
                              void* d_out, int out_size)
{
    const float* x          = (const float*)d_in[0];
    const float* in_proj_w  = (const float*)d_in[1];
    const float* in_proj_b  = (const float*)d_in[2];
    const float* out_proj_w = (const float*)d_in[3];
    const float* out_proj_b = (const float*)d_in[4];
    const float* ln_local_g = (const float*)d_in[5];
    const float* ln_local_b = (const float*)d_in[6];
    const float* t_wq       = (const float*)d_in[7];
    const float* t_wk       = (const float*)d_in[8];
    const float* t_wv       = (const float*)d_in[9];
    const float* t_wo       = (const float*)d_in[10];
    const float* ln_tit_g   = (const float*)d_in[11];
    const float* ln_tit_b   = (const float*)d_in[12];
    const float* gate_w     = (const float*)d_in[13];
    const float* gate_b     = (const float*)d_in[14];
    const float* cms_w1     = (const float*)d_in[15];
    const float* cms_b1     = (const float*)d_in[16];
    const float* cms_w2     = (const float*)d_in[17];
    const float* cms_b2     = (const float*)d_in[18];
    const float* ln_cms_g   = (const float*)d_in[19];
    const float* ln_cms_b   = (const float*)d_in[20];

    float* qkv    = (float*)symp(g_qkv);
    float* proj   = (float*)symp(g_proj);
    float* proj2  = (float*)symp(g_proj2);
    float* xlocal = (float*)symp(g_xlocal);
    float* xglob  = (float*)symp(g_xglobal);
    float* tq     = (float*)symp(g_tq);
    float* tk     = (float*)symp(g_tk);
    float* tv     = (float*)symp(g_tv);
    float* xc     = (float*)symp(g_xc);
    float* cmsb   = (float*)symp(g_cms);

    __half* x_h   = (__half*)symp(g_x_h);   __half* x_l   = (__half*)symp(g_x_l);
    __half* wi_h  = (__half*)symp(g_wi_h);  __half* wi_l  = (__half*)symp(g_wi_l);
    __half* wo_h  = (__half*)symp(g_wo_h);  __half* wo_l  = (__half*)symp(g_wo_l);
    __half* wtq_h = (__half*)symp(g_wtq_h); __half* wtq_l = (__half*)symp(g_wtq_l);
    __half* wtk_h = (__half*)symp(g_wtk_h); __half* wtk_l = (__half*)symp(g_wtk_l);
    __half* wtv_h = (__half*)symp(g_wtv_h); __half* wtv_l = (__half*)symp(g_wtv_l);
    __half* wto_h = (__half*)symp(g_wto_h); __half* wto_l = (__half*)symp(g_wto_l);
    __half* wg_h  = (__half*)symp(g_wg_h);  __half* wg_l  = (__half*)symp(g_wg_l);
    __half* wc1_h = (__half*)symp(g_wc1_h); __half* wc1_l = (__half*)symp(g_wc1_l);
    __half* wc2_h = (__half*)symp(g_wc2_h); __half* wc2_l = (__half*)symp(g_wc2_l);
    __half* att_h = (__half*)symp(g_att_h); __half* att_l = (__half*)symp(g_att_l);
    __half* to_h  = (__half*)symp(g_to_h);  __half* to_l  = (__half*)symp(g_to_l);
    __half* xl_h  = (__half*)symp(g_xl_h);  __half* xl_l  = (__half*)symp(g_xl_l);
    __half* xg_h  = (__half*)symp(g_xg_h);  __half* xg_l  = (__half*)symp(g_xg_l);
    __half* xc_h  = (__half*)symp(g_xc_h);  __half* xc_l  = (__half*)symp(g_xc_l);
    __half* hb_h  = (__half*)symp(g_hb_h);  __half* hb_l  = (__half*)symp(g_hb_l);

    float* out = (float*)d_out;
    float* mout = (out_size >= ROWS * DIM + BATCH * NH * HD * HD)
                      ? out + (size_t)ROWS * DIM : nullptr;

    static cudaStream_t s2 = nullptr;
    static cudaEvent_t ev_fork = nullptr, ev_join = nullptr;
    if (!s2) {
        cudaFuncSetAttribute(gemm_tc, cudaFuncAttributeMaxDynamicSharedMemorySize, GEMM_SMEM);
        cudaStreamCreateWithFlags(&s2, cudaStreamNonBlocking);
        cudaEventCreateWithFlags(&ev_fork, cudaEventDisableTiming);
        cudaEventCreateWithFlags(&ev_join, cudaEventDisableTiming);
    }

    B4 b{};

    // [0] split x, then fork
    split_arr(x, x_h, x_l, (size_t)ROWS * DIM, 0);
    cudaEventRecord(ev_fork, 0);
    cudaStreamWaitEvent(s2, ev_fork, 0);

    // [0] remaining weight splits (overlap with s2 titans branch)
    split_arr(in_proj_w, wi_h, wi_l, (size_t)3 * DIM * DIM, 0);
    split_arr(out_proj_w, wo_h, wo_l, (size_t)DIM * DIM, 0);
    split_arr(gate_w, wg_h, wg_l, (size_t)2 * DIM * DIM, 0);
    split_arr(cms_w1, wc1_h, wc1_l, (size_t)16 * DIM * DIM, 0);
    split_arr(cms_w2, wc2_h, wc2_l, (size_t)16 * DIM * DIM, 0);

    // [s2] titans weight splits + projections (z-batched x3)
    split_arr(t_wq, wtq_h, wtq_l, (size_t)DIM * DIM, s2);
    split_arr(t_wk, wtk_h, wtk_l, (size_t)DIM * DIM, s2);
    split_arr(t_wv, wtv_h, wtv_l, (size_t)DIM * DIM, s2);
    split_arr(t_wo, wto_h, wto_l, (size_t)DIM * DIM, s2);
    b = B4{};
    b.Ah[0] = x_h; b.Al[0] = x_l; b.Wh[0] = wtq_h; b.Wl[0] = wtq_l; b.C[0] = tq;
    b.Ah[1] = x_h; b.Al[1] = x_l; b.Wh[1] = wtk_h; b.Wl[1] = wtk_l; b.C[1] = tk;
    b.Ah[2] = x_h; b.Al[2] = x_l; b.Wh[2] = wtv_h; b.Wl[2] = wtv_l; b.C[2] = tv;
    gemm_tc<<<dim3(DIM / TBN, ROWS / TBM, 3), 256, GEMM_SMEM, s2>>>(b, DIM, DIM, DIM, DIM, 0);

    // [s2] delta-rule scan (split outputs + memory_state)
    delta_scan_kernel<<<BATCH * NH, 256, 0, s2>>>(tq, tk, tv, to_h, to_l, mout);

    // [s2] titans out proj + residual LN -> x_global (+split)
    b = B4{};
    b.Ah[0] = to_h; b.Al[0] = to_l; b.Wh[0] = wto_h; b.Wl[0] = wto_l; b.C[0] = proj2;
    gemm_tc<<<dim3(DIM / TBN, ROWS / TBM, 1), 256, GEMM_SMEM, s2>>>(b, DIM, DIM, DIM, DIM, 0);
    add_ln_kernel<<<ROWS, 256, 0, s2>>>(x, proj2, ln_tit_g, ln_tit_b, xglob, xg_h, xg_l);
    cudaEventRecord(ev_join, s2);

    // [0] packed QKV projection
    b = B4{};
    b.Ah[0] = x_h; b.Al[0] = x_l; b.Wh[0] = wi_h; b.Wl[0] = wi_l;
    b.bias[0] = in_proj_b; b.C[0] = qkv;
    gemm_tc<<<dim3(3 * DIM / TBN, ROWS / TBM, 1), 256, GEMM_SMEM>>>(b, DIM, DIM, 3 * DIM, DIM, 0);

    // [0] sliding-window attention -> split att
    attn_kernel<<<dim3(SEQ / 64, BATCH, NH), 64>>>(qkv, att_h, att_l);

    // [0] out_proj + residual LN -> x_local (+split)
    b = B4{};
    b.Ah[0] = att_h; b.Al[0] = att_l; b.Wh[0] = wo_h; b.Wl[0] = wo_l;
    b.bias[0] = out_proj_b; b.C[0] = proj;
    gemm_tc<<<dim3(DIM / TBN, ROWS / TBM, 1), 256, GEMM_SMEM>>>(b, DIM, DIM, DIM, DIM, 0);
    add_ln_kernel<<<ROWS, 256>>>(x, proj, ln_local_g, ln_local_b, xlocal, xl_h, xl_l);

    // ---- join ----
    cudaStreamWaitEvent(0, ev_join, 0);

    // [0] gate: two K-passes over [xlocal|xglob] with fused sigmoid-combine
    b = B4{};
    b.Ah[0] = xl_h; b.Al[0] = xl_l; b.Wh[0] = wg_h; b.Wl[0] = wg_l;
    b.bias[0] = gate_b; b.C[0] = xc;
    b.A2h = xg_h; b.A2l = xg_l; b.W2h = wg_h + DIM; b.W2l = wg_l + DIM;
    b.xl = xlocal; b.xg = xglob; b.xch = xc_h; b.xcl = xc_l;
    gemm_tc<<<dim3(DIM / TBN, ROWS / TBM, 1), 256, GEMM_SMEM>>>(b, DIM, 2 * DIM, DIM, DIM, 3);

    // [0] CMS: w1 x4 (gelu, split-only output), z-batched
    b = B4{};
    for (int l = 0; l < 4; ++l) {
        b.Ah[l] = xc_h; b.Al[l] = xc_l;
        b.Wh[l] = wc1_h + (size_t)l * 4 * DIM * DIM;
        b.Wl[l] = wc1_l + (size_t)l * 4 * DIM * DIM;
        b.bias[l] = cms_b1 + (size_t)l * 4 * DIM;
        b.Ch[l] = hb_h + (size_t)l * ROWS * 4 * DIM;
        b.Cl[l] = hb_l + (size_t)l * ROWS * 4 * DIM;
    }
    gemm_tc<<<dim3(4 * DIM / TBN, ROWS / TBM, 4), 256, GEMM_SMEM>>>(b, DIM, DIM, 4 * DIM, DIM, 1);

    // [0] CMS: w2 x4, z-batched, per-level f32 outputs
    b = B4{};
    for (int l = 0; l < 4; ++l) {
        b.Ah[l] = hb_h + (size_t)l * ROWS * 4 * DIM;
        b.Al[l] = hb_l + (size_t)l * ROWS * 4 * DIM;
        b.Wh[l] = wc2_h + (size_t)l * 4 * DIM * DIM;
        b.Wl[l] = wc2_l + (size_t)l * 4 * DIM * DIM;
        b.bias[l] = cms_b2 + (size_t)l * DIM;
        b.C[l] = cmsb + (size_t)l * ROWS * DIM;
    }
    gemm_tc<<<dim3(DIM / TBN, ROWS / TBM, 4), 256, GEMM_SMEM>>>(b, 4 * DIM, 4 * DIM, DIM, 4 * DIM, 0);

    // [0] final LN: out = LN(xc + mean over levels)
    ln_final_kernel<<<ROWS, 256>>>(xc, cmsb, cmsb + (size_t)ROWS * DIM,
                                   cmsb + 2 * (size_t)ROWS * DIM, cmsb + 3 * (size_t)ROWS * DIM,
                                   ln_cms_g, ln_cms_b, out);
}

// round 8
// speedup vs baseline: 2.8361x; 1.0076x over previous
#include <cuda_runtime.h>
#include <cuda_fp16.h>
#include <math.h>
#include <stdint.h>

#define SEQ   2048
#define BATCH 2
#define DIM   768
#define NH    12
#define HD    64
#define WIN   512
#define ROWS  (BATCH*SEQ)     // 4096
#define LRATE 0.1f

typedef unsigned long long ull;

// ----------------- device scratch (no cudaMalloc allowed) -----------------
__device__ float g_qkv[ROWS*3*DIM];
__device__ float g_proj[ROWS*DIM];
__device__ float g_proj2[ROWS*DIM];
__device__ float g_xlocal[ROWS*DIM];
__device__ float g_xglobal[ROWS*DIM];
__device__ float g_tq[ROWS*DIM];
__device__ float g_tk[ROWS*DIM];
__device__ float g_tv[ROWS*DIM];
__device__ float g_xc[ROWS*DIM];
__device__ float g_cms[4*(size_t)ROWS*DIM];

// hi/lo f16 planes for GEMM operands
__device__ __half g_x_h[ROWS*DIM],     g_x_l[ROWS*DIM];
__device__ __half g_wi_h[3*DIM*DIM],   g_wi_l[3*DIM*DIM];
__device__ __half g_wo_h[DIM*DIM],     g_wo_l[DIM*DIM];
__device__ __half g_wtq_h[DIM*DIM],    g_wtq_l[DIM*DIM];
__device__ __half g_wtk_h[DIM*DIM],    g_wtk_l[DIM*DIM];
__device__ __half g_wtv_h[DIM*DIM],    g_wtv_l[DIM*DIM];
__device__ __half g_wto_h[DIM*DIM],    g_wto_l[DIM*DIM];
__device__ __half g_wg_h[2*DIM*DIM],   g_wg_l[2*DIM*DIM];
__device__ __half g_wc1_h[4*4*DIM*DIM], g_wc1_l[4*4*DIM*DIM];
__device__ __half g_wc2_h[4*4*DIM*DIM], g_wc2_l[4*4*DIM*DIM];
__device__ __half g_att_h[ROWS*DIM],   g_att_l[ROWS*DIM];
__device__ __half g_to_h[ROWS*DIM],    g_to_l[ROWS*DIM];
__device__ __half g_xl_h[ROWS*DIM],    g_xl_l[ROWS*DIM];
__device__ __half g_xg_h[ROWS*DIM],    g_xg_l[ROWS*DIM];
__device__ __half g_xc_h[ROWS*DIM],    g_xc_l[ROWS*DIM];
__device__ __half g_hb_h[4*(size_t)ROWS*4*DIM], g_hb_l[4*(size_t)ROWS*4*DIM];

// ----------------- f32x2 packed helpers ------------------------------------
__device__ __forceinline__ void ffma2(ull& d, ull a, ull b) {      // d += a*b
    asm("fma.rn.f32x2 %0, %1, %2, %0;" : "+l"(d) : "l"(a), "l"(b));
}
__device__ __forceinline__ void ffma2b(ull& d, ull a, ull b) {     // d = d*a + b
    asm("fma.rn.f32x2 %0, %0, %1, %2;" : "+l"(d) : "l"(a), "l"(b));
}
__device__ __forceinline__ ull pack2f(float x, float y) {
    ull r; asm("mov.b64 %0, {%1, %2};" : "=l"(r) : "f"(x), "f"(y)); return r;
}
__device__ __forceinline__ float2 unpack2f(ull v) {
    float x, y; asm("mov.b64 {%0, %1}, %2;" : "=f"(x), "=f"(y) : "l"(v));
    return make_float2(x, y);
}

// ===================== fp16x3 GEMM with pre-split operands =================
#define TBM 128
#define TBN 128
#define TBK 32
#define STG_BYTES 32768
#define GEMM_SMEM (3*STG_BYTES)          // 98304 -> 2 blocks/SM

#define CP_ASYNC16(dst, src) \
    asm volatile("cp.async.cg.shared.global [%0], [%1], 16;" :: "r"(dst), "l"(src))
#define CP_COMMIT() asm volatile("cp.async.commit_group;")
#define CP_WAIT1()  asm volatile("cp.async.wait_group 1;" ::: "memory")
#define CP_WAIT0()  asm volatile("cp.async.wait_group 0;" ::: "memory")
#define LDSM_X4(r0,r1,r2,r3,addr) \
    asm volatile("ldmatrix.sync.aligned.m8n8.x4.shared.b16 {%0,%1,%2,%3}, [%4];" \
        : "=r"(r0),"=r"(r1),"=r"(r2),"=r"(r3) : "r"(addr))

struct B4 {
    const __half *Ah[4], *Al[4], *Wh[4], *Wl[4];
    const float* bias[4];
    float* C[4];
    __half *Ch[4], *Cl[4];
    const __half *A2h, *A2l, *W2h, *W2l;
    const float *xl, *xg;
    __half *xch, *xcl;
};

__device__ __forceinline__ uint32_t smem_u32(const void* p) {
    uint32_t a;
    asm("{ .reg .u64 t; cvta.to.shared.u64 t, %1; cvt.u32.u64 %0, t; }" : "=r"(a) : "l"(p));
    return a;
}
__device__ __forceinline__ void mma_f16(float* c, uint32_t a0, uint32_t a1,
                                        uint32_t a2, uint32_t a3,
                                        uint32_t b0, uint32_t b1) {
    asm volatile("mma.sync.aligned.m16n8k16.row.col.f32.f16.f16.f32 "
                 "{%0,%1,%2,%3}, {%4,%5,%6,%7}, {%8,%9}, {%0,%1,%2,%3};"
                 : "+f"(c[0]), "+f"(c[1]), "+f"(c[2]), "+f"(c[3])
                 : "r"(a0), "r"(a1), "r"(a2), "r"(a3), "r"(b0), "r"(b1));
}

__global__ __launch_bounds__(256, 2) void gemm_tc(
    B4 b, int lda, int ldw, int N, int K, int epi)
{
    extern __shared__ char smc[];
    const int t   = threadIdx.x;
    const int lid = t & 31;
    const int wid = t >> 5;
    const int wm  = wid & 1;
    const int wn  = wid >> 1;
    const int grp = lid >> 2;
    const int tg  = lid & 3;
    const int bm  = blockIdx.y * TBM;
    const int bn  = blockIdx.x * TBN;
    const int z   = blockIdx.z;

    float acc[4][4][4];
#pragma unroll
    for (int mi = 0; mi < 4; ++mi)
#pragma unroll
        for (int ni = 0; ni < 4; ++ni)
#pragma unroll
            for (int r = 0; r < 4; ++r) acc[mi][ni][r] = 0.f;

    const int nstage = K / TBK;
    const int npass  = b.A2h ? 2 : 1;
    const uint32_t sbase = smem_u32(smc);

    for (int pass = 0; pass < npass; ++pass) {
        const __half* pAh = pass ? b.A2h : b.Ah[z];
        const __half* pAl = pass ? b.A2l : b.Al[z];
        const __half* pWh = pass ? b.W2h : b.Wh[z];
        const __half* pWl = pass ? b.W2l : b.Wl[z];
        __syncthreads();

        auto ld_stage = [&](int buf, int k0) {
#pragma unroll
            for (int i = 0; i < 8; ++i) {
                const int tile = i >> 1;               // 0:Ahi 1:Alo 2:Whi 3:Wlo
                const int rem  = ((i & 1) << 8) + t;   // 0..511
                const int row  = rem >> 2;
                const int chn  = t & 3;
                const __half* src;
                if (tile == 0)      src = pAh + (size_t)(bm + row) * lda + k0 + chn * 8;
                else if (tile == 1) src = pAl + (size_t)(bm + row) * lda + k0 + chn * 8;
                else if (tile == 2) src = pWh + (size_t)(bn + row) * ldw + k0 + chn * 8;
                else                src = pWl + (size_t)(bn + row) * ldw + k0 + chn * 8;
                const uint32_t dst = sbase + buf * STG_BYTES + tile * 8192
                                   + row * 64 + ((chn ^ ((row >> 1) & 3)) << 4);
                CP_ASYNC16(dst, src);
            }
        };

        ld_stage(0, 0);   CP_COMMIT();
        ld_stage(1, TBK); CP_COMMIT();

        const int lr    = lid & 7;
        const int hsel  = (lid >> 3) & 1;
        const int seg2  = (lid >> 4) & 1;

        for (int s = 0; s < nstage; ++s) {
            if (s == nstage - 1) CP_WAIT0(); else CP_WAIT1();
            __syncthreads();
            if (s + 2 < nstage) { ld_stage((s + 2) % 3, (s + 2) * TBK); CP_COMMIT(); }

            const uint32_t stg = sbase + (s % 3) * STG_BYTES;
            const uint32_t a_h = stg, a_l = stg + 8192;
            const uint32_t w_h = stg + 16384, w_l = stg + 24576;

#pragma unroll
            for (int kk = 0; kk < 2; ++kk) {
                uint32_t bh[4][2], bl[4][2];
#pragma unroll
                for (int np = 0; np < 2; ++np) {
                    // X4 over ni pair: lanes0-7 ni0/k0, 8-15 ni0/k1, 16-23 ni1/k0, 24-31 ni1/k1
                    const int nr = wn * 32 + np * 16 + seg2 * 8 + lr;
                    const int ch = kk * 2 + hsel;
                    const uint32_t off = nr * 64 + ((ch ^ ((nr >> 1) & 3)) << 4);
                    LDSM_X4(bh[np*2][0], bh[np*2][1], bh[np*2+1][0], bh[np*2+1][1], w_h + off);
                    LDSM_X4(bl[np*2][0], bl[np*2][1], bl[np*2+1][0], bl[np*2+1][1], w_l + off);
                }
#pragma unroll
                for (int mi = 0; mi < 4; ++mi) {
                    const int ar = wm * 64 + mi * 16 + hsel * 8 + lr;
                    const int ch = kk * 2 + seg2;
                    const uint32_t off = ar * 64 + ((ch ^ ((ar >> 1) & 3)) << 4);
                    uint32_t ah[4], al[4];
                    LDSM_X4(ah[0], ah[1], ah[2], ah[3], a_h + off);
                    LDSM_X4(al[0], al[1], al[2], al[3], a_l + off);
#pragma unroll
                    for (int ni = 0; ni < 4; ++ni)
                        mma_f16(acc[mi][ni], ah[0], ah[1], ah[2], ah[3], bh[ni][0], bh[ni][1]);
#pragma unroll
                    for (int ni = 0; ni < 4; ++ni)
                        mma_f16(acc[mi][ni], al[0], al[1], al[2], al[3], bh[ni][0], bh[ni][1]);
#pragma unroll
                    for (int ni = 0; ni < 4; ++ni)
                        mma_f16(acc[mi][ni], ah[0], ah[1], ah[2], ah[3], bl[ni][0], bl[ni][1]);
                }
            }
        }
    }

    // ---------------- epilogue ----------------
#pragma unroll
    for (int mi = 0; mi < 4; ++mi) {
#pragma unroll
        for (int ni = 0; ni < 4; ++ni) {
            const int col = bn + wn * 32 + ni * 8 + 2 * tg;
            float bx = 0.f, by = 0.f;
            if (b.bias[z]) { bx = b.bias[z][col]; by = b.bias[z][col + 1]; }
#pragma unroll
            for (int hf = 0; hf < 2; ++hf) {
                const int row = bm + wm * 64 + mi * 16 + grp + hf * 8;
                float v0 = acc[mi][ni][hf * 2 + 0] + bx;
                float v1 = acc[mi][ni][hf * 2 + 1] + by;
                const size_t idx = (size_t)row * N + col;
                if (epi == 0) {
                    *(float2*)(b.C[z] + idx) = make_float2(v0, v1);
                } else if (epi == 1) {
                    float u3;
                    u3 = v0 * v0 * v0;
                    v0 = 0.5f * v0 * (1.f + tanhf(0.7978845608028654f * (v0 + 0.044715f * u3)));
                    u3 = v1 * v1 * v1;
                    v1 = 0.5f * v1 * (1.f + tanhf(0.7978845608028654f * (v1 + 0.044715f * u3)));
                    __half2 hh = __floats2half2_rn(v0, v1);
                    float2 hv = __half22float2(hh);
                    __half2 ll = __floats2half2_rn(v0 - hv.x, v1 - hv.y);
                    *(__half2*)(b.Ch[z] + idx) = hh;
                    *(__half2*)(b.Cl[z] + idx) = ll;
                } else { // epi == 3
                    float s0 = 1.f / (1.f + __expf(-v0));
                    float s1 = 1.f / (1.f + __expf(-v1));
                    float2 xl2 = *(const float2*)(b.xl + idx);
                    float2 xg2 = *(const float2*)(b.xg + idx);
                    v0 = s0 * xl2.x + (1.f - s0) * xg2.x;
                    v1 = s1 * xl2.y + (1.f - s1) * xg2.y;
                    *(float2*)(b.C[z] + idx) = make_float2(v0, v1);
                    __half2 hh = __floats2half2_rn(v0, v1);
                    float2 hv = __half22float2(hh);
                    __half2 ll = __floats2half2_rn(v0 - hv.x, v1 - hv.y);
                    *(__half2*)(b.xch + idx) = hh;
                    *(__half2*)(b.xcl + idx) = ll;
                }
            }
        }
    }
}

// ----------------- fused splitter: f32 -> f16 hi/lo, all tensors ----------
struct SplitSeg { const float4* src; uint2* hi; uint2* lo; unsigned n4; };
struct SplitTab { SplitSeg seg[10]; };

__global__ void split_all_kernel(SplitTab tab)
{
    unsigned idx = blockIdx.x * blockDim.x + threadIdx.x;
#pragma unroll
    for (int s = 0; s < 10; ++s) {
        if (idx < tab.seg[s].n4) {
            float4 v = tab.seg[s].src[idx];
            __half2 h0 = __floats2half2_rn(v.x, v.y);
            __half2 h1 = __floats2half2_rn(v.z, v.w);
            float2 f0 = __half22float2(h0), f1 = __half22float2(h1);
            __half2 l0 = __floats2half2_rn(v.x - f0.x, v.y - f0.y);
            __half2 l1 = __floats2half2_rn(v.z - f1.x, v.w - f1.y);
            tab.seg[s].hi[idx] = make_uint2(*(uint32_t*)&h0, *(uint32_t*)&h1);
            tab.seg[s].lo[idx] = make_uint2(*(uint32_t*)&l0, *(uint32_t*)&l1);
            return;
        }
        idx -= tab.seg[s].n4;
    }
}

// ----------------- sliding-window causal attention (f32x2) ----------------
__global__ __launch_bounds__(64) void attn_kernel(const float* __restrict__ qkv,
                                                  __half* __restrict__ oh,
                                                  __half* __restrict__ ol)
{
    const int qt = blockIdx.x;
    const int b  = blockIdx.y;
    const int h  = blockIdx.z;
    const int t  = threadIdx.x;
    const int qi = qt * 64 + t;

    __shared__ __align__(16) float ks[64][64];
    __shared__ __align__(16) float vs[64][64];

    ull q2[32], o2[32];
    {
        const float4* qb = (const float4*)(qkv + ((size_t)(b * SEQ + qi)) * (3 * DIM) + h * HD);
#pragma unroll
        for (int d4 = 0; d4 < 16; ++d4) {
            float4 v = qb[d4];
            q2[2*d4]   = pack2f(v.x * 0.125f, v.y * 0.125f);
            q2[2*d4+1] = pack2f(v.z * 0.125f, v.w * 0.125f);
        }
    }
#pragma unroll
    for (int i = 0; i < 32; ++i) o2[i] = 0ull;
    float m = -1e30f, l = 0.f;

    const int kt0 = (qt >= 8) ? (qt - 8) : 0;
    for (int kt = kt0; kt <= qt; ++kt) {
        const float* kbase = qkv + ((size_t)(b * SEQ + kt * 64)) * (3 * DIM) + DIM + h * HD + t;
        const float* vbase = kbase + DIM;
        for (int r = 0; r < 64; ++r) {
            ks[r][t] = kbase[(size_t)r * (3 * DIM)];
            vs[r][t] = vbase[(size_t)r * (3 * DIM)];
        }
        __syncthreads();

        int jlo = qi - WIN + 1 - kt * 64; if (jlo < 0)  jlo = 0;
        int jhi = qi - kt * 64;           if (jhi > 63) jhi = 63;
        for (int j = jlo; j <= jhi; ++j) {
            const ull* kr2 = (const ull*)ks[j];
            ull a0 = 0ull, a1 = 0ull, a2 = 0ull, a3 = 0ull;
#pragma unroll
            for (int i = 0; i < 32; i += 4) {
                ffma2(a0, q2[i],   kr2[i]);
                ffma2(a1, q2[i+1], kr2[i+1]);
                ffma2(a2, q2[i+2], kr2[i+2]);
                ffma2(a3, q2[i+3], kr2[i+3]);
            }
            float2 f0 = unpack2f(a0), f1 = unpack2f(a1);
            float2 f2 = unpack2f(a2), f3 = unpack2f(a3);
            float s = ((f0.x + f0.y) + (f1.x + f1.y)) + ((f2.x + f2.y) + (f3.x + f3.y));
            const ull* vr2 = (const ull*)vs[j];
            if (s <= m) {
                float p = __expf(s - m);
                l += p;
                ull p2 = pack2f(p, p);
#pragma unroll
                for (int i = 0; i < 32; ++i) ffma2(o2[i], p2, vr2[i]);
            } else {
                float al = __expf(m - s);
                m = s; l = l * al + 1.f;
                ull al2 = pack2f(al, al);
#pragma unroll
                for (int i = 0; i < 32; ++i) ffma2b(o2[i], al2, vr2[i]);
            }
        }
        __syncthreads();
    }

    const float inv = 1.f / l;
    const size_t ob = ((size_t)(b * SEQ + qi)) * DIM + h * HD;
#pragma unroll
    for (int i = 0; i < 32; i += 2) {
        float2 p0 = unpack2f(o2[i]), p1 = unpack2f(o2[i+1]);
        float v0 = p0.x * inv, v1 = p0.y * inv, v2 = p1.x * inv, v3 = p1.y * inv;
        __half2 h0 = __floats2half2_rn(v0, v1);
        __half2 h1 = __floats2half2_rn(v2, v3);
        float2 f0 = __half22float2(h0), f1 = __half22float2(h1);
        __half2 l0 = __floats2half2_rn(v0 - f0.x, v1 - f0.y);
        __half2 l1 = __floats2half2_rn(v2 - f1.x, v3 - f1.y);
        *(uint2*)(oh + ob + 2*i) = make_uint2(*(uint32_t*)&h0, *(uint32_t*)&h1);
        *(uint2*)(ol + ob + 2*i) = make_uint2(*(uint32_t*)&l0, *(uint32_t*)&l1);
    }
}

// ----------------- fused residual-add + LayerNorm (+split out) ------------
__global__ __launch_bounds__(256) void add_ln_kernel(const float* __restrict__ x,
    const float* __restrict__ r, const float* __restrict__ gg,
    const float* __restrict__ bb, float* __restrict__ y,
    __half* __restrict__ yh, __half* __restrict__ yl)
{
    const int row = blockIdx.x;
    const int t = threadIdx.x;
    __shared__ float red[8];
    __shared__ float bc0, bc1;

    const float* xr = x + (size_t)row * DIM;
    const float* rr = r + (size_t)row * DIM;
    float v[3]; float s = 0.f;
#pragma unroll
    for (int i = 0; i < 3; ++i) { int c = t + i * 256; v[i] = xr[c] + rr[c]; s += v[i]; }
#pragma unroll
    for (int off = 16; off; off >>= 1) s += __shfl_xor_sync(0xffffffffu, s, off);
    if ((t & 31) == 0) red[t >> 5] = s;
    __syncthreads();
    if (t == 0) { float tot = 0.f;
#pragma unroll
        for (int w = 0; w < 8; ++w) tot += red[w];
        bc0 = tot * (1.f / DIM);
    }
    __syncthreads();
    const float mean = bc0;
    float sq = 0.f;
#pragma unroll
    for (int i = 0; i < 3; ++i) { float d = v[i] - mean; sq += d * d; }
#pragma unroll
    for (int off = 16; off; off >>= 1) sq += __shfl_xor_sync(0xffffffffu, sq, off);
    if ((t & 31) == 0) red[t >> 5] = sq;
    __syncthreads();
    if (t == 0) { float tot = 0.f;
#pragma unroll
        for (int w = 0; w < 8; ++w) tot += red[w];
        bc1 = rsqrtf(tot * (1.f / DIM) + 1e-5f);
    }
    __syncthreads();
    const float rstd = bc1;
#pragma unroll
    for (int i = 0; i < 3; ++i) {
        int c = t + i * 256;
        float val = (v[i] - mean) * rstd * gg[c] + bb[c];
        y[(size_t)row * DIM + c] = val;
        __half hh = __float2half_rn(val);
        __half ll = __float2half_rn(val - __half2float(hh));
        yh[(size_t)row * DIM + c] = hh;
        yl[(size_t)row * DIM + c] = ll;
    }
}

// ----------------- final LN with 4-way CMS mean ----------------------------
__global__ __launch_bounds__(256) void ln_final_kernel(const float* __restrict__ xc,
    const float* __restrict__ c0, const float* __restrict__ c1,
    const float* __restrict__ c2, const float* __restrict__ c3,
    const float* __restrict__ gg, const float* __restrict__ bb,
    float* __restrict__ y)
{
    const int row = blockIdx.x;
    const int t = threadIdx.x;
    __shared__ float red[8];
    __shared__ float bc0, bc1;

    const size_t rb = (size_t)row * DIM;
    float v[3]; float s = 0.f;
#pragma unroll
    for (int i = 0; i < 3; ++i) {
        int c = t + i * 256;
        v[i] = xc[rb + c] + 0.25f * (c0[rb + c] + c1[rb + c] + c2[rb + c] + c3[rb + c]);
        s += v[i];
    }
#pragma unroll
    for (int off = 16; off; off >>= 1) s += __shfl_xor_sync(0xffffffffu, s, off);
    if ((t & 31) == 0) red[t >> 5] = s;
    __syncthreads();
    if (t == 0) { float tot = 0.f;
#pragma unroll
        for (int w = 0; w < 8; ++w) tot += red[w];
        bc0 = tot * (1.f / DIM);
    }
    __syncthreads();
    const float mean = bc0;
    float sq = 0.f;
#pragma unroll
    for (int i = 0; i < 3; ++i) { float d = v[i] - mean; sq += d * d; }
#pragma unroll
    for (int off = 16; off; off >>= 1) sq += __shfl_xor_sync(0xffffffffu, sq, off);
    if ((t & 31) == 0) red[t >> 5] = sq;
    __syncthreads();
    if (t == 0) { float tot = 0.f;
#pragma unroll
        for (int w = 0; w < 8; ++w) tot += red[w];
        bc1 = rsqrtf(tot * (1.f / DIM) + 1e-5f);
    }
    __syncthreads();
    const float rstd = bc1;
#pragma unroll
    for (int i = 0; i < 3; ++i) {
        int c = t + i * 256;
        y[rb + c] = (v[i] - mean) * rstd * gg[c] + bb[c];
    }
}

// ----------------- delta-rule scan: f32x2 + 2 barriers/step ---------------
__global__ __launch_bounds__(256) void delta_scan_kernel(const float* __restrict__ tq,
    const float* __restrict__ tk, const float* __restrict__ tv,
    __half* __restrict__ toh, __half* __restrict__ tol, float* __restrict__ Mout)
{
    const int bh = blockIdx.x;
    const int b = bh / NH, h = bh % NH;
    const int t = threadIdx.x;
    const int e = t & 63;
    const int g = t >> 6;

    __shared__ __align__(8) float ks[2][64], vs[2][64], qs[2][64];
    __shared__ float part[2][4][64];
    __shared__ float opart[2][4][64];

    ull M2[8];
#pragma unroll
    for (int i = 0; i < 8; ++i) M2[i] = 0ull;

    const size_t base = ((size_t)b * SEQ) * DIM + h * HD + e;
    float nxt = 0.f;
    if (g == 0) nxt = tk[base];
    else if (g == 1) nxt = tv[base];
    else if (g == 2) nxt = tq[base];

    for (int s = 0; s < SEQ; ++s) {
        const int p = s & 1;
        if (g == 0) ks[p][e] = nxt;
        else if (g == 1) vs[p][e] = nxt;
        else if (g == 2) qs[p][e] = nxt;
        __syncthreads();   // B1: staging visible; also publishes opart of step s-1
        if (s + 1 < SEQ) {
            size_t nb = base + (size_t)(s + 1) * DIM;
            if (g == 0) nxt = tk[nb];
            else if (g == 1) nxt = tv[nb];
            else if (g == 2) nxt = tq[nb];
        }
        // delayed output for step s-1
        if (g == 0 && s > 0) {
            const int pp = p ^ 1;
            float ov = (opart[pp][0][e] + opart[pp][1][e])
                     + (opart[pp][2][e] + opart[pp][3][e]);
            __half hh = __float2half_rn(ov);
            __half ll = __float2half_rn(ov - __half2float(hh));
            toh[base + (size_t)(s - 1) * DIM] = hh;
            tol[base + (size_t)(s - 1) * DIM] = ll;
        }
        // pred partial: sum_d M[d][e] * k[d] over this group's 16 d's
        ull k2[8];
        ull pa = 0ull, pb = 0ull;
        const ull* kp = (const ull*)&ks[p][g * 16];
#pragma unroll
        for (int i = 0; i < 8; i += 2) {
            k2[i] = kp[i]; k2[i+1] = kp[i+1];
            ffma2(pa, M2[i], k2[i]);
            ffma2(pb, M2[i+1], k2[i+1]);
        }
        float2 pf = unpack2f(pa), pg = unpack2f(pb);
        part[p][g][e] = (pf.x + pf.y) + (pg.x + pg.y);
        __syncthreads();   // B2: part visible
        const float pred  = (part[p][0][e] + part[p][1][e]) + (part[p][2][e] + part[p][3][e]);
        const float delta = LRATE * (vs[p][e] - pred);
        const ull d2 = pack2f(delta, delta);
        const ull* qp = (const ull*)&qs[p][g * 16];
        ull oa = 0ull, obb = 0ull;
#pragma unroll
        for (int i = 0; i < 8; i += 2) {
            ffma2(M2[i], k2[i], d2);     ffma2(oa, M2[i], qp[i]);
            ffma2(M2[i+1], k2[i+1], d2); ffma2(obb, M2[i+1], qp[i+1]);
        }
        float2 of = unpack2f(oa), og = unpack2f(obb);
        opart[p][g][e] = (of.x + of.y) + (og.x + og.y);
        // no barrier: next iteration's B1 publishes opart
    }
    __syncthreads();
    if (g == 0) {
        const int pp = (SEQ - 1) & 1;
        float ov = (opart[pp][0][e] + opart[pp][1][e]) + (opart[pp][2][e] + opart[pp][3][e]);
        __half hh = __float2half_rn(ov);
        __half ll = __float2half_rn(ov - __half2float(hh));
        toh[base + (size_t)(SEQ - 1) * DIM] = hh;
        tol[base + (size_t)(SEQ - 1) * DIM] = ll;
    }
    if (Mout) {
#pragma unroll
        for (int i = 0; i < 8; ++i) {
            float2 mv = unpack2f(M2[i]);
            Mout[(((size_t)b * NH + h) * HD + (g * 16 + 2*i))     * HD + e] = mv.x;
            Mout[(((size_t)b * NH + h) * HD + (g * 16 + 2*i + 1)) * HD + e] = mv.y;
        }
    }
}

// ----------------- launch ---------------------------------------------------
static void* symp(const void* s) {
    void* p = nullptr;
    cudaGetSymbolAddress(&p, s);
    return p;
}

extern "C" void kernel_launch(void* const* d_in, const int* in_sizes, int n_in,
                              void* d_out, int out_size)
{
    const float* x          = (const float*)d_in[0];
    const float* in_proj_w  = (const float*)d_in[1];
    const float* in_proj_b  = (const float*)d_in[2];
    const float* out_proj_w = (const float*)d_in[3];
    const float* out_proj_b = (const float*)d_in[4];
    const float* ln_local_g = (const float*)d_in[5];
    const float* ln_local_b = (const float*)d_in[6];
    const float* t_wq       = (const float*)d_in[7];
    const float* t_wk       = (const float*)d_in[8];
    const float* t_wv       = (const float*)d_in[9];
    const float* t_wo       = (const float*)d_in[10];
    const float* ln_tit_g   = (const float*)d_in[11];
    const float* ln_tit_b   = (const float*)d_in[12];
    const float* gate_w     = (const float*)d_in[13];
    const float* gate_b     = (const float*)d_in[14];
    const float* cms_w1     = (const float*)d_in[15];
    const float* cms_b1     = (const float*)d_in[16];
    const float* cms_w2     = (const float*)d_in[17];
    const float* cms_b2     = (const float*)d_in[18];
    const float* ln_cms_g   = (const float*)d_in[19];
    const float* ln_cms_b   = (const float*)d_in[20];

    float* qkv    = (float*)symp(g_qkv);
    float* proj   = (float*)symp(g_proj);
    float* proj2  = (float*)symp(g_proj2);
    float* xlocal = (float*)symp(g_xlocal);
    float* xglob  = (float*)symp(g_xglobal);
    float* tq     = (float*)symp(g_tq);
    float* tk     = (float*)symp(g_tk);
    float* tv     = (float*)symp(g_tv);
    float* xc     = (float*)symp(g_xc);
    float* cmsb   = (float*)symp(g_cms);

    __half* x_h   = (__half*)symp(g_x_h);   __half* x_l   = (__half*)symp(g_x_l);
    __half* wi_h  = (__half*)symp(g_wi_h);  __half* wi_l  = (__half*)symp(g_wi_l);
    __half* wo_h  = (__half*)symp(g_wo_h);  __half* wo_l  = (__half*)symp(g_wo_l);
    __half* wtq_h = (__half*)symp(g_wtq_h); __half* wtq_l = (__half*)symp(g_wtq_l);
    __half* wtk_h = (__half*)symp(g_wtk_h); __half* wtk_l = (__half*)symp(g_wtk_l);
    __half* wtv_h = (__half*)symp(g_wtv_h); __half* wtv_l = (__half*)symp(g_wtv_l);
    __half* wto_h = (__half*)symp(g_wto_h); __half* wto_l = (__half*)symp(g_wto_l);
    __half* wg_h  = (__half*)symp(g_wg_h);  __half* wg_l  = (__half*)symp(g_wg_l);
    __half* wc1_h = (__half*)symp(g_wc1_h); __half* wc1_l = (__half*)symp(g_wc1_l);
    __half* wc2_h = (__half*)symp(g_wc2_h); __half* wc2_l = (__half*)symp(g_wc2_l);
    __half* att_h = (__half*)symp(g_att_h); __half* att_l = (__half*)symp(g_att_l);
    __half* to_h  = (__half*)symp(g_to_h);  __half* to_l  = (__half*)symp(g_to_l);
    __half* xl_h  = (__half*)symp(g_xl_h);  __half* xl_l  = (__half*)symp(g_xl_l);
    __half* xg_h  = (__half*)symp(g_xg_h);  __half* xg_l  = (__half*)symp(g_xg_l);
    __half* xc_h  = (__half*)symp(g_xc_h);  __half* xc_l  = (__half*)symp(g_xc_l);
    __half* hb_h  = (__half*)symp(g_hb_h);  __half* hb_l  = (__half*)symp(g_hb_l);

    float* out = (float*)d_out;
    float* mout = (out_size >= ROWS * DIM + BATCH * NH * HD * HD)
                      ? out + (size_t)ROWS * DIM : nullptr;

    static cudaStream_t s2 = nullptr;
    static cudaEvent_t ev_fork = nullptr, ev_join = nullptr;
    if (!s2) {
        cudaFuncSetAttribute(gemm_tc, cudaFuncAttributeMaxDynamicSharedMemorySize, GEMM_SMEM);
        cudaStreamCreateWithFlags(&s2, cudaStreamNonBlocking);
        cudaEventCreateWithFlags(&ev_fork, cudaEventDisableTiming);
        cudaEventCreateWithFlags(&ev_join, cudaEventDisableTiming);
    }

    // [0] single fused split of all f32 operands -> f16 hi/lo planes
    {
        SplitTab tab{};
        unsigned tot4 = 0;
        auto add = [&](int i, const float* s, __half* h, __half* l, size_t n) {
            tab.seg[i] = SplitSeg{ (const float4*)s, (uint2*)h, (uint2*)l, (unsigned)(n / 4) };
            tot4 += (unsigned)(n / 4);
        };
        add(0, x, x_h, x_l, (size_t)ROWS * DIM);
        add(1, t_wq, wtq_h, wtq_l, (size_t)DIM * DIM);
        add(2, t_wk, wtk_h, wtk_l, (size_t)DIM * DIM);
        add(3, t_wv, wtv_h, wtv_l, (size_t)DIM * DIM);
        add(4, t_wo, wto_h, wto_l, (size_t)DIM * DIM);
        add(5, in_proj_w, wi_h, wi_l, (size_t)3 * DIM * DIM);
        add(6, out_proj_w, wo_h, wo_l, (size_t)DIM * DIM);
        add(7, gate_w, wg_h, wg_l, (size_t)2 * DIM * DIM);
        add(8, cms_w1, wc1_h, wc1_l, (size_t)16 * DIM * DIM);
        add(9, cms_w2, wc2_h, wc2_l, (size_t)16 * DIM * DIM);
        split_all_kernel<<<(tot4 + 255) / 256, 256>>>(tab);
    }

    cudaEventRecord(ev_fork, 0);
    cudaStreamWaitEvent(s2, ev_fork, 0);

    B4 b{};

    // [s2] Titans projections (z-batched x3)
    b = B4{};
    b.Ah[0] = x_h; b.Al[0] = x_l; b.Wh[0] = wtq_h; b.Wl[0] = wtq_l; b.C[0] = tq;
    b.Ah[1] = x_h; b.Al[1] = x_l; b.Wh[1] = wtk_h; b.Wl[1] = wtk_l; b.C[1] = tk;
    b.Ah[2] = x_h; b.Al[2] = x_l; b.Wh[2] = wtv_h; b.Wl[2] = wtv_l; b.C[2] = tv;
    gemm_tc<<<dim3(DIM / TBN, ROWS / TBM, 3), 256, GEMM_SMEM, s2>>>(b, DIM, DIM, DIM, DIM, 0);

    // [s2] delta-rule scan
    delta_scan_kernel<<<BATCH * NH, 256, 0, s2>>>(tq, tk, tv, to_h, to_l, mout);

    // [s2] titans out proj + residual LN -> x_global (+split)
    b = B4{};
    b.Ah[0] = to_h; b.Al[0] = to_l; b.Wh[0] = wto_h; b.Wl[0] = wto_l; b.C[0] = proj2;
    gemm_tc<<<dim3(DIM / TBN, ROWS / TBM, 1), 256, GEMM_SMEM, s2>>>(b, DIM, DIM, DIM, DIM, 0);
    add_ln_kernel<<<ROWS, 256, 0, s2>>>(x, proj2, ln_tit_g, ln_tit_b, xglob, xg_h, xg_l);
    cudaEventRecord(ev_join, s2);

    // [0] packed QKV projection
    b = B4{};
    b.Ah[0] = x_h; b.Al[0] = x_l; b.Wh[0] = wi_h; b.Wl[0] = wi_l;
    b.bias[0] = in_proj_b; b.C[0] = qkv;
    gemm_tc<<<dim3(3 * DIM / TBN, ROWS / TBM, 1), 256, GEMM_SMEM>>>(b, DIM, DIM, 3 * DIM, DIM, 0);

    // [0] sliding-window attention -> split att
    attn_kernel<<<dim3(SEQ / 64, BATCH, NH), 64>>>(qkv, att_h, att_l);

    // [0] out_proj + residual LN -> x_local (+split)
    b = B4{};
    b.Ah[0] = att_h; b.Al[0] = att_l; b.Wh[0] = wo_h; b.Wl[0] = wo_l;
    b.bias[0] = out_proj_b; b.C[0] = proj;
    gemm_tc<<<dim3(DIM / TBN, ROWS / TBM, 1), 256, GEMM_SMEM>>>(b, DIM, DIM, DIM, DIM, 0);
    add_ln_kernel<<<ROWS, 256>>>(x, proj, ln_local_g, ln_local_b, xlocal, xl_h, xl_l);

    // ---- join ----
    cudaStreamWaitEvent(0, ev_join, 0);

    // [0] gate: two K-passes with fused sigmoid-combine
    b = B4{};
    b.Ah[0] = xl_h; b.Al[0] = xl_l; b.Wh[0] = wg_h; b.Wl[0] = wg_l;
    b.bias[0] = gate_b; b.C[0] = xc;
    b.A2h = xg_h; b.A2l = xg_l; b.W2h = wg_h + DIM; b.W2l = wg_l + DIM;
    b.xl = xlocal; b.xg = xglob; b.xch = xc_h; b.xcl = xc_l;
    gemm_tc<<<dim3(DIM / TBN, ROWS / TBM, 1), 256, GEMM_SMEM>>>(b, DIM, 2 * DIM, DIM, DIM, 3);

    // [0] CMS: w1 x4 (gelu, split-only output), z-batched
    b = B4{};
    for (int l = 0; l < 4; ++l) {
        b.Ah[l] = xc_h; b.Al[l] = xc_l;
        b.Wh[l] = wc1_h + (size_t)l * 4 * DIM * DIM;
        b.Wl[l] = wc1_l + (size_t)l * 4 * DIM * DIM;
        b.bias[l] = cms_b1 + (size_t)l * 4 * DIM;
        b.Ch[l] = hb_h + (size_t)l * ROWS * 4 * DIM;
        b.Cl[l] = hb_l + (size_t)l * ROWS * 4 * DIM;
    }
    gemm_tc<<<dim3(4 * DIM / TBN, ROWS / TBM, 4), 256, GEMM_SMEM>>>(b, DIM, DIM, 4 * DIM, DIM, 1);

    // [0] CMS: w2 x4, z-batched, per-level f32 outputs
    b = B4{};
    for (int l = 0; l < 4; ++l) {
        b.Ah[l] = hb_h + (size_t)l * ROWS * 4 * DIM;
        b.Al[l] = hb_l + (size_t)l * ROWS * 4 * DIM;
        b.Wh[l] = wc2_h + (size_t)l * 4 * DIM * DIM;
        b.Wl[l] = wc2_l + (size_t)l * 4 * DIM * DIM;
        b.bias[l] = cms_b2 + (size_t)l * DIM;
        b.C[l] = cmsb + (size_t)l * ROWS * DIM;
    }
    gemm_tc<<<dim3(DIM / TBN, ROWS / TBM, 4), 256, GEMM_SMEM>>>(b, 4 * DIM, 4 * DIM, DIM, 4 * DIM, 0);

    // [0] final LN
    ln_final_kernel<<<ROWS, 256>>>(xc, cmsb, cmsb + (size_t)ROWS * DIM,
                                   cmsb + 2 * (size_t)ROWS * DIM, cmsb + 3 * (size_t)ROWS * DIM,
                                   ln_cms_g, ln_cms_b, out);
}

// round 9
// speedup vs baseline: 2.8593x; 1.0082x over previous
#include <cuda_runtime.h>
#include <cuda_fp16.h>
#include <math.h>
#include <stdint.h>

#define SEQ   2048
#define BATCH 2
#define DIM   768
#define NH    12
#define HD    64
#define WIN   512
#define ROWS  (BATCH*SEQ)     // 4096
#define LRATE 0.1f

typedef unsigned long long ull;

// ----------------- device scratch (no cudaMalloc allowed) -----------------
__device__ float g_qkv[ROWS*3*DIM];
__device__ float g_proj[ROWS*DIM];
__device__ float g_proj2[ROWS*DIM];
__device__ float g_xlocal[ROWS*DIM];
__device__ float g_xglobal[ROWS*DIM];
__device__ float g_tq[ROWS*DIM];
__device__ float g_tk[ROWS*DIM];
__device__ float g_tv[ROWS*DIM];
__device__ float g_xc[ROWS*DIM];
__device__ float g_cms[4*(size_t)ROWS*DIM];

// hi/lo f16 planes for GEMM operands
__device__ __half g_x_h[ROWS*DIM],     g_x_l[ROWS*DIM];
__device__ __half g_wi_h[3*DIM*DIM],   g_wi_l[3*DIM*DIM];
__device__ __half g_wo_h[DIM*DIM],     g_wo_l[DIM*DIM];
__device__ __half g_wtq_h[DIM*DIM],    g_wtq_l[DIM*DIM];
__device__ __half g_wtk_h[DIM*DIM],    g_wtk_l[DIM*DIM];
__device__ __half g_wtv_h[DIM*DIM],    g_wtv_l[DIM*DIM];
__device__ __half g_wto_h[DIM*DIM],    g_wto_l[DIM*DIM];
__device__ __half g_wg_h[2*DIM*DIM],   g_wg_l[2*DIM*DIM];
__device__ __half g_wc1_h[4*4*DIM*DIM], g_wc1_l[4*4*DIM*DIM];
__device__ __half g_wc2_h[4*4*DIM*DIM], g_wc2_l[4*4*DIM*DIM];
__device__ __half g_att_h[ROWS*DIM],   g_att_l[ROWS*DIM];
__device__ __half g_to_h[ROWS*DIM],    g_to_l[ROWS*DIM];
__device__ __half g_xl_h[ROWS*DIM],    g_xl_l[ROWS*DIM];
__device__ __half g_xg_h[ROWS*DIM],    g_xg_l[ROWS*DIM];
__device__ __half g_xc_h[ROWS*DIM],    g_xc_l[ROWS*DIM];
__device__ __half g_hb_h[4*(size_t)ROWS*4*DIM], g_hb_l[4*(size_t)ROWS*4*DIM];

// ----------------- f32x2 packed helpers ------------------------------------
__device__ __forceinline__ void ffma2(ull& d, ull a, ull b) {      // d += a*b
    asm("fma.rn.f32x2 %0, %1, %2, %0;" : "+l"(d) : "l"(a), "l"(b));
}
__device__ __forceinline__ void ffma2b(ull& d, ull a, ull b) {     // d = d*a + b
    asm("fma.rn.f32x2 %0, %0, %1, %2;" : "+l"(d) : "l"(a), "l"(b));
}
__device__ __forceinline__ ull pack2f(float x, float y) {
    ull r; asm("mov.b64 %0, {%1, %2};" : "=l"(r) : "f"(x), "f"(y)); return r;
}
__device__ __forceinline__ float2 unpack2f(ull v) {
    float x, y; asm("mov.b64 {%0, %1}, %2;" : "=f"(x), "=f"(y) : "l"(v));
    return make_float2(x, y);
}

// ===================== fp16x3 GEMM with pre-split operands =================
#define TBM 128
#define TBN 128
#define TBK 32
#define STG_BYTES 32768
#define GEMM_SMEM (3*STG_BYTES)          // 98304 -> 2 blocks/SM

#define CP_ASYNC16(dst, src) \
    asm volatile("cp.async.cg.shared.global [%0], [%1], 16;" :: "r"(dst), "l"(src))
#define CP_COMMIT() asm volatile("cp.async.commit_group;")
#define CP_WAIT1()  asm volatile("cp.async.wait_group 1;" ::: "memory")
#define CP_WAIT0()  asm volatile("cp.async.wait_group 0;" ::: "memory")
#define LDSM_X4(r0,r1,r2,r3,addr) \
    asm volatile("ldmatrix.sync.aligned.m8n8.x4.shared.b16 {%0,%1,%2,%3}, [%4];" \
        : "=r"(r0),"=r"(r1),"=r"(r2),"=r"(r3) : "r"(addr))

struct B4 {
    const __half *Ah[4], *Al[4], *Wh[4], *Wl[4];
    const float* bias[4];
    float* C[4];
    __half *Ch[4], *Cl[4];
    const __half *A2h, *A2l, *W2h, *W2l;
    const float *xl, *xg;
    __half *xch, *xcl;
};

__device__ __forceinline__ uint32_t smem_u32(const void* p) {
    uint32_t a;
    asm("{ .reg .u64 t; cvta.to.shared.u64 t, %1; cvt.u32.u64 %0, t; }" : "=r"(a) : "l"(p));
    return a;
}
__device__ __forceinline__ void mma_f16(float* c, uint32_t a0, uint32_t a1,
                                        uint32_t a2, uint32_t a3,
                                        uint32_t b0, uint32_t b1) {
    asm volatile("mma.sync.aligned.m16n8k16.row.col.f32.f16.f16.f32 "
                 "{%0,%1,%2,%3}, {%4,%5,%6,%7}, {%8,%9}, {%0,%1,%2,%3};"
                 : "+f"(c[0]), "+f"(c[1]), "+f"(c[2]), "+f"(c[3])
                 : "r"(a0), "r"(a1), "r"(a2), "r"(a3), "r"(b0), "r"(b1));
}

__global__ __launch_bounds__(256, 2) void gemm_tc(
    B4 b, int lda, int ldw, int N, int K, int epi)
{
    extern __shared__ char smc[];
    const int t   = threadIdx.x;
    const int lid = t & 31;
    const int wid = t >> 5;
    const int wm  = wid & 1;
    const int wn  = wid >> 1;
    const int grp = lid >> 2;
    const int tg  = lid & 3;
    const int bm  = blockIdx.y * TBM;
    const int bn  = blockIdx.x * TBN;
    const int z   = blockIdx.z;

    float acc[4][4][4];
#pragma unroll
    for (int mi = 0; mi < 4; ++mi)
#pragma unroll
        for (int ni = 0; ni < 4; ++ni)
#pragma unroll
            for (int r = 0; r < 4; ++r) acc[mi][ni][r] = 0.f;

    const int nstage = K / TBK;
    const int npass  = b.A2h ? 2 : 1;
    const uint32_t sbase = smem_u32(smc);

    const int lr    = lid & 7;
    const int hsel  = (lid >> 3) & 1;
    const int seg2  = (lid >> 4) & 1;

    // software-pipelined register fragments
    uint32_t Bh[2][4][2], Bl[2][4][2];   // per-kk double buffer
    uint32_t Ah[2][4],    Al[2][4];      // ping-pong per (kk,mi)

    for (int pass = 0; pass < npass; ++pass) {
        const __half* pAh = pass ? b.A2h : b.Ah[z];
        const __half* pAl = pass ? b.A2l : b.Al[z];
        const __half* pWh = pass ? b.W2h : b.Wh[z];
        const __half* pWl = pass ? b.W2l : b.Wl[z];
        __syncthreads();

        auto ld_stage = [&](int buf, int k0) {
#pragma unroll
            for (int i = 0; i < 8; ++i) {
                const int tile = i >> 1;               // 0:Ahi 1:Alo 2:Whi 3:Wlo
                const int rem  = ((i & 1) << 8) + t;   // 0..511
                const int row  = rem >> 2;
                const int chn  = t & 3;
                const __half* src;
                if (tile == 0)      src = pAh + (size_t)(bm + row) * lda + k0 + chn * 8;
                else if (tile == 1) src = pAl + (size_t)(bm + row) * lda + k0 + chn * 8;
                else if (tile == 2) src = pWh + (size_t)(bn + row) * ldw + k0 + chn * 8;
                else                src = pWl + (size_t)(bn + row) * ldw + k0 + chn * 8;
                const uint32_t dst = sbase + buf * STG_BYTES + tile * 8192
                                   + row * 64 + ((chn ^ ((row >> 1) & 3)) << 4);
                CP_ASYNC16(dst, src);
            }
        };

        ld_stage(0, 0);   CP_COMMIT();
        ld_stage(1, TBK); CP_COMMIT();

        for (int s = 0; s < nstage; ++s) {
            if (s == nstage - 1) CP_WAIT0(); else CP_WAIT1();
            __syncthreads();
            if (s + 2 < nstage) { ld_stage((s + 2) % 3, (s + 2) * TBK); CP_COMMIT(); }

            const uint32_t stg = sbase + (s % 3) * STG_BYTES;
            const uint32_t a_h = stg, a_l = stg + 8192;
            const uint32_t w_h = stg + 16384, w_l = stg + 24576;

            auto ldB = [&](int kk, int buf) {
#pragma unroll
                for (int np = 0; np < 2; ++np) {
                    const int nr = wn * 32 + np * 16 + seg2 * 8 + lr;
                    const int ch = kk * 2 + hsel;
                    const uint32_t off = nr * 64 + ((ch ^ ((nr >> 1) & 3)) << 4);
                    LDSM_X4(Bh[buf][np*2][0], Bh[buf][np*2][1],
                            Bh[buf][np*2+1][0], Bh[buf][np*2+1][1], w_h + off);
                    LDSM_X4(Bl[buf][np*2][0], Bl[buf][np*2][1],
                            Bl[buf][np*2+1][0], Bl[buf][np*2+1][1], w_l + off);
                }
            };
            auto ldA = [&](int kk, int mi, int buf) {
                const int ar = wm * 64 + mi * 16 + hsel * 8 + lr;
                const int ch = kk * 2 + seg2;
                const uint32_t off = ar * 64 + ((ch ^ ((ar >> 1) & 3)) << 4);
                LDSM_X4(Ah[buf][0], Ah[buf][1], Ah[buf][2], Ah[buf][3], a_h + off);
                LDSM_X4(Al[buf][0], Al[buf][1], Al[buf][2], Al[buf][3], a_l + off);
            };

            // stage prologue: kk0 fragments
            ldB(0, 0);
            ldA(0, 0, 0);

#pragma unroll
            for (int kk = 0; kk < 2; ++kk) {
#pragma unroll
                for (int mi = 0; mi < 4; ++mi) {
                    const int cur = (kk * 4 + mi) & 1;
                    const int nxt = cur ^ 1;
                    // prefetch next fragments before issuing MMAs
                    if (kk == 0 && mi == 0) ldB(1, 1);
                    if (mi < 3)            ldA(kk, mi + 1, nxt);
                    else if (kk == 0)      ldA(1, 0, nxt);
#pragma unroll
                    for (int ni = 0; ni < 4; ++ni)
                        mma_f16(acc[mi][ni], Ah[cur][0], Ah[cur][1], Ah[cur][2], Ah[cur][3],
                                Bh[kk][ni][0], Bh[kk][ni][1]);
#pragma unroll
                    for (int ni = 0; ni < 4; ++ni)
                        mma_f16(acc[mi][ni], Al[cur][0], Al[cur][1], Al[cur][2], Al[cur][3],
                                Bh[kk][ni][0], Bh[kk][ni][1]);
#pragma unroll
                    for (int ni = 0; ni < 4; ++ni)
                        mma_f16(acc[mi][ni], Ah[cur][0], Ah[cur][1], Ah[cur][2], Ah[cur][3],
                                Bl[kk][ni][0], Bl[kk][ni][1]);
                }
            }
        }
    }

    // ---------------- epilogue ----------------
#pragma unroll
    for (int mi = 0; mi < 4; ++mi) {
#pragma unroll
        for (int ni = 0; ni < 4; ++ni) {
            const int col = bn + wn * 32 + ni * 8 + 2 * tg;
            float bx = 0.f, by = 0.f;
            if (b.bias[z]) { bx = b.bias[z][col]; by = b.bias[z][col + 1]; }
#pragma unroll
            for (int hf = 0; hf < 2; ++hf) {
                const int row = bm + wm * 64 + mi * 16 + grp + hf * 8;
                float v0 = acc[mi][ni][hf * 2 + 0] + bx;
                float v1 = acc[mi][ni][hf * 2 + 1] + by;
                const size_t idx = (size_t)row * N + col;
                if (epi == 0) {
                    *(float2*)(b.C[z] + idx) = make_float2(v0, v1);
                } else if (epi == 1) {
                    float u3;
                    u3 = v0 * v0 * v0;
                    v0 = 0.5f * v0 * (1.f + tanhf(0.7978845608028654f * (v0 + 0.044715f * u3)));
                    u3 = v1 * v1 * v1;
                    v1 = 0.5f * v1 * (1.f + tanhf(0.7978845608028654f * (v1 + 0.044715f * u3)));
                    __half2 hh = __floats2half2_rn(v0, v1);
                    float2 hv = __half22float2(hh);
                    __half2 ll = __floats2half2_rn(v0 - hv.x, v1 - hv.y);
                    *(__half2*)(b.Ch[z] + idx) = hh;
                    *(__half2*)(b.Cl[z] + idx) = ll;
                } else { // epi == 3
                    float s0 = 1.f / (1.f + __expf(-v0));
                    float s1 = 1.f / (1.f + __expf(-v1));
                    float2 xl2 = *(const float2*)(b.xl + idx);
                    float2 xg2 = *(const float2*)(b.xg + idx);
                    v0 = s0 * xl2.x + (1.f - s0) * xg2.x;
                    v1 = s1 * xl2.y + (1.f - s1) * xg2.y;
                    *(float2*)(b.C[z] + idx) = make_float2(v0, v1);
                    __half2 hh = __floats2half2_rn(v0, v1);
                    float2 hv = __half22float2(hh);
                    __half2 ll = __floats2half2_rn(v0 - hv.x, v1 - hv.y);
                    *(__half2*)(b.xch + idx) = hh;
                    *(__half2*)(b.xcl + idx) = ll;
                }
            }
        }
    }
}

// ----------------- fused splitter: f32 -> f16 hi/lo, all tensors ----------
struct SplitSeg { const float4* src; uint2* hi; uint2* lo; unsigned n4; };
struct SplitTab { SplitSeg seg[10]; };

__global__ void split_all_kernel(SplitTab tab)
{
    unsigned idx = blockIdx.x * blockDim.x + threadIdx.x;
#pragma unroll
    for (int s = 0; s < 10; ++s) {
        if (idx < tab.seg[s].n4) {
            float4 v = tab.seg[s].src[idx];
            __half2 h0 = __floats2half2_rn(v.x, v.y);
            __half2 h1 = __floats2half2_rn(v.z, v.w);
            float2 f0 = __half22float2(h0), f1 = __half22float2(h1);
            __half2 l0 = __floats2half2_rn(v.x - f0.x, v.y - f0.y);
            __half2 l1 = __floats2half2_rn(v.z - f1.x, v.w - f1.y);
            tab.seg[s].hi[idx] = make_uint2(*(uint32_t*)&h0, *(uint32_t*)&h1);
            tab.seg[s].lo[idx] = make_uint2(*(uint32_t*)&l0, *(uint32_t*)&l1);
            return;
        }
        idx -= tab.seg[s].n4;
    }
}

// ----------------- sliding-window causal attention (f32x2) ----------------
__global__ __launch_bounds__(64) void attn_kernel(const float* __restrict__ qkv,
                                                  __half* __restrict__ oh,
                                                  __half* __restrict__ ol)
{
    const int qt = blockIdx.x;
    const int b  = blockIdx.y;
    const int h  = blockIdx.z;
    const int t  = threadIdx.x;
    const int qi = qt * 64 + t;

    __shared__ __align__(16) float ks[64][64];
    __shared__ __align__(16) float vs[64][64];

    ull q2[32], o2[32];
    {
        const float4* qb = (const float4*)(qkv + ((size_t)(b * SEQ + qi)) * (3 * DIM) + h * HD);
#pragma unroll
        for (int d4 = 0; d4 < 16; ++d4) {
            float4 v = qb[d4];
            q2[2*d4]   = pack2f(v.x * 0.125f, v.y * 0.125f);
            q2[2*d4+1] = pack2f(v.z * 0.125f, v.w * 0.125f);
        }
    }
#pragma unroll
    for (int i = 0; i < 32; ++i) o2[i] = 0ull;
    float m = -1e30f, l = 0.f;

    const int kt0 = (qt >= 8) ? (qt - 8) : 0;
    for (int kt = kt0; kt <= qt; ++kt) {
        const float* kbase = qkv + ((size_t)(b * SEQ + kt * 64)) * (3 * DIM) + DIM + h * HD + t;
        const float* vbase = kbase + DIM;
        for (int r = 0; r < 64; ++r) {
            ks[r][t] = kbase[(size_t)r * (3 * DIM)];
            vs[r][t] = vbase[(size_t)r * (3 * DIM)];
        }
        __syncthreads();

        int jlo = qi - WIN + 1 - kt * 64; if (jlo < 0)  jlo = 0;
        int jhi = qi - kt * 64;           if (jhi > 63) jhi = 63;
        for (int j = jlo; j <= jhi; ++j) {
            const ull* kr2 = (const ull*)ks[j];
            ull a0 = 0ull, a1 = 0ull, a2 = 0ull, a3 = 0ull;
#pragma unroll
            for (int i = 0; i < 32; i += 4) {
                ffma2(a0, q2[i],   kr2[i]);
                ffma2(a1, q2[i+1], kr2[i+1]);
                ffma2(a2, q2[i+2], kr2[i+2]);
                ffma2(a3, q2[i+3], kr2[i+3]);
            }
            float2 f0 = unpack2f(a0), f1 = unpack2f(a1);
            float2 f2 = unpack2f(a2), f3 = unpack2f(a3);
            float s = ((f0.x + f0.y) + (f1.x + f1.y)) + ((f2.x + f2.y) + (f3.x + f3.y));
            const ull* vr2 = (const ull*)vs[j];
            if (s <= m) {
                float p = __expf(s - m);
                l += p;
                ull p2 = pack2f(p, p);
#pragma unroll
                for (int i = 0; i < 32; ++i) ffma2(o2[i], p2, vr2[i]);
            } else {
                float al = __expf(m - s);
                m = s; l = l * al + 1.f;
                ull al2 = pack2f(al, al);
#pragma unroll
                for (int i = 0; i < 32; ++i) ffma2b(o2[i], al2, vr2[i]);
            }
        }
        __syncthreads();
    }

    const float inv = 1.f / l;
    const size_t ob = ((size_t)(b * SEQ + qi)) * DIM + h * HD;
#pragma unroll
    for (int i = 0; i < 32; i += 2) {
        float2 p0 = unpack2f(o2[i]), p1 = unpack2f(o2[i+1]);
        float v0 = p0.x * inv, v1 = p0.y * inv, v2 = p1.x * inv, v3 = p1.y * inv;
        __half2 h0 = __floats2half2_rn(v0, v1);
        __half2 h1 = __floats2half2_rn(v2, v3);
        float2 f0 = __half22float2(h0), f1 = __half22float2(h1);
        __half2 l0 = __floats2half2_rn(v0 - f0.x, v1 - f0.y);
        __half2 l1 = __floats2half2_rn(v2 - f1.x, v3 - f1.y);
        *(uint2*)(oh + ob + 2*i) = make_uint2(*(uint32_t*)&h0, *(uint32_t*)&h1);
        *(uint2*)(ol + ob + 2*i) = make_uint2(*(uint32_t*)&l0, *(uint32_t*)&l1);
    }
}

// ----------------- fused residual-add + LayerNorm (+split out) ------------
__global__ __launch_bounds__(256) void add_ln_kernel(const float* __restrict__ x,
    const float* __restrict__ r, const float* __restrict__ gg,
    const float* __restrict__ bb, float* __restrict__ y,
    __half* __restrict__ yh, __half* __restrict__ yl)
{
    const int row = blockIdx.x;
    const int t = threadIdx.x;
    __shared__ float red[8];
    __shared__ float bc0, bc1;

    const float* xr = x + (size_t)row * DIM;
    const float* rr = r + (size_t)row * DIM;
    float v[3]; float s = 0.f;
#pragma unroll
    for (int i = 0; i < 3; ++i) { int c = t + i * 256; v[i] = xr[c] + rr[c]; s += v[i]; }
#pragma unroll
    for (int off = 16; off; off >>= 1) s += __shfl_xor_sync(0xffffffffu, s, off);
    if ((t & 31) == 0) red[t >> 5] = s;
    __syncthreads();
    if (t == 0) { float tot = 0.f;
#pragma unroll
        for (int w = 0; w < 8; ++w) tot += red[w];
        bc0 = tot * (1.f / DIM);
    }
    __syncthreads();
    const float mean = bc0;
    float sq = 0.f;
#pragma unroll
    for (int i = 0; i < 3; ++i) { float d = v[i] - mean; sq += d * d; }
#pragma unroll
    for (int off = 16; off; off >>= 1) sq += __shfl_xor_sync(0xffffffffu, sq, off);
    if ((t & 31) == 0) red[t >> 5] = sq;
    __syncthreads();
    if (t == 0) { float tot = 0.f;
#pragma unroll
        for (int w = 0; w < 8; ++w) tot += red[w];
        bc1 = rsqrtf(tot * (1.f / DIM) + 1e-5f);
    }
    __syncthreads();
    const float rstd = bc1;
#pragma unroll
    for (int i = 0; i < 3; ++i) {
        int c = t + i * 256;
        float val = (v[i] - mean) * rstd * gg[c] + bb[c];
        y[(size_t)row * DIM + c] = val;
        __half hh = __float2half_rn(val);
        __half ll = __float2half_rn(val - __half2float(hh));
        yh[(size_t)row * DIM + c] = hh;
        yl[(size_t)row * DIM + c] = ll;
    }
}

// ----------------- final LN with 4-way CMS mean ----------------------------
__global__ __launch_bounds__(256) void ln_final_kernel(const float* __restrict__ xc,
    const float* __restrict__ c0, const float* __restrict__ c1,
    const float* __restrict__ c2, const float* __restrict__ c3,
    const float* __restrict__ gg, const float* __restrict__ bb,
    float* __restrict__ y)
{
    const int row = blockIdx.x;
    const int t = threadIdx.x;
    __shared__ float red[8];
    __shared__ float bc0, bc1;

    const size_t rb = (size_t)row * DIM;
    float v[3]; float s = 0.f;
#pragma unroll
    for (int i = 0; i < 3; ++i) {
        int c = t + i * 256;
        v[i] = xc[rb + c] + 0.25f * (c0[rb + c] + c1[rb + c] + c2[rb + c] + c3[rb + c]);
        s += v[i];
    }
#pragma unroll
    for (int off = 16; off; off >>= 1) s += __shfl_xor_sync(0xffffffffu, s, off);
    if ((t & 31) == 0) red[t >> 5] = s;
    __syncthreads();
    if (t == 0) { float tot = 0.f;
#pragma unroll
        for (int w = 0; w < 8; ++w) tot += red[w];
        bc0 = tot * (1.f / DIM);
    }
    __syncthreads();
    const float mean = bc0;
    float sq = 0.f;
#pragma unroll
    for (int i = 0; i < 3; ++i) { float d = v[i] - mean; sq += d * d; }
#pragma unroll
    for (int off = 16; off; off >>= 1) sq += __shfl_xor_sync(0xffffffffu, sq, off);
    if ((t & 31) == 0) red[t >> 5] = sq;
    __syncthreads();
    if (t == 0) { float tot = 0.f;
#pragma unroll
        for (int w = 0; w < 8; ++w) tot += red[w];
        bc1 = rsqrtf(tot * (1.f / DIM) + 1e-5f);
    }
    __syncthreads();
    const float rstd = bc1;
#pragma unroll
    for (int i = 0; i < 3; ++i) {
        int c = t + i * 256;
        y[rb + c] = (v[i] - mean) * rstd * gg[c] + bb[c];
    }
}

// ----------------- delta-rule scan: f32x2 + 2 barriers/step ---------------
__global__ __launch_bounds__(256) void delta_scan_kernel(const float* __restrict__ tq,
    const float* __restrict__ tk, const float* __restrict__ tv,
    __half* __restrict__ toh, __half* __restrict__ tol, float* __restrict__ Mout)
{
    const int bh = blockIdx.x;
    const int b = bh / NH, h = bh % NH;
    const int t = threadIdx.x;
    const int e = t & 63;
    const int g = t >> 6;

    __shared__ __align__(8) float ks[2][64], vs[2][64], qs[2][64];
    __shared__ float part[2][4][64];
    __shared__ float opart[2][4][64];

    ull M2[8];
#pragma unroll
    for (int i = 0; i < 8; ++i) M2[i] = 0ull;

    const size_t base = ((size_t)b * SEQ) * DIM + h * HD + e;
    float nxt = 0.f;
    if (g == 0) nxt = tk[base];
    else if (g == 1) nxt = tv[base];
    else if (g == 2) nxt = tq[base];

    for (int s = 0; s < SEQ; ++s) {
        const int p = s & 1;
        if (g == 0) ks[p][e] = nxt;
        else if (g == 1) vs[p][e] = nxt;
        else if (g == 2) qs[p][e] = nxt;
        __syncthreads();   // B1
        if (s + 1 < SEQ) {
            size_t nb = base + (size_t)(s + 1) * DIM;
            if (g == 0) nxt = tk[nb];
            else if (g == 1) nxt = tv[nb];
            else if (g == 2) nxt = tq[nb];
        }
        if (g == 0 && s > 0) {
            const int pp = p ^ 1;
            float ov = (opart[pp][0][e] + opart[pp][1][e])
                     + (opart[pp][2][e] + opart[pp][3][e]);
            __half hh = __float2half_rn(ov);
            __half ll = __float2half_rn(ov - __half2float(hh));
            toh[base + (size_t)(s - 1) * DIM] = hh;
            tol[base + (size_t)(s - 1) * DIM] = ll;
        }
        ull k2[8];
        ull pa = 0ull, pb = 0ull;
        const ull* kp = (const ull*)&ks[p][g * 16];
#pragma unroll
        for (int i = 0; i < 8; i += 2) {
            k2[i] = kp[i]; k2[i+1] = kp[i+1];
            ffma2(pa, M2[i], k2[i]);
            ffma2(pb, M2[i+1], k2[i+1]);
        }
        float2 pf = unpack2f(pa), pg = unpack2f(pb);
        part[p][g][e] = (pf.x + pf.y) + (pg.x + pg.y);
        __syncthreads();   // B2
        const float pred  = (part[p][0][e] + part[p][1][e]) + (part[p][2][e] + part[p][3][e]);
        const float delta = LRATE * (vs[p][e] - pred);
        const ull d2 = pack2f(delta, delta);
        const ull* qp = (const ull*)&qs[p][g * 16];
        ull oa = 0ull, obb = 0ull;
#pragma unroll
        for (int i = 0; i < 8; i += 2) {
            ffma2(M2[i], k2[i], d2);     ffma2(oa, M2[i], qp[i]);
            ffma2(M2[i+1], k2[i+1], d2); ffma2(obb, M2[i+1], qp[i+1]);
        }
        float2 of = unpack2f(oa), og = unpack2f(obb);
        opart[p][g][e] = (of.x + of.y) + (og.x + og.y);
    }
    __syncthreads();
    if (g == 0) {
        const int pp = (SEQ - 1) & 1;
        float ov = (opart[pp][0][e] + opart[pp][1][e]) + (opart[pp][2][e] + opart[pp][3][e]);
        __half hh = __float2half_rn(ov);
        __half ll = __float2half_rn(ov - __half2float(hh));
        toh[base + (size_t)(SEQ - 1) * DIM] = hh;
        tol[base + (size_t)(SEQ - 1) * DIM] = ll;
    }
    if (Mout) {
#pragma unroll
        for (int i = 0; i < 8; ++i) {
            float2 mv = unpack2f(M2[i]);
            Mout[(((size_t)b * NH + h) * HD + (g * 16 + 2*i))     * HD + e] = mv.x;
            Mout[(((size_t)b * NH + h) * HD + (g * 16 + 2*i + 1)) * HD + e] = mv.y;
        }
    }
}

// ----------------- launch ---------------------------------------------------
static void* symp(const void* s) {
    void* p = nullptr;
    cudaGetSymbolAddress(&p, s);
    return p;
}

extern "C" void kernel_launch(void* const* d_in, const int* in_sizes, int n_in,
                              void* d_out, int out_size)
{
    const float* x          = (const float*)d_in[0];
    const float* in_proj_w  = (const float*)d_in[1];
    const float* in_proj_b  = (const float*)d_in[2];
    const float* out_proj_w = (const float*)d_in[3];
    const float* out_proj_b = (const float*)d_in[4];
    const float* ln_local_g = (const float*)d_in[5];
    const float* ln_local_b = (const float*)d_in[6];
    const float* t_wq       = (const float*)d_in[7];
    const float* t_wk       = (const float*)d_in[8];
    const float* t_wv       = (const float*)d_in[9];
    const float* t_wo       = (const float*)d_in[10];
    const float* ln_tit_g   = (const float*)d_in[11];
    const float* ln_tit_b   = (const float*)d_in[12];
    const float* gate_w     = (const float*)d_in[13];
    const float* gate_b     = (const float*)d_in[14];
    const float* cms_w1     = (const float*)d_in[15];
    const float* cms_b1     = (const float*)d_in[16];
    const float* cms_w2     = (const float*)d_in[17];
    const float* cms_b2     = (const float*)d_in[18];
    const float* ln_cms_g   = (const float*)d_in[19];
    const float* ln_cms_b   = (const float*)d_in[20];

    float* qkv    = (float*)symp(g_qkv);
    float* proj   = (float*)symp(g_proj);
    float* proj2  = (float*)symp(g_proj2);
    float* xlocal = (float*)symp(g_xlocal);
    float* xglob  = (float*)symp(g_xglobal);
    float* tq     = (float*)symp(g_tq);
    float* tk     = (float*)symp(g_tk);
    float* tv     = (float*)symp(g_tv);
    float* xc     = (float*)symp(g_xc);
    float* cmsb   = (float*)symp(g_cms);

    __half* x_h   = (__half*)symp(g_x_h);   __half* x_l   = (__half*)symp(g_x_l);
    __half* wi_h  = (__half*)symp(g_wi_h);  __half* wi_l  = (__half*)symp(g_wi_l);
    __half* wo_h  = (__half*)symp(g_wo_h);  __half* wo_l  = (__half*)symp(g_wo_l);
    __half* wtq_h = (__half*)symp(g_wtq_h); __half* wtq_l = (__half*)symp(g_wtq_l);
    __half* wtk_h = (__half*)symp(g_wtk_h); __half* wtk_l = (__half*)symp(g_wtk_l);
    __half* wtv_h = (__half*)symp(g_wtv_h); __half* wtv_l = (__half*)symp(g_wtv_l);
    __half* wto_h = (__half*)symp(g_wto_h); __half* wto_l = (__half*)symp(g_wto_l);
    __half* wg_h  = (__half*)symp(g_wg_h);  __half* wg_l  = (__half*)symp(g_wg_l);
    __half* wc1_h = (__half*)symp(g_wc1_h); __half* wc1_l = (__half*)symp(g_wc1_l);
    __half* wc2_h = (__half*)symp(g_wc2_h); __half* wc2_l = (__half*)symp(g_wc2_l);
    __half* att_h = (__half*)symp(g_att_h); __half* att_l = (__half*)symp(g_att_l);
    __half* to_h  = (__half*)symp(g_to_h);  __half* to_l  = (__half*)symp(g_to_l);
    __half* xl_h  = (__half*)symp(g_xl_h);  __half* xl_l  = (__half*)symp(g_xl_l);
    __half* xg_h  = (__half*)symp(g_xg_h);  __half* xg_l  = (__half*)symp(g_xg_l);
    __half* xc_h  = (__half*)symp(g_xc_h);  __half* xc_l  = (__half*)symp(g_xc_l);
    __half* hb_h  = (__half*)symp(g_hb_h);  __half* hb_l  = (__half*)symp(g_hb_l);

    float* out = (float*)d_out;
    float* mout = (out_size >= ROWS * DIM + BATCH * NH * HD * HD)
                      ? out + (size_t)ROWS * DIM : nullptr;

    static cudaStream_t s2 = nullptr;
    static cudaEvent_t ev_fork = nullptr, ev_join = nullptr;
    if (!s2) {
        cudaFuncSetAttribute(gemm_tc, cudaFuncAttributeMaxDynamicSharedMemorySize, GEMM_SMEM);
        cudaStreamCreateWithFlags(&s2, cudaStreamNonBlocking);
        cudaEventCreateWithFlags(&ev_fork, cudaEventDisableTiming);
        cudaEventCreateWithFlags(&ev_join, cudaEventDisableTiming);
    }

    // [0] single fused split of all f32 operands -> f16 hi/lo planes
    {
        SplitTab tab{};
        unsigned tot4 = 0;
        auto add = [&](int i, const float* s, __half* h, __half* l, size_t n) {
            tab.seg[i] = SplitSeg{ (const float4*)s, (uint2*)h, (uint2*)l, (unsigned)(n / 4) };
            tot4 += (unsigned)(n / 4);
        };
        add(0, x, x_h, x_l, (size_t)ROWS * DIM);
        add(1, t_wq, wtq_h, wtq_l, (size_t)DIM * DIM);
        add(2, t_wk, wtk_h, wtk_l, (size_t)DIM * DIM);
        add(3, t_wv, wtv_h, wtv_l, (size_t)DIM * DIM);
        add(4, t_wo, wto_h, wto_l, (size_t)DIM * DIM);
        add(5, in_proj_w, wi_h, wi_l, (size_t)3 * DIM * DIM);
        add(6, out_proj_w, wo_h, wo_l, (size_t)DIM * DIM);
        add(7, gate_w, wg_h, wg_l, (size_t)2 * DIM * DIM);
        add(8, cms_w1, wc1_h, wc1_l, (size_t)16 * DIM * DIM);
        add(9, cms_w2, wc2_h, wc2_l, (size_t)16 * DIM * DIM);
        split_all_kernel<<<(tot4 + 255) / 256, 256>>>(tab);
    }

    cudaEventRecord(ev_fork, 0);
    cudaStreamWaitEvent(s2, ev_fork, 0);

    B4 b{};

    // [s2] Titans projections (z-batched x3)
    b = B4{};
    b.Ah[0] = x_h; b.Al[0] = x_l; b.Wh[0] = wtq_h; b.Wl[0] = wtq_l; b.C[0] = tq;
    b.Ah[1] = x_h; b.Al[1] = x_l; b.Wh[1] = wtk_h; b.Wl[1] = wtk_l; b.C[1] = tk;
    b.Ah[2] = x_h; b.Al[2] = x_l; b.Wh[2] = wtv_h; b.Wl[2] = wtv_l; b.C[2] = tv;
    gemm_tc<<<dim3(DIM / TBN, ROWS / TBM, 3), 256, GEMM_SMEM, s2>>>(b, DIM, DIM, DIM, DIM, 0);

    // [s2] delta-rule scan
    delta_scan_kernel<<<BATCH * NH, 256, 0, s2>>>(tq, tk, tv, to_h, to_l, mout);

    // [s2] titans out proj + residual LN -> x_global (+split)
    b = B4{};
    b.Ah[0] = to_h; b.Al[0] = to_l; b.Wh[0] = wto_h; b.Wl[0] = wto_l; b.C[0] = proj2;
    gemm_tc<<<dim3(DIM / TBN, ROWS / TBM, 1), 256, GEMM_SMEM, s2>>>(b, DIM, DIM, DIM, DIM, 0);
    add_ln_kernel<<<ROWS, 256, 0, s2>>>(x, proj2, ln_tit_g, ln_tit_b, xglob, xg_h, xg_l);
    cudaEventRecord(ev_join, s2);

    // [0] packed QKV projection
    b = B4{};
    b.Ah[0] = x_h; b.Al[0] = x_l; b.Wh[0] = wi_h; b.Wl[0] = wi_l;
    b.bias[0] = in_proj_b; b.C[0] = qkv;
    gemm_tc<<<dim3(3 * DIM / TBN, ROWS / TBM, 1), 256, GEMM_SMEM>>>(b, DIM, DIM, 3 * DIM, DIM, 0);

    // [0] sliding-window attention -> split att
    attn_kernel<<<dim3(SEQ / 64, BATCH, NH), 64>>>(qkv, att_h, att_l);

    // [0] out_proj + residual LN -> x_local (+split)
    b = B4{};
    b.Ah[0] = att_h; b.Al[0] = att_l; b.Wh[0] = wo_h; b.Wl[0] = wo_l;
    b.bias[0] = out_proj_b; b.C[0] = proj;
    gemm_tc<<<dim3(DIM / TBN, ROWS / TBM, 1), 256, GEMM_SMEM>>>(b, DIM, DIM, DIM, DIM, 0);
    add_ln_kernel<<<ROWS, 256>>>(x, proj, ln_local_g, ln_local_b, xlocal, xl_h, xl_l);

    // ---- join ----
    cudaStreamWaitEvent(0, ev_join, 0);

    // [0] gate: two K-passes with fused sigmoid-combine
    b = B4{};
    b.Ah[0] = xl_h; b.Al[0] = xl_l; b.Wh[0] = wg_h; b.Wl[0] = wg_l;
    b.bias[0] = gate_b; b.C[0] = xc;
    b.A2h = xg_h; b.A2l = xg_l; b.W2h = wg_h + DIM; b.W2l = wg_l + DIM;
    b.xl = xlocal; b.xg = xglob; b.xch = xc_h; b.xcl = xc_l;
    gemm_tc<<<dim3(DIM / TBN, ROWS / TBM, 1), 256, GEMM_SMEM>>>(b, DIM, 2 * DIM, DIM, DIM, 3);

    // [0] CMS: w1 x4 (gelu, split-only output), z-batched
    b = B4{};
    for (int l = 0; l < 4; ++l) {
        b.Ah[l] = xc_h; b.Al[l] = xc_l;
        b.Wh[l] = wc1_h + (size_t)l * 4 * DIM * DIM;
        b.Wl[l] = wc1_l + (size_t)l * 4 * DIM * DIM;
        b.bias[l] = cms_b1 + (size_t)l * 4 * DIM;
        b.Ch[l] = hb_h + (size_t)l * ROWS * 4 * DIM;
        b.Cl[l] = hb_l + (size_t)l * ROWS * 4 * DIM;
    }
    gemm_tc<<<dim3(4 * DIM / TBN, ROWS / TBM, 4), 256, GEMM_SMEM>>>(b, DIM, DIM, 4 * DIM, DIM, 1);

    // [0] CMS: w2 x4, z-batched, per-level f32 outputs
    b = B4{};
    for (int l = 0; l < 4; ++l) {
        b.Ah[l] = hb_h + (size_t)l * ROWS * 4 * DIM;
        b.Al[l] = hb_l + (size_t)l * ROWS * 4 * DIM;
        b.Wh[l] = wc2_h + (size_t)l * 4 * DIM * DIM;
        b.Wl[l] = wc2_l + (size_t)l * 4 * DIM * DIM;
        b.bias[l] = cms_b2 + (size_t)l * DIM;
        b.C[l] = cmsb + (size_t)l * ROWS * DIM;
    }
    gemm_tc<<<dim3(DIM / TBN, ROWS / TBM, 4), 256, GEMM_SMEM>>>(b, 4 * DIM, 4 * DIM, DIM, 4 * DIM, 0);

    // [0] final LN
    ln_final_kernel<<<ROWS, 256>>>(xc, cmsb, cmsb + (size_t)ROWS * DIM,
                                   cmsb + 2 * (size_t)ROWS * DIM, cmsb + 3 * (size_t)ROWS * DIM,
                                   ln_cms_g, ln_cms_b, out);
}